// round 2
// baseline (speedup 1.0000x reference)
#include <cuda_runtime.h>
#include <math.h>
#include <stdint.h>

#define BATCH 8
#define DIMC 512
#define HW 1024
#define HEADS 8
#define HD 64
#define LCTX 77
#define CTXD 768
#define TKV 1101      // 77 ctx + 1024 image keys
#define NCH2 9        // ceil(1101/128)

// ---- scratch (device globals; no allocation allowed) ----
__device__ float g_xn[BATCH * DIMC * HW];        // 16 MB groupnormed x
__device__ float g_qkv[BATCH * 3 * DIMC * HW];   // 50 MB qkv projections
__device__ float g_ckv[BATCH * 2 * DIMC * LCTX]; // 2.5 MB context kv, [b][o][l]
__device__ float g_attn[BATCH * DIMC * HW];      // 16 MB attention output

// ============================================================
// GroupNorm: one block per (b, group). 16 ch * 1024 spatial = 16384 contiguous.
// ============================================================
__global__ void gn_kernel(const float* __restrict__ x, const float* __restrict__ gamma,
                          const float* __restrict__ beta, float* __restrict__ xn) {
    __shared__ float ssum[256], ssq[256];
    int bg = blockIdx.x;
    int b = bg >> 5, g = bg & 31;
    const float* xp = x + ((size_t)b * DIMC + g * 16) * HW;
    float* xo = xn + ((size_t)b * DIMC + g * 16) * HW;
    int tid = threadIdx.x;

    float s = 0.f, sq = 0.f;
#pragma unroll
    for (int i = 0; i < 64; i++) {
        float v = xp[tid + i * 256];
        s += v; sq += v * v;
    }
    ssum[tid] = s; ssq[tid] = sq;
    __syncthreads();
    for (int off = 128; off > 0; off >>= 1) {
        if (tid < off) { ssum[tid] += ssum[tid + off]; ssq[tid] += ssq[tid + off]; }
        __syncthreads();
    }
    float mu = ssum[0] * (1.f / 16384.f);
    float var = ssq[0] * (1.f / 16384.f) - mu * mu;
    float inv = rsqrtf(var + 1e-5f);
#pragma unroll
    for (int i = 0; i < 64; i++) {
        int idx = tid + i * 256;
        int c = g * 16 + (idx >> 10);
        xo[idx] = (xp[idx] - mu) * inv * gamma[c] + beta[c];
    }
}

// ============================================================
// SGEMM: C[b][m][n] = sum_k W[m][k] * X[b][k][n] + bias[m] (+ res[b][m][n])
// 128x128 tile, BK=8, 256 threads, 8x8 microtile.
// ============================================================
__global__ void gemm128(const float* __restrict__ W, const float* __restrict__ bias,
                        const float* __restrict__ X, const float* __restrict__ res,
                        float* __restrict__ C, int M, int N, int K) {
    __shared__ float ws[8 * 128];
    __shared__ float xs[8 * 128];
    int b = blockIdx.z;
    int m0 = blockIdx.y * 128, n0 = blockIdx.x * 128;
    const float* Xb = X + (size_t)b * K * N;
    int tid = threadIdx.x;
    int tx = tid & 15, ty = tid >> 4;

    float acc[8][8];
#pragma unroll
    for (int i = 0; i < 8; i++)
#pragma unroll
        for (int j = 0; j < 8; j++) acc[i][j] = 0.f;

    int wm = tid >> 1;            // 0..127
    int wk = (tid & 1) * 4;       // 0 or 4
    int xn4 = (tid & 31) * 4;     // 0..124
    int xk = tid >> 5;            // 0..7

    for (int k0 = 0; k0 < K; k0 += 8) {
        float4 wv = *(const float4*)(W + (size_t)(m0 + wm) * K + k0 + wk);
        ws[(wk + 0) * 128 + wm] = wv.x;
        ws[(wk + 1) * 128 + wm] = wv.y;
        ws[(wk + 2) * 128 + wm] = wv.z;
        ws[(wk + 3) * 128 + wm] = wv.w;
        float4 xv = *(const float4*)(Xb + (size_t)(k0 + xk) * N + n0 + xn4);
        *(float4*)&xs[xk * 128 + xn4] = xv;
        __syncthreads();
#pragma unroll
        for (int kk = 0; kk < 8; kk++) {
            float4 a0 = *(float4*)&ws[kk * 128 + ty * 8];
            float4 a1 = *(float4*)&ws[kk * 128 + ty * 8 + 4];
            float4 b0 = *(float4*)&xs[kk * 128 + tx * 8];
            float4 b1 = *(float4*)&xs[kk * 128 + tx * 8 + 4];
            float a[8] = {a0.x, a0.y, a0.z, a0.w, a1.x, a1.y, a1.z, a1.w};
            float bb[8] = {b0.x, b0.y, b0.z, b0.w, b1.x, b1.y, b1.z, b1.w};
#pragma unroll
            for (int i = 0; i < 8; i++)
#pragma unroll
                for (int j = 0; j < 8; j++) acc[i][j] += a[i] * bb[j];
        }
        __syncthreads();
    }

#pragma unroll
    for (int i = 0; i < 8; i++) {
        int m = m0 + ty * 8 + i;
        float bv = bias[m];
        size_t off = ((size_t)b * M + m) * N + n0 + tx * 8;
        float4 o0, o1;
        o0.x = acc[i][0] + bv; o0.y = acc[i][1] + bv; o0.z = acc[i][2] + bv; o0.w = acc[i][3] + bv;
        o1.x = acc[i][4] + bv; o1.y = acc[i][5] + bv; o1.z = acc[i][6] + bv; o1.w = acc[i][7] + bv;
        if (res) {
            float4 r0 = *(const float4*)(res + off);
            float4 r1 = *(const float4*)(res + off + 4);
            o0.x += r0.x; o0.y += r0.y; o0.z += r0.z; o0.w += r0.w;
            o1.x += r1.x; o1.y += r1.y; o1.z += r1.z; o1.w += r1.w;
        }
        *(float4*)(C + off) = o0;
        *(float4*)(C + off + 4) = o1;
    }
}

// ============================================================
// ckv GEMM: g_ckv[b][o][l] = sum_c context[b][l][c]*ckv_w[o][c] + ckv_b[o]
// ============================================================
__global__ void ckv_kernel(const float* __restrict__ ctx, const float* __restrict__ W,
                           const float* __restrict__ bias) {
    __shared__ float ws2[32 * 65];
    __shared__ float cs[32 * 81];
    int ot = blockIdx.x, b = blockIdx.y;
    int tid = threadIdx.x;
    int tx = tid & 15, tg = tid >> 4;
    int cc = tid & 31, rr = tid >> 5;
    int ob = tg * 4, lb = tx * 5;

    float acc[4][5];
#pragma unroll
    for (int i = 0; i < 4; i++)
#pragma unroll
        for (int j = 0; j < 5; j++) acc[i][j] = 0.f;

    for (int c0 = 0; c0 < CTXD; c0 += 32) {
#pragma unroll
        for (int p = 0; p < 8; p++) {
            int o = p * 8 + rr;
            ws2[cc * 65 + o] = W[(size_t)(ot * 64 + o) * CTXD + c0 + cc];
        }
#pragma unroll
        for (int p = 0; p < 10; p++) {
            int l = p * 8 + rr;
            float v = (l < LCTX) ? ctx[((size_t)b * LCTX + l) * CTXD + c0 + cc] : 0.f;
            cs[cc * 81 + l] = v;
        }
        __syncthreads();
#pragma unroll
        for (int kk = 0; kk < 32; kk++) {
            float wv[4], cv[5];
#pragma unroll
            for (int i = 0; i < 4; i++) wv[i] = ws2[kk * 65 + ob + i];
#pragma unroll
            for (int j = 0; j < 5; j++) cv[j] = cs[kk * 81 + lb + j];
#pragma unroll
            for (int i = 0; i < 4; i++)
#pragma unroll
                for (int j = 0; j < 5; j++) acc[i][j] += wv[i] * cv[j];
        }
        __syncthreads();
    }

#pragma unroll
    for (int i = 0; i < 4; i++) {
        int o = ot * 64 + ob + i;
        float bv = bias[o];
#pragma unroll
        for (int j = 0; j < 5; j++) {
            int l = lb + j;
            if (l < LCTX)
                g_ckv[((size_t)b * 1024 + o) * LCTX + l] = acc[i][j] + bv;
        }
    }
}

// ============================================================
// Flash attention v2: 128 queries/block, 128-key chunks, 256 threads.
// QK^T: 8x8 microtile (1 B/FMA smem traffic, A broadcast).
// PV:   8q x 4d microtile, float4 P/V reads, P broadcast.
// smem: qs[64][128] ks[64][128] vs[128][68] ps[128][132]  = 164 KB
// ============================================================
__global__ void __launch_bounds__(256, 1) flash2_kernel() {
    extern __shared__ float sm[];
    float* qs = sm;                    // 64*128
    float* ks = qs + 64 * 128;         // 64*128
    float* vs = ks + 64 * 128;         // 128*68
    float* ps = vs + 128 * 68;         // 128*132

    int s0 = blockIdx.x * 128;
    int n = blockIdx.y, b = blockIdx.z;
    int tid = threadIdx.x;
    int tx = tid & 15, ty = tid >> 4;

    const float* qbase = g_qkv + ((size_t)b * 1536 + n * 64) * 1024 + s0;
    const float* kck = g_ckv + ((size_t)b * 1024 + n * 64) * LCTX;
    const float* vck = g_ckv + ((size_t)b * 1024 + 512 + n * 64) * LCTX;
    const float* kim = g_qkv + ((size_t)b * 1536 + 512 + n * 64) * 1024;
    const float* vim = g_qkv + ((size_t)b * 1536 + 1024 + n * 64) * 1024;

    // ---- load Q tile [64 d][128 q], float4 coalesced ----
    {
        int lane = tid & 31, row = tid >> 5;
#pragma unroll
        for (int p = 0; p < 8; p++) {
            int d = p * 8 + row;
            *(float4*)&qs[d * 128 + lane * 4] =
                *(const float4*)(qbase + (size_t)d * 1024 + lane * 4);
        }
    }

    float m_i[8], l_i[8], acc_o[8][4];
#pragma unroll
    for (int i = 0; i < 8; i++) {
        m_i[i] = -1e30f; l_i[i] = 0.f;
#pragma unroll
        for (int j = 0; j < 4; j++) acc_o[i][j] = 0.f;
    }

    int tl = tid & 127, dg = tid >> 7;

    for (int c = 0; c < NCH2; c++) {
        int t0 = c * 128;
        // ---- load K[d][t] and V[t][d] for this 128-key chunk ----
        {
            int t = t0 + tl;
#pragma unroll
            for (int p = 0; p < 32; p++) {
                int d = p * 2 + dg;
                float kv = 0.f, vv = 0.f;
                if (t < LCTX) {
                    kv = kck[d * LCTX + t];
                    vv = vck[d * LCTX + t];
                } else if (t < TKV) {
                    kv = kim[(size_t)d * 1024 + (t - LCTX)];
                    vv = vim[(size_t)d * 1024 + (t - LCTX)];
                }
                ks[d * 128 + tl] = kv;
                vs[tl * 68 + d] = vv;
            }
        }
        __syncthreads();

        // ---- S = Q^T K, 8x8 per thread ----
        float s_acc[8][8];
#pragma unroll
        for (int i = 0; i < 8; i++)
#pragma unroll
            for (int j = 0; j < 8; j++) s_acc[i][j] = 0.f;

#pragma unroll 4
        for (int d = 0; d < 64; d++) {
            float4 a0 = *(float4*)&qs[d * 128 + ty * 8];
            float4 a1 = *(float4*)&qs[d * 128 + ty * 8 + 4];
            float4 b0 = *(float4*)&ks[d * 128 + tx * 8];
            float4 b1 = *(float4*)&ks[d * 128 + tx * 8 + 4];
            float a[8] = {a0.x, a0.y, a0.z, a0.w, a1.x, a1.y, a1.z, a1.w};
            float bb[8] = {b0.x, b0.y, b0.z, b0.w, b1.x, b1.y, b1.z, b1.w};
#pragma unroll
            for (int i = 0; i < 8; i++)
#pragma unroll
                for (int j = 0; j < 8; j++) s_acc[i][j] += a[i] * bb[j];
        }

        // scale + mask
#pragma unroll
        for (int i = 0; i < 8; i++)
#pragma unroll
            for (int j = 0; j < 8; j++) {
                float sv = s_acc[i][j] * 0.125f;
                if (t0 + tx * 8 + j >= TKV) sv = -1e30f;
                s_acc[i][j] = sv;
            }

        // ---- online softmax (row split across 16 tx lanes) ----
#pragma unroll
        for (int i = 0; i < 8; i++) {
            float mx = s_acc[i][0];
#pragma unroll
            for (int j = 1; j < 8; j++) mx = fmaxf(mx, s_acc[i][j]);
#pragma unroll
            for (int off = 8; off > 0; off >>= 1)
                mx = fmaxf(mx, __shfl_xor_sync(0xffffffffu, mx, off, 16));
            float mn = fmaxf(m_i[i], mx);
            float sc = __expf(m_i[i] - mn);
            m_i[i] = mn;
            float ls = 0.f;
#pragma unroll
            for (int j = 0; j < 8; j++) {
                float pv = __expf(s_acc[i][j] - mn);
                s_acc[i][j] = pv;
                ls += pv;
            }
#pragma unroll
            for (int off = 8; off > 0; off >>= 1)
                ls += __shfl_xor_sync(0xffffffffu, ls, off, 16);
            l_i[i] = l_i[i] * sc + ls;
#pragma unroll
            for (int j = 0; j < 4; j++) acc_o[i][j] *= sc;
            float4 w0 = {s_acc[i][0], s_acc[i][1], s_acc[i][2], s_acc[i][3]};
            float4 w1 = {s_acc[i][4], s_acc[i][5], s_acc[i][6], s_acc[i][7]};
            *(float4*)&ps[(ty * 8 + i) * 132 + tx * 8] = w0;
            *(float4*)&ps[(ty * 8 + i) * 132 + tx * 8 + 4] = w1;
        }
        __syncthreads();

        // ---- O += P V : 8q x 4d per thread, 4 t-steps per iter ----
#pragma unroll 2
        for (int t4 = 0; t4 < 128; t4 += 4) {
            float4 v0 = *(float4*)&vs[(t4 + 0) * 68 + tx * 4];
            float4 v1 = *(float4*)&vs[(t4 + 1) * 68 + tx * 4];
            float4 v2 = *(float4*)&vs[(t4 + 2) * 68 + tx * 4];
            float4 v3 = *(float4*)&vs[(t4 + 3) * 68 + tx * 4];
#pragma unroll
            for (int i = 0; i < 8; i++) {
                float4 pv = *(float4*)&ps[(ty * 8 + i) * 132 + t4];
                acc_o[i][0] += pv.x * v0.x + pv.y * v1.x + pv.z * v2.x + pv.w * v3.x;
                acc_o[i][1] += pv.x * v0.y + pv.y * v1.y + pv.z * v2.y + pv.w * v3.y;
                acc_o[i][2] += pv.x * v0.z + pv.y * v1.z + pv.z * v2.z + pv.w * v3.z;
                acc_o[i][3] += pv.x * v0.w + pv.y * v1.w + pv.z * v2.w + pv.w * v3.w;
            }
        }
        __syncthreads();
    }

    // ---- normalize, stage in smem (reuse ps as [128 q][68 d]), copy out ----
#pragma unroll
    for (int i = 0; i < 8; i++) {
        float inv = 1.f / l_i[i];
        float4 o;
        o.x = acc_o[i][0] * inv; o.y = acc_o[i][1] * inv;
        o.z = acc_o[i][2] * inv; o.w = acc_o[i][3] * inv;
        *(float4*)&ps[(ty * 8 + i) * 68 + tx * 4] = o;
    }
    __syncthreads();

    float* outp = g_attn + ((size_t)b * 512 + n * 64) * 1024 + s0;
#pragma unroll
    for (int p = 0; p < 32; p++) {
        int d = p * 2 + dg;
        outp[(size_t)d * 1024 + tl] = ps[tl * 68 + d];
    }
}

// ============================================================
extern "C" void kernel_launch(void* const* d_in, const int* in_sizes, int n_in,
                              void* d_out, int out_size) {
    const float* x       = (const float*)d_in[0];
    const float* context = (const float*)d_in[1];
    const float* gamma   = (const float*)d_in[2];
    const float* beta    = (const float*)d_in[3];
    const float* qkv_w   = (const float*)d_in[4];
    const float* qkv_b   = (const float*)d_in[5];
    const float* ckv_w   = (const float*)d_in[6];
    const float* ckv_b   = (const float*)d_in[7];
    const float* proj_w  = (const float*)d_in[8];
    const float* proj_b  = (const float*)d_in[9];
    float* out = (float*)d_out;

    float *xn_p, *qkv_p, *attn_p;
    cudaGetSymbolAddress((void**)&xn_p, g_xn);
    cudaGetSymbolAddress((void**)&qkv_p, g_qkv);
    cudaGetSymbolAddress((void**)&attn_p, g_attn);

    // 1. GroupNorm
    gn_kernel<<<BATCH * 32, 256>>>(x, gamma, beta, xn_p);

    // 2. QKV projection: M=1536, N=1024, K=512, batched 8
    gemm128<<<dim3(8, 12, BATCH), 256>>>(qkv_w, qkv_b, xn_p, nullptr, qkv_p, 1536, 1024, 512);

    // 3. Context KV projection
    ckv_kernel<<<dim3(16, BATCH), 256>>>(context, ckv_w, ckv_b);

    // 4. Flash attention v2 (128q x 128k tiles)
    int smem = (64 * 128 * 2 + 128 * 68 + 128 * 132) * (int)sizeof(float);  // 167936 B
    cudaFuncSetAttribute(flash2_kernel, cudaFuncAttributeMaxDynamicSharedMemorySize, smem);
    flash2_kernel<<<dim3(8, HEADS, BATCH), 256, smem>>>();

    // 5. Output projection + bias + residual
    gemm128<<<dim3(8, 4, BATCH), 256>>>(proj_w, proj_b, attn_p, x, out, 512, 1024, 512);
}

// round 5
// speedup vs baseline: 1.4533x; 1.4533x over previous
#include <cuda_runtime.h>
#include <math.h>
#include <stdint.h>

#define BATCH 8
#define DIMC 512
#define HW 1024
#define HEADS 8
#define HD 64
#define LCTX 77
#define CTXD 768
#define TKV 1101      // 77 ctx + 1024 image keys
#define NCHUNK 18     // ceil(1101/64)

// ---- scratch (device globals; no allocation allowed) ----
__device__ float g_xn[BATCH * DIMC * HW];        // 16 MB groupnormed x
__device__ float g_qkv[BATCH * 3 * DIMC * HW];   // 50 MB qkv projections
__device__ float g_ckv[BATCH * 2 * DIMC * LCTX]; // 2.5 MB context kv, [b][o][l]
__device__ float g_attn[BATCH * DIMC * HW];      // 16 MB attention output

// round fp32 -> tf32 (round-to-nearest, keep 10 mantissa bits), pure ALU
__device__ __forceinline__ float f2tf(float x) {
    uint32_t u = __float_as_uint(x);
    u = (u + 0x1000u) & 0xFFFFE000u;
    return __uint_as_float(u);
}

// ============================================================
// GroupNorm
// ============================================================
__global__ void gn_kernel(const float* __restrict__ x, const float* __restrict__ gamma,
                          const float* __restrict__ beta, float* __restrict__ xn) {
    __shared__ float ssum[256], ssq[256];
    int bg = blockIdx.x;
    int b = bg >> 5, g = bg & 31;
    const float* xp = x + ((size_t)b * DIMC + g * 16) * HW;
    float* xo = xn + ((size_t)b * DIMC + g * 16) * HW;
    int tid = threadIdx.x;

    float s = 0.f, sq = 0.f;
#pragma unroll
    for (int i = 0; i < 64; i++) {
        float v = xp[tid + i * 256];
        s += v; sq += v * v;
    }
    ssum[tid] = s; ssq[tid] = sq;
    __syncthreads();
    for (int off = 128; off > 0; off >>= 1) {
        if (tid < off) { ssum[tid] += ssum[tid + off]; ssq[tid] += ssq[tid + off]; }
        __syncthreads();
    }
    float mu = ssum[0] * (1.f / 16384.f);
    float var = ssq[0] * (1.f / 16384.f) - mu * mu;
    float inv = rsqrtf(var + 1e-5f);
#pragma unroll
    for (int i = 0; i < 64; i++) {
        int idx = tid + i * 256;
        int c = g * 16 + (idx >> 10);
        xo[idx] = (xp[idx] - mu) * inv * gamma[c] + beta[c];
    }
}

// ============================================================
// tf32 tensor-core GEMM: C[b][m][n] = sum_k W[m][k]*X[b][k][n] + bias[m] (+res)
// 128x128 block tile, BK=32, 256 threads (8 warps), warp tile 64x32,
// mma.sync.m16n8k8 tf32, fp32 accumulate.
// ============================================================
__global__ void __launch_bounds__(256) gemm_tf32(
        const float* __restrict__ W, const float* __restrict__ bias,
        const float* __restrict__ X, const float* __restrict__ res,
        float* __restrict__ C, int M, int N, int K) {
    __shared__ float ws[32 * 132];   // [k][m], tf32 bits
    __shared__ float xs[32 * 132];   // [k][n], tf32 bits

    int b = blockIdx.z;
    int m0 = blockIdx.y * 128, n0 = blockIdx.x * 128;
    const float* Xb = X + (size_t)b * K * N;
    int tid = threadIdx.x;
    int warp = tid >> 5, lane = tid & 31;
    int warpM = warp >> 2, warpN = warp & 3;      // 2 x 4 warp grid
    int g = lane >> 2, tig = lane & 3;            // groupID, thread-in-group

    float c[4][4][4];
#pragma unroll
    for (int mt = 0; mt < 4; mt++)
#pragma unroll
        for (int nt = 0; nt < 4; nt++)
#pragma unroll
            for (int r = 0; r < 4; r++) c[mt][nt][r] = 0.f;

    int wr = tid >> 3;              // 0..31 (row group for W load)
    int wc4 = (tid & 7) * 4;        // k offset
    int xkr = tid >> 5;             // 0..7
    int xn4 = (tid & 31) * 4;

    for (int k0 = 0; k0 < K; k0 += 32) {
        // stage W tile [m0..+127][k0..+31] -> ws[k][m] (transposed, tf32)
#pragma unroll
        for (int p = 0; p < 4; p++) {
            int m = p * 32 + wr;
            float4 wv = *(const float4*)(W + (size_t)(m0 + m) * K + k0 + wc4);
            ws[(wc4 + 0) * 132 + m] = f2tf(wv.x);
            ws[(wc4 + 1) * 132 + m] = f2tf(wv.y);
            ws[(wc4 + 2) * 132 + m] = f2tf(wv.z);
            ws[(wc4 + 3) * 132 + m] = f2tf(wv.w);
        }
        // stage X tile [k0..+31][n0..+127] -> xs[k][n] (tf32)
#pragma unroll
        for (int p = 0; p < 4; p++) {
            int k = p * 8 + xkr;
            float4 xv = *(const float4*)(Xb + (size_t)(k0 + k) * N + n0 + xn4);
            float4 t;
            t.x = f2tf(xv.x);
            t.y = f2tf(xv.y);
            t.z = f2tf(xv.z);
            t.w = f2tf(xv.w);
            *(float4*)&xs[k * 132 + xn4] = t;
        }
        __syncthreads();

#pragma unroll
        for (int ks = 0; ks < 4; ks++) {
            int k8 = ks * 8;
            uint32_t a[4][4], bb[4][2];
#pragma unroll
            for (int mt = 0; mt < 4; mt++) {
                int mo = warpM * 64 + mt * 16;
                a[mt][0] = __float_as_uint(ws[(k8 + tig) * 132 + mo + g]);
                a[mt][1] = __float_as_uint(ws[(k8 + tig) * 132 + mo + g + 8]);
                a[mt][2] = __float_as_uint(ws[(k8 + tig + 4) * 132 + mo + g]);
                a[mt][3] = __float_as_uint(ws[(k8 + tig + 4) * 132 + mo + g + 8]);
            }
#pragma unroll
            for (int nt = 0; nt < 4; nt++) {
                int no = warpN * 32 + nt * 8;
                bb[nt][0] = __float_as_uint(xs[(k8 + tig) * 132 + no + g]);
                bb[nt][1] = __float_as_uint(xs[(k8 + tig + 4) * 132 + no + g]);
            }
#pragma unroll
            for (int mt = 0; mt < 4; mt++)
#pragma unroll
                for (int nt = 0; nt < 4; nt++) {
                    asm volatile(
                        "mma.sync.aligned.m16n8k8.row.col.f32.tf32.tf32.f32 "
                        "{%0,%1,%2,%3}, {%4,%5,%6,%7}, {%8,%9}, {%0,%1,%2,%3};"
                        : "+f"(c[mt][nt][0]), "+f"(c[mt][nt][1]),
                          "+f"(c[mt][nt][2]), "+f"(c[mt][nt][3])
                        : "r"(a[mt][0]), "r"(a[mt][1]), "r"(a[mt][2]), "r"(a[mt][3]),
                          "r"(bb[nt][0]), "r"(bb[nt][1]));
                }
        }
        __syncthreads();
    }

    // epilogue: C[m][n], m = m0+warpM*64+mt*16+g(+8), n = n0+warpN*32+nt*8+2*tig(+1)
#pragma unroll
    for (int mt = 0; mt < 4; mt++) {
#pragma unroll
        for (int half = 0; half < 2; half++) {
            int m = m0 + warpM * 64 + mt * 16 + g + half * 8;
            float bv = bias[m];
            size_t rowoff = ((size_t)b * M + m) * N;
#pragma unroll
            for (int nt = 0; nt < 4; nt++) {
                int n = n0 + warpN * 32 + nt * 8 + tig * 2;
                float v0 = c[mt][nt][half * 2 + 0] + bv;
                float v1 = c[mt][nt][half * 2 + 1] + bv;
                if (res) {
                    v0 += res[rowoff + n];
                    v1 += res[rowoff + n + 1];
                }
                C[rowoff + n] = v0;
                C[rowoff + n + 1] = v1;
            }
        }
    }
}

// ============================================================
// ckv GEMM (fp32, small)
// ============================================================
__global__ void ckv_kernel(const float* __restrict__ ctx, const float* __restrict__ W,
                           const float* __restrict__ bias) {
    __shared__ float ws2[32 * 65];
    __shared__ float cs[32 * 81];
    int ot = blockIdx.x, b = blockIdx.y;
    int tid = threadIdx.x;
    int tx = tid & 15, tg = tid >> 4;
    int cc = tid & 31, rr = tid >> 5;
    int ob = tg * 4, lb = tx * 5;

    float acc[4][5];
#pragma unroll
    for (int i = 0; i < 4; i++)
#pragma unroll
        for (int j = 0; j < 5; j++) acc[i][j] = 0.f;

    for (int c0 = 0; c0 < CTXD; c0 += 32) {
#pragma unroll
        for (int p = 0; p < 8; p++) {
            int o = p * 8 + rr;
            ws2[cc * 65 + o] = W[(size_t)(ot * 64 + o) * CTXD + c0 + cc];
        }
#pragma unroll
        for (int p = 0; p < 10; p++) {
            int l = p * 8 + rr;
            float v = (l < LCTX) ? ctx[((size_t)b * LCTX + l) * CTXD + c0 + cc] : 0.f;
            cs[cc * 81 + l] = v;
        }
        __syncthreads();
#pragma unroll
        for (int kk = 0; kk < 32; kk++) {
            float wv[4], cv[5];
#pragma unroll
            for (int i = 0; i < 4; i++) wv[i] = ws2[kk * 65 + ob + i];
#pragma unroll
            for (int j = 0; j < 5; j++) cv[j] = cs[kk * 81 + lb + j];
#pragma unroll
            for (int i = 0; i < 4; i++)
#pragma unroll
                for (int j = 0; j < 5; j++) acc[i][j] += wv[i] * cv[j];
        }
        __syncthreads();
    }

#pragma unroll
    for (int i = 0; i < 4; i++) {
        int o = ot * 64 + ob + i;
        float bv = bias[o];
#pragma unroll
        for (int j = 0; j < 5; j++) {
            int l = lb + j;
            if (l < LCTX)
                g_ckv[((size_t)b * 1024 + o) * LCTX + l] = acc[i][j] + bv;
        }
    }
}

// ============================================================
// Flash attention v1 (known good): 64q/block, 64-key chunks, 256 threads.
// ============================================================
__global__ void flash_kernel() {
    extern __shared__ float sm[];
    float* qs = sm;                  // 4096
    float* ks = qs + 64 * 64;        // 4096
    float* vs = ks + 64 * 64;        // 64*65
    float* ps = vs + 64 * 65;        // 64*65

    int s0 = blockIdx.x * 64;
    int n = blockIdx.y, b = blockIdx.z;
    int tid = threadIdx.x;
    int tx = tid & 15, ty = tid >> 4;
    int lt = tid & 63, ld4 = tid >> 6;

    const float* qbase = g_qkv + ((size_t)b * 1536 + n * 64) * 1024 + s0;
    const float* kck = g_ckv + ((size_t)b * 1024 + n * 64) * LCTX;
    const float* vck = g_ckv + ((size_t)b * 1024 + 512 + n * 64) * LCTX;
    const float* kim = g_qkv + ((size_t)b * 1536 + 512 + n * 64) * 1024;
    const float* vim = g_qkv + ((size_t)b * 1536 + 1024 + n * 64) * 1024;

#pragma unroll
    for (int p = 0; p < 16; p++) {
        int d = p * 4 + ld4;
        qs[d * 64 + lt] = qbase[(size_t)d * 1024 + lt];
    }

    float m_i[4], l_i[4], acc_o[4][4];
#pragma unroll
    for (int i = 0; i < 4; i++) {
        m_i[i] = -1e30f; l_i[i] = 0.f;
#pragma unroll
        for (int j = 0; j < 4; j++) acc_o[i][j] = 0.f;
    }

    for (int c = 0; c < NCHUNK; c++) {
        int t0 = c * 64;
#pragma unroll
        for (int p = 0; p < 16; p++) {
            int d = p * 4 + ld4;
            int t = t0 + lt;
            float kv, vv;
            if (t < LCTX) {
                kv = kck[d * LCTX + t];
                vv = vck[d * LCTX + t];
            } else if (t < TKV) {
                kv = kim[(size_t)d * 1024 + (t - LCTX)];
                vv = vim[(size_t)d * 1024 + (t - LCTX)];
            } else {
                kv = 0.f; vv = 0.f;
            }
            ks[d * 64 + lt] = kv;
            vs[lt * 65 + d] = vv;
        }
        __syncthreads();

        float s_acc[4][4];
#pragma unroll
        for (int i = 0; i < 4; i++)
#pragma unroll
            for (int j = 0; j < 4; j++) s_acc[i][j] = 0.f;
        for (int d = 0; d < 64; d++) {
            float4 a = *(float4*)&qs[d * 64 + ty * 4];
            float4 bb = *(float4*)&ks[d * 64 + tx * 4];
            float av[4] = {a.x, a.y, a.z, a.w};
            float bv[4] = {bb.x, bb.y, bb.z, bb.w};
#pragma unroll
            for (int i = 0; i < 4; i++)
#pragma unroll
                for (int j = 0; j < 4; j++) s_acc[i][j] += av[i] * bv[j];
        }
#pragma unroll
        for (int i = 0; i < 4; i++)
#pragma unroll
            for (int j = 0; j < 4; j++) {
                float sv = s_acc[i][j] * 0.125f;
                if (t0 + tx * 4 + j >= TKV) sv = -1e30f;
                s_acc[i][j] = sv;
            }

#pragma unroll
        for (int i = 0; i < 4; i++) {
            float mx = fmaxf(fmaxf(s_acc[i][0], s_acc[i][1]), fmaxf(s_acc[i][2], s_acc[i][3]));
#pragma unroll
            for (int off = 8; off > 0; off >>= 1)
                mx = fmaxf(mx, __shfl_xor_sync(0xffffffffu, mx, off, 16));
            float mn = fmaxf(m_i[i], mx);
            float sc = __expf(m_i[i] - mn);
            m_i[i] = mn;
            float ls = 0.f;
#pragma unroll
            for (int j = 0; j < 4; j++) {
                float pv = __expf(s_acc[i][j] - mn);
                s_acc[i][j] = pv;
                ls += pv;
            }
#pragma unroll
            for (int off = 8; off > 0; off >>= 1)
                ls += __shfl_xor_sync(0xffffffffu, ls, off, 16);
            l_i[i] = l_i[i] * sc + ls;
#pragma unroll
            for (int j = 0; j < 4; j++) acc_o[i][j] *= sc;
#pragma unroll
            for (int j = 0; j < 4; j++) ps[(ty * 4 + i) * 65 + tx * 4 + j] = s_acc[i][j];
        }
        __syncthreads();

        for (int tt = 0; tt < 64; tt++) {
            float a0 = ps[(ty * 4 + 0) * 65 + tt];
            float a1 = ps[(ty * 4 + 1) * 65 + tt];
            float a2 = ps[(ty * 4 + 2) * 65 + tt];
            float a3 = ps[(ty * 4 + 3) * 65 + tt];
            float b0 = vs[tt * 65 + tx * 4 + 0];
            float b1 = vs[tt * 65 + tx * 4 + 1];
            float b2 = vs[tt * 65 + tx * 4 + 2];
            float b3 = vs[tt * 65 + tx * 4 + 3];
            acc_o[0][0] += a0 * b0; acc_o[0][1] += a0 * b1; acc_o[0][2] += a0 * b2; acc_o[0][3] += a0 * b3;
            acc_o[1][0] += a1 * b0; acc_o[1][1] += a1 * b1; acc_o[1][2] += a1 * b2; acc_o[1][3] += a1 * b3;
            acc_o[2][0] += a2 * b0; acc_o[2][1] += a2 * b1; acc_o[2][2] += a2 * b2; acc_o[2][3] += a2 * b3;
            acc_o[3][0] += a3 * b0; acc_o[3][1] += a3 * b1; acc_o[3][2] += a3 * b2; acc_o[3][3] += a3 * b3;
        }
        __syncthreads();
    }

#pragma unroll
    for (int i = 0; i < 4; i++) {
        float inv = 1.f / l_i[i];
#pragma unroll
        for (int j = 0; j < 4; j++)
            ps[(ty * 4 + i) * 65 + tx * 4 + j] = acc_o[i][j] * inv;
    }
    __syncthreads();

    float* outp = g_attn + ((size_t)b * 512 + n * 64) * 1024 + s0;
#pragma unroll
    for (int p = 0; p < 16; p++) {
        int d = p * 4 + ld4;
        outp[(size_t)d * 1024 + lt] = ps[lt * 65 + d];
    }
}

// ============================================================
extern "C" void kernel_launch(void* const* d_in, const int* in_sizes, int n_in,
                              void* d_out, int out_size) {
    const float* x       = (const float*)d_in[0];
    const float* context = (const float*)d_in[1];
    const float* gamma   = (const float*)d_in[2];
    const float* beta    = (const float*)d_in[3];
    const float* qkv_w   = (const float*)d_in[4];
    const float* qkv_b   = (const float*)d_in[5];
    const float* ckv_w   = (const float*)d_in[6];
    const float* ckv_b   = (const float*)d_in[7];
    const float* proj_w  = (const float*)d_in[8];
    const float* proj_b  = (const float*)d_in[9];
    float* out = (float*)d_out;

    float *xn_p, *qkv_p, *attn_p;
    cudaGetSymbolAddress((void**)&xn_p, g_xn);
    cudaGetSymbolAddress((void**)&qkv_p, g_qkv);
    cudaGetSymbolAddress((void**)&attn_p, g_attn);

    // 1. GroupNorm
    gn_kernel<<<BATCH * 32, 256>>>(x, gamma, beta, xn_p);

    // 2. QKV projection (tf32 tensor cores): M=1536, N=1024, K=512
    gemm_tf32<<<dim3(8, 12, BATCH), 256>>>(qkv_w, qkv_b, xn_p, nullptr, qkv_p, 1536, 1024, 512);

    // 3. Context KV projection
    ckv_kernel<<<dim3(16, BATCH), 256>>>(context, ckv_w, ckv_b);

    // 4. Flash attention v1
    int smem = (64 * 64 * 2 + 64 * 65 * 2) * (int)sizeof(float);  // 66048 B
    cudaFuncSetAttribute(flash_kernel, cudaFuncAttributeMaxDynamicSharedMemorySize, smem);
    flash_kernel<<<dim3(16, HEADS, BATCH), 256, smem>>>();

    // 5. Output projection + bias + residual (tf32 tensor cores)
    gemm_tf32<<<dim3(8, 4, BATCH), 256>>>(proj_w, proj_b, attn_p, x, out, 512, 1024, 512);
}

// round 6
// speedup vs baseline: 2.2301x; 1.5346x over previous
#include <cuda_runtime.h>
#include <math.h>
#include <stdint.h>

#define BATCH 8
#define DIMC 512
#define HW 1024
#define HEADS 8
#define HD 64
#define LCTX 77
#define CTXD 768
#define TKV 1101      // 77 ctx + 1024 image keys
#define NCHUNK 18     // ceil(1101/64)

// ---- scratch (device globals; no allocation allowed) ----
__device__ float g_xn[BATCH * DIMC * HW];
__device__ float g_qkv[BATCH * 3 * DIMC * HW];
__device__ float g_ckv[BATCH * 2 * DIMC * LCTX];
__device__ float g_attn[BATCH * DIMC * HW];

// round fp32 -> tf32 (round-to-nearest, keep 10 mantissa bits), pure ALU
__device__ __forceinline__ float f2tf(float x) {
    uint32_t u = __float_as_uint(x);
    u = (u + 0x1000u) & 0xFFFFE000u;
    return __uint_as_float(u);
}

#define MMA_TF32(c0,c1,c2,c3,a0,a1,a2,a3,b0,b1)                               \
    asm volatile(                                                              \
        "mma.sync.aligned.m16n8k8.row.col.f32.tf32.tf32.f32 "                  \
        "{%0,%1,%2,%3}, {%4,%5,%6,%7}, {%8,%9}, {%0,%1,%2,%3};"                \
        : "+f"(c0), "+f"(c1), "+f"(c2), "+f"(c3)                               \
        : "r"(a0), "r"(a1), "r"(a2), "r"(a3), "r"(b0), "r"(b1))

// ============================================================
// GroupNorm
// ============================================================
__global__ void gn_kernel(const float* __restrict__ x, const float* __restrict__ gamma,
                          const float* __restrict__ beta, float* __restrict__ xn) {
    __shared__ float ssum[256], ssq[256];
    int bg = blockIdx.x;
    int b = bg >> 5, g = bg & 31;
    const float* xp = x + ((size_t)b * DIMC + g * 16) * HW;
    float* xo = xn + ((size_t)b * DIMC + g * 16) * HW;
    int tid = threadIdx.x;

    float s = 0.f, sq = 0.f;
#pragma unroll
    for (int i = 0; i < 64; i++) {
        float v = xp[tid + i * 256];
        s += v; sq += v * v;
    }
    ssum[tid] = s; ssq[tid] = sq;
    __syncthreads();
    for (int off = 128; off > 0; off >>= 1) {
        if (tid < off) { ssum[tid] += ssum[tid + off]; ssq[tid] += ssq[tid + off]; }
        __syncthreads();
    }
    float mu = ssum[0] * (1.f / 16384.f);
    float var = ssq[0] * (1.f / 16384.f) - mu * mu;
    float inv = rsqrtf(var + 1e-5f);
#pragma unroll
    for (int i = 0; i < 64; i++) {
        int idx = tid + i * 256;
        int c = g * 16 + (idx >> 10);
        xo[idx] = (xp[idx] - mu) * inv * gamma[c] + beta[c];
    }
}

// ============================================================
// tf32 tensor-core GEMM (validated R5)
// ============================================================
__global__ void __launch_bounds__(256) gemm_tf32(
        const float* __restrict__ W, const float* __restrict__ bias,
        const float* __restrict__ X, const float* __restrict__ res,
        float* __restrict__ C, int M, int N, int K) {
    __shared__ float ws[32 * 132];
    __shared__ float xs[32 * 132];

    int b = blockIdx.z;
    int m0 = blockIdx.y * 128, n0 = blockIdx.x * 128;
    const float* Xb = X + (size_t)b * K * N;
    int tid = threadIdx.x;
    int warp = tid >> 5, lane = tid & 31;
    int warpM = warp >> 2, warpN = warp & 3;
    int g = lane >> 2, tig = lane & 3;

    float c[4][4][4];
#pragma unroll
    for (int mt = 0; mt < 4; mt++)
#pragma unroll
        for (int nt = 0; nt < 4; nt++)
#pragma unroll
            for (int r = 0; r < 4; r++) c[mt][nt][r] = 0.f;

    int wr = tid >> 3;
    int wc4 = (tid & 7) * 4;
    int xkr = tid >> 5;
    int xn4 = (tid & 31) * 4;

    for (int k0 = 0; k0 < K; k0 += 32) {
#pragma unroll
        for (int p = 0; p < 4; p++) {
            int m = p * 32 + wr;
            float4 wv = *(const float4*)(W + (size_t)(m0 + m) * K + k0 + wc4);
            ws[(wc4 + 0) * 132 + m] = f2tf(wv.x);
            ws[(wc4 + 1) * 132 + m] = f2tf(wv.y);
            ws[(wc4 + 2) * 132 + m] = f2tf(wv.z);
            ws[(wc4 + 3) * 132 + m] = f2tf(wv.w);
        }
#pragma unroll
        for (int p = 0; p < 4; p++) {
            int k = p * 8 + xkr;
            float4 xv = *(const float4*)(Xb + (size_t)(k0 + k) * N + n0 + xn4);
            float4 t;
            t.x = f2tf(xv.x); t.y = f2tf(xv.y); t.z = f2tf(xv.z); t.w = f2tf(xv.w);
            *(float4*)&xs[k * 132 + xn4] = t;
        }
        __syncthreads();

#pragma unroll
        for (int ks = 0; ks < 4; ks++) {
            int k8 = ks * 8;
            uint32_t a[4][4], bb[4][2];
#pragma unroll
            for (int mt = 0; mt < 4; mt++) {
                int mo = warpM * 64 + mt * 16;
                a[mt][0] = __float_as_uint(ws[(k8 + tig) * 132 + mo + g]);
                a[mt][1] = __float_as_uint(ws[(k8 + tig) * 132 + mo + g + 8]);
                a[mt][2] = __float_as_uint(ws[(k8 + tig + 4) * 132 + mo + g]);
                a[mt][3] = __float_as_uint(ws[(k8 + tig + 4) * 132 + mo + g + 8]);
            }
#pragma unroll
            for (int nt = 0; nt < 4; nt++) {
                int no = warpN * 32 + nt * 8;
                bb[nt][0] = __float_as_uint(xs[(k8 + tig) * 132 + no + g]);
                bb[nt][1] = __float_as_uint(xs[(k8 + tig + 4) * 132 + no + g]);
            }
#pragma unroll
            for (int mt = 0; mt < 4; mt++)
#pragma unroll
                for (int nt = 0; nt < 4; nt++)
                    MMA_TF32(c[mt][nt][0], c[mt][nt][1], c[mt][nt][2], c[mt][nt][3],
                             a[mt][0], a[mt][1], a[mt][2], a[mt][3],
                             bb[nt][0], bb[nt][1]);
        }
        __syncthreads();
    }

#pragma unroll
    for (int mt = 0; mt < 4; mt++) {
#pragma unroll
        for (int half = 0; half < 2; half++) {
            int m = m0 + warpM * 64 + mt * 16 + g + half * 8;
            float bv = bias[m];
            size_t rowoff = ((size_t)b * M + m) * N;
#pragma unroll
            for (int nt = 0; nt < 4; nt++) {
                int n = n0 + warpN * 32 + nt * 8 + tig * 2;
                float v0 = c[mt][nt][half * 2 + 0] + bv;
                float v1 = c[mt][nt][half * 2 + 1] + bv;
                if (res) {
                    v0 += res[rowoff + n];
                    v1 += res[rowoff + n + 1];
                }
                C[rowoff + n] = v0;
                C[rowoff + n + 1] = v1;
            }
        }
    }
}

// ============================================================
// ckv GEMM (fp32, small)
// ============================================================
__global__ void ckv_kernel(const float* __restrict__ ctx, const float* __restrict__ W,
                           const float* __restrict__ bias) {
    __shared__ float ws2[32 * 65];
    __shared__ float cs[32 * 81];
    int ot = blockIdx.x, b = blockIdx.y;
    int tid = threadIdx.x;
    int tx = tid & 15, tg = tid >> 4;
    int cc = tid & 31, rr = tid >> 5;
    int ob = tg * 4, lb = tx * 5;

    float acc[4][5];
#pragma unroll
    for (int i = 0; i < 4; i++)
#pragma unroll
        for (int j = 0; j < 5; j++) acc[i][j] = 0.f;

    for (int c0 = 0; c0 < CTXD; c0 += 32) {
#pragma unroll
        for (int p = 0; p < 8; p++) {
            int o = p * 8 + rr;
            ws2[cc * 65 + o] = W[(size_t)(ot * 64 + o) * CTXD + c0 + cc];
        }
#pragma unroll
        for (int p = 0; p < 10; p++) {
            int l = p * 8 + rr;
            float v = (l < LCTX) ? ctx[((size_t)b * LCTX + l) * CTXD + c0 + cc] : 0.f;
            cs[cc * 81 + l] = v;
        }
        __syncthreads();
#pragma unroll
        for (int kk = 0; kk < 32; kk++) {
            float wv[4], cv[5];
#pragma unroll
            for (int i = 0; i < 4; i++) wv[i] = ws2[kk * 65 + ob + i];
#pragma unroll
            for (int j = 0; j < 5; j++) cv[j] = cs[kk * 81 + lb + j];
#pragma unroll
            for (int i = 0; i < 4; i++)
#pragma unroll
                for (int j = 0; j < 5; j++) acc[i][j] += wv[i] * cv[j];
        }
        __syncthreads();
    }

#pragma unroll
    for (int i = 0; i < 4; i++) {
        int o = ot * 64 + ob + i;
        float bv = bias[o];
#pragma unroll
        for (int j = 0; j < 5; j++) {
            int l = lb + j;
            if (l < LCTX)
                g_ckv[((size_t)b * 1024 + o) * LCTX + l] = acc[i][j] + bv;
        }
    }
}

// ============================================================
// Flash attention v3: tensor-core (tf32 mma) flash.
// 256 thr / 8 warps, 128 q per block (16 q per warp), 64-key chunks.
// smem: qs[128][68] (Q[q][d]), kd[64][72] (K^T[d][t]),
//       vt[64][72] (V[t][d], XOR-swizzled), ps[128][68] (P / out staging)
// ============================================================
#define QSTR 68
#define KSTR 72
#define VSTR 72
#define PSTR 68
#define VSWZ(t, d) ((d) ^ ((t) & 4) ^ (((t) & 8) >> 1))

__global__ void __launch_bounds__(256, 2) flash3_kernel() {
    extern __shared__ float sm[];
    float* qs = sm;                        // 128*68
    float* kd = qs + 128 * QSTR;           // 64*72
    float* vt = kd + 64 * KSTR;            // 64*72
    float* ps = vt + 64 * VSTR;            // 128*68

    int s0 = blockIdx.x * 128;
    int n = blockIdx.y, b = blockIdx.z;
    int tid = threadIdx.x;
    int warp = tid >> 5, lane = tid & 31;
    int g = lane >> 2, tig = lane & 3;
    int q0w = warp * 16;
    float* psw = ps + q0w * PSTR;          // warp-private P staging

    const float* qbase = g_qkv + ((size_t)b * 1536 + n * 64) * 1024 + s0;
    const float* kck = g_ckv + ((size_t)b * 1024 + n * 64) * LCTX;
    const float* vck = g_ckv + ((size_t)b * 1024 + 512 + n * 64) * LCTX;
    const float* kim = g_qkv + ((size_t)b * 1536 + 512 + n * 64) * 1024;
    const float* vim = g_qkv + ((size_t)b * 1536 + 1024 + n * 64) * 1024;

    // ---- load Q[q][d] (transpose from [d][s]), rounded to tf32 ----
    {
        int s = tid & 127, hi = tid >> 7;
#pragma unroll
        for (int p = 0; p < 32; p++) {
            int d = p * 2 + hi;
            qs[s * QSTR + d] = f2tf(qbase[(size_t)d * 1024 + s]);
        }
    }

    float m0r = -1e30f, m1r = -1e30f, l0 = 0.f, l1 = 0.f;
    float o[8][4];
#pragma unroll
    for (int nt = 0; nt < 8; nt++)
#pragma unroll
        for (int r = 0; r < 4; r++) o[nt][r] = 0.f;

    int tld = tid & 63, dld = tid >> 6;

    for (int c = 0; c < NCHUNK; c++) {
        int t0 = c * 64;
        // ---- load K^T[d][t], V[t][d] (swizzled), tf32-rounded ----
#pragma unroll
        for (int p = 0; p < 16; p++) {
            int d = p * 4 + dld;
            int gt = t0 + tld;
            float kv, vv;
            if (gt < LCTX) {
                kv = kck[d * LCTX + gt];
                vv = vck[d * LCTX + gt];
            } else if (gt < TKV) {
                kv = kim[(size_t)d * 1024 + (gt - LCTX)];
                vv = vim[(size_t)d * 1024 + (gt - LCTX)];
            } else {
                kv = 0.f; vv = 0.f;
            }
            kd[d * KSTR + tld] = f2tf(kv);
            vt[tld * VSTR + VSWZ(tld, d)] = f2tf(vv);
        }
        __syncthreads();

        // ---- S = Q K^T (tf32 mma), S[16q x 64t] per warp ----
        float sfr[8][4];
#pragma unroll
        for (int nt = 0; nt < 8; nt++)
#pragma unroll
            for (int r = 0; r < 4; r++) sfr[nt][r] = 0.f;

#pragma unroll
        for (int ks = 0; ks < 8; ks++) {
            int k8 = ks * 8;
            uint32_t a0 = __float_as_uint(qs[(q0w + g) * QSTR + k8 + tig]);
            uint32_t a1 = __float_as_uint(qs[(q0w + g + 8) * QSTR + k8 + tig]);
            uint32_t a2 = __float_as_uint(qs[(q0w + g) * QSTR + k8 + tig + 4]);
            uint32_t a3 = __float_as_uint(qs[(q0w + g + 8) * QSTR + k8 + tig + 4]);
#pragma unroll
            for (int nt = 0; nt < 8; nt++) {
                uint32_t b0 = __float_as_uint(kd[(k8 + tig) * KSTR + nt * 8 + g]);
                uint32_t b1 = __float_as_uint(kd[(k8 + tig + 4) * KSTR + nt * 8 + g]);
                MMA_TF32(sfr[nt][0], sfr[nt][1], sfr[nt][2], sfr[nt][3],
                         a0, a1, a2, a3, b0, b1);
            }
        }

        // scale + mask (mask only matters in last chunk)
#pragma unroll
        for (int nt = 0; nt < 8; nt++)
#pragma unroll
            for (int r = 0; r < 4; r++) sfr[nt][r] *= 0.125f;
        if (t0 + 64 > TKV) {
#pragma unroll
            for (int nt = 0; nt < 8; nt++) {
                int t = t0 + nt * 8 + tig * 2;
                if (t >= TKV) { sfr[nt][0] = -1e30f; sfr[nt][2] = -1e30f; }
                if (t + 1 >= TKV) { sfr[nt][1] = -1e30f; sfr[nt][3] = -1e30f; }
            }
        }

        // ---- online softmax: row g (regs 0,1), row g+8 (regs 2,3) ----
        float mx0 = -1e30f, mx1 = -1e30f;
#pragma unroll
        for (int nt = 0; nt < 8; nt++) {
            mx0 = fmaxf(mx0, fmaxf(sfr[nt][0], sfr[nt][1]));
            mx1 = fmaxf(mx1, fmaxf(sfr[nt][2], sfr[nt][3]));
        }
        mx0 = fmaxf(mx0, __shfl_xor_sync(0xffffffffu, mx0, 1));
        mx0 = fmaxf(mx0, __shfl_xor_sync(0xffffffffu, mx0, 2));
        mx1 = fmaxf(mx1, __shfl_xor_sync(0xffffffffu, mx1, 1));
        mx1 = fmaxf(mx1, __shfl_xor_sync(0xffffffffu, mx1, 2));

        float mn0 = fmaxf(m0r, mx0), mn1 = fmaxf(m1r, mx1);
        float sc0 = __expf(m0r - mn0), sc1 = __expf(m1r - mn1);
        m0r = mn0; m1r = mn1;

        float sum0 = 0.f, sum1 = 0.f;
#pragma unroll
        for (int nt = 0; nt < 8; nt++) {
            float p0 = __expf(sfr[nt][0] - mn0);
            float p1 = __expf(sfr[nt][1] - mn0);
            float p2 = __expf(sfr[nt][2] - mn1);
            float p3 = __expf(sfr[nt][3] - mn1);
            sum0 += p0 + p1; sum1 += p2 + p3;
            psw[g * PSTR + nt * 8 + tig * 2 + 0] = f2tf(p0);
            psw[g * PSTR + nt * 8 + tig * 2 + 1] = f2tf(p1);
            psw[(g + 8) * PSTR + nt * 8 + tig * 2 + 0] = f2tf(p2);
            psw[(g + 8) * PSTR + nt * 8 + tig * 2 + 1] = f2tf(p3);
        }
        sum0 += __shfl_xor_sync(0xffffffffu, sum0, 1);
        sum0 += __shfl_xor_sync(0xffffffffu, sum0, 2);
        sum1 += __shfl_xor_sync(0xffffffffu, sum1, 1);
        sum1 += __shfl_xor_sync(0xffffffffu, sum1, 2);
        l0 = l0 * sc0 + sum0;
        l1 = l1 * sc1 + sum1;

#pragma unroll
        for (int nt = 0; nt < 8; nt++) {
            o[nt][0] *= sc0; o[nt][1] *= sc0;
            o[nt][2] *= sc1; o[nt][3] *= sc1;
        }
        __syncwarp();

        // ---- O += P V (tf32 mma), O[16q x 64d] per warp ----
#pragma unroll
        for (int ks = 0; ks < 8; ks++) {
            int k8 = ks * 8;
            uint32_t a0 = __float_as_uint(psw[g * PSTR + k8 + tig]);
            uint32_t a1 = __float_as_uint(psw[(g + 8) * PSTR + k8 + tig]);
            uint32_t a2 = __float_as_uint(psw[g * PSTR + k8 + tig + 4]);
            uint32_t a3 = __float_as_uint(psw[(g + 8) * PSTR + k8 + tig + 4]);
            int sw = (k8 & 8) >> 1;   // V row swizzle: t&4 = 0 for rows tig, 4 for tig+4
#pragma unroll
            for (int nt = 0; nt < 8; nt++) {
                uint32_t b0 = __float_as_uint(vt[(k8 + tig) * VSTR + ((nt * 8 + g) ^ sw)]);
                uint32_t b1 = __float_as_uint(vt[(k8 + tig + 4) * VSTR + ((nt * 8 + g) ^ sw ^ 4)]);
                MMA_TF32(o[nt][0], o[nt][1], o[nt][2], o[nt][3],
                         a0, a1, a2, a3, b0, b1);
            }
        }
        __syncthreads();
    }

    // ---- normalize + stage O[q][d] in ps, then coalesced write ----
    {
        float inv0 = 1.f / l0, inv1 = 1.f / l1;
        __syncwarp();
#pragma unroll
        for (int nt = 0; nt < 8; nt++) {
            psw[g * PSTR + nt * 8 + tig * 2 + 0] = o[nt][0] * inv0;
            psw[g * PSTR + nt * 8 + tig * 2 + 1] = o[nt][1] * inv0;
            psw[(g + 8) * PSTR + nt * 8 + tig * 2 + 0] = o[nt][2] * inv1;
            psw[(g + 8) * PSTR + nt * 8 + tig * 2 + 1] = o[nt][3] * inv1;
        }
    }
    __syncthreads();

    float* outp = g_attn + ((size_t)b * 512 + n * 64) * 1024 + s0;
    {
        int s = tid & 127, hi = tid >> 7;
#pragma unroll
        for (int p = 0; p < 32; p++) {
            int d = p * 2 + hi;
            outp[(size_t)d * 1024 + s] = ps[s * PSTR + d];
        }
    }
}

// ============================================================
extern "C" void kernel_launch(void* const* d_in, const int* in_sizes, int n_in,
                              void* d_out, int out_size) {
    const float* x       = (const float*)d_in[0];
    const float* context = (const float*)d_in[1];
    const float* gamma   = (const float*)d_in[2];
    const float* beta    = (const float*)d_in[3];
    const float* qkv_w   = (const float*)d_in[4];
    const float* qkv_b   = (const float*)d_in[5];
    const float* ckv_w   = (const float*)d_in[6];
    const float* ckv_b   = (const float*)d_in[7];
    const float* proj_w  = (const float*)d_in[8];
    const float* proj_b  = (const float*)d_in[9];
    float* out = (float*)d_out;

    float *xn_p, *qkv_p, *attn_p;
    cudaGetSymbolAddress((void**)&xn_p, g_xn);
    cudaGetSymbolAddress((void**)&qkv_p, g_qkv);
    cudaGetSymbolAddress((void**)&attn_p, g_attn);

    // 1. GroupNorm
    gn_kernel<<<BATCH * 32, 256>>>(x, gamma, beta, xn_p);

    // 2. QKV projection (tf32 tensor cores)
    gemm_tf32<<<dim3(8, 12, BATCH), 256>>>(qkv_w, qkv_b, xn_p, nullptr, qkv_p, 1536, 1024, 512);

    // 3. Context KV projection
    ckv_kernel<<<dim3(16, BATCH), 256>>>(context, ckv_w, ckv_b);

    // 4. Flash attention v3 (tf32 tensor cores)
    int smem = (128 * QSTR + 64 * KSTR + 64 * VSTR + 128 * PSTR) * (int)sizeof(float); // 106496
    cudaFuncSetAttribute(flash3_kernel, cudaFuncAttributeMaxDynamicSharedMemorySize, smem);
    flash3_kernel<<<dim3(8, HEADS, BATCH), 256, smem>>>();

    // 5. Output projection + bias + residual (tf32 tensor cores)
    gemm_tf32<<<dim3(8, 4, BATCH), 256>>>(proj_w, proj_b, attn_p, x, out, 512, 1024, 512);
}

// round 7
// speedup vs baseline: 2.4314x; 1.0903x over previous
#include <cuda_runtime.h>
#include <cuda_bf16.h>
#include <math.h>
#include <stdint.h>

#define BATCH 8
#define DIMC 512
#define HW 1024
#define HEADS 8
#define HD 64
#define LCTX 77
#define CTXD 768
#define TKV 1101      // 77 ctx + 1024 image keys
#define NCHB 9        // ceil(1101/128)

// ---- scratch (device globals; no allocation allowed) ----
__device__ float g_xn[BATCH * DIMC * HW];
__device__ float g_qkv[BATCH * 3 * DIMC * HW];
__device__ float g_ckv[BATCH * 2 * DIMC * LCTX];
__device__ float g_attn[BATCH * DIMC * HW];

// round fp32 -> tf32 (round-to-nearest, keep 10 mantissa bits), pure ALU
__device__ __forceinline__ float f2tf(float x) {
    uint32_t u = __float_as_uint(x);
    u = (u + 0x1000u) & 0xFFFFE000u;
    return __uint_as_float(u);
}

__device__ __forceinline__ uint32_t pkbf2(float lo, float hi) {
    __nv_bfloat162 v = __floats2bfloat162_rn(lo, hi);
    return *reinterpret_cast<uint32_t*>(&v);
}

#define MMA_TF32(c0,c1,c2,c3,a0,a1,a2,a3,b0,b1)                               \
    asm volatile(                                                              \
        "mma.sync.aligned.m16n8k8.row.col.f32.tf32.tf32.f32 "                  \
        "{%0,%1,%2,%3}, {%4,%5,%6,%7}, {%8,%9}, {%0,%1,%2,%3};"                \
        : "+f"(c0), "+f"(c1), "+f"(c2), "+f"(c3)                               \
        : "r"(a0), "r"(a1), "r"(a2), "r"(a3), "r"(b0), "r"(b1))

#define MMA_BF16(c0,c1,c2,c3,a0,a1,a2,a3,b0,b1)                               \
    asm volatile(                                                              \
        "mma.sync.aligned.m16n8k16.row.col.f32.bf16.bf16.f32 "                 \
        "{%0,%1,%2,%3}, {%4,%5,%6,%7}, {%8,%9}, {%0,%1,%2,%3};"                \
        : "+f"(c0), "+f"(c1), "+f"(c2), "+f"(c3)                               \
        : "r"(a0), "r"(a1), "r"(a2), "r"(a3), "r"(b0), "r"(b1))

// ============================================================
// GroupNorm
// ============================================================
__global__ void gn_kernel(const float* __restrict__ x, const float* __restrict__ gamma,
                          const float* __restrict__ beta, float* __restrict__ xn) {
    __shared__ float ssum[256], ssq[256];
    int bg = blockIdx.x;
    int b = bg >> 5, g = bg & 31;
    const float* xp = x + ((size_t)b * DIMC + g * 16) * HW;
    float* xo = xn + ((size_t)b * DIMC + g * 16) * HW;
    int tid = threadIdx.x;

    float s = 0.f, sq = 0.f;
#pragma unroll
    for (int i = 0; i < 64; i++) {
        float v = xp[tid + i * 256];
        s += v; sq += v * v;
    }
    ssum[tid] = s; ssq[tid] = sq;
    __syncthreads();
    for (int off = 128; off > 0; off >>= 1) {
        if (tid < off) { ssum[tid] += ssum[tid + off]; ssq[tid] += ssq[tid + off]; }
        __syncthreads();
    }
    float mu = ssum[0] * (1.f / 16384.f);
    float var = ssq[0] * (1.f / 16384.f) - mu * mu;
    float inv = rsqrtf(var + 1e-5f);
#pragma unroll
    for (int i = 0; i < 64; i++) {
        int idx = tid + i * 256;
        int c = g * 16 + (idx >> 10);
        xo[idx] = (xp[idx] - mu) * inv * gamma[c] + beta[c];
    }
}

// ============================================================
// tf32 tensor-core GEMM (validated R5)
// ============================================================
__global__ void __launch_bounds__(256) gemm_tf32(
        const float* __restrict__ W, const float* __restrict__ bias,
        const float* __restrict__ X, const float* __restrict__ res,
        float* __restrict__ C, int M, int N, int K) {
    __shared__ float ws[32 * 132];
    __shared__ float xs[32 * 132];

    int b = blockIdx.z;
    int m0 = blockIdx.y * 128, n0 = blockIdx.x * 128;
    const float* Xb = X + (size_t)b * K * N;
    int tid = threadIdx.x;
    int warp = tid >> 5, lane = tid & 31;
    int warpM = warp >> 2, warpN = warp & 3;
    int g = lane >> 2, tig = lane & 3;

    float c[4][4][4];
#pragma unroll
    for (int mt = 0; mt < 4; mt++)
#pragma unroll
        for (int nt = 0; nt < 4; nt++)
#pragma unroll
            for (int r = 0; r < 4; r++) c[mt][nt][r] = 0.f;

    int wr = tid >> 3;
    int wc4 = (tid & 7) * 4;
    int xkr = tid >> 5;
    int xn4 = (tid & 31) * 4;

    for (int k0 = 0; k0 < K; k0 += 32) {
#pragma unroll
        for (int p = 0; p < 4; p++) {
            int m = p * 32 + wr;
            float4 wv = *(const float4*)(W + (size_t)(m0 + m) * K + k0 + wc4);
            ws[(wc4 + 0) * 132 + m] = f2tf(wv.x);
            ws[(wc4 + 1) * 132 + m] = f2tf(wv.y);
            ws[(wc4 + 2) * 132 + m] = f2tf(wv.z);
            ws[(wc4 + 3) * 132 + m] = f2tf(wv.w);
        }
#pragma unroll
        for (int p = 0; p < 4; p++) {
            int k = p * 8 + xkr;
            float4 xv = *(const float4*)(Xb + (size_t)(k0 + k) * N + n0 + xn4);
            float4 t;
            t.x = f2tf(xv.x); t.y = f2tf(xv.y); t.z = f2tf(xv.z); t.w = f2tf(xv.w);
            *(float4*)&xs[k * 132 + xn4] = t;
        }
        __syncthreads();

#pragma unroll
        for (int ks = 0; ks < 4; ks++) {
            int k8 = ks * 8;
            uint32_t a[4][4], bb[4][2];
#pragma unroll
            for (int mt = 0; mt < 4; mt++) {
                int mo = warpM * 64 + mt * 16;
                a[mt][0] = __float_as_uint(ws[(k8 + tig) * 132 + mo + g]);
                a[mt][1] = __float_as_uint(ws[(k8 + tig) * 132 + mo + g + 8]);
                a[mt][2] = __float_as_uint(ws[(k8 + tig + 4) * 132 + mo + g]);
                a[mt][3] = __float_as_uint(ws[(k8 + tig + 4) * 132 + mo + g + 8]);
            }
#pragma unroll
            for (int nt = 0; nt < 4; nt++) {
                int no = warpN * 32 + nt * 8;
                bb[nt][0] = __float_as_uint(xs[(k8 + tig) * 132 + no + g]);
                bb[nt][1] = __float_as_uint(xs[(k8 + tig + 4) * 132 + no + g]);
            }
#pragma unroll
            for (int mt = 0; mt < 4; mt++)
#pragma unroll
                for (int nt = 0; nt < 4; nt++)
                    MMA_TF32(c[mt][nt][0], c[mt][nt][1], c[mt][nt][2], c[mt][nt][3],
                             a[mt][0], a[mt][1], a[mt][2], a[mt][3],
                             bb[nt][0], bb[nt][1]);
        }
        __syncthreads();
    }

#pragma unroll
    for (int mt = 0; mt < 4; mt++) {
#pragma unroll
        for (int half = 0; half < 2; half++) {
            int m = m0 + warpM * 64 + mt * 16 + g + half * 8;
            float bv = bias[m];
            size_t rowoff = ((size_t)b * M + m) * N;
#pragma unroll
            for (int nt = 0; nt < 4; nt++) {
                int n = n0 + warpN * 32 + nt * 8 + tig * 2;
                float v0 = c[mt][nt][half * 2 + 0] + bv;
                float v1 = c[mt][nt][half * 2 + 1] + bv;
                if (res) {
                    v0 += res[rowoff + n];
                    v1 += res[rowoff + n + 1];
                }
                C[rowoff + n] = v0;
                C[rowoff + n + 1] = v1;
            }
        }
    }
}

// ============================================================
// ckv GEMM (fp32, small)
// ============================================================
__global__ void ckv_kernel(const float* __restrict__ ctx, const float* __restrict__ W,
                           const float* __restrict__ bias) {
    __shared__ float ws2[32 * 65];
    __shared__ float cs[32 * 81];
    int ot = blockIdx.x, b = blockIdx.y;
    int tid = threadIdx.x;
    int tx = tid & 15, tg = tid >> 4;
    int cc = tid & 31, rr = tid >> 5;
    int ob = tg * 4, lb = tx * 5;

    float acc[4][5];
#pragma unroll
    for (int i = 0; i < 4; i++)
#pragma unroll
        for (int j = 0; j < 5; j++) acc[i][j] = 0.f;

    for (int c0 = 0; c0 < CTXD; c0 += 32) {
#pragma unroll
        for (int p = 0; p < 8; p++) {
            int o = p * 8 + rr;
            ws2[cc * 65 + o] = W[(size_t)(ot * 64 + o) * CTXD + c0 + cc];
        }
#pragma unroll
        for (int p = 0; p < 10; p++) {
            int l = p * 8 + rr;
            float v = (l < LCTX) ? ctx[((size_t)b * LCTX + l) * CTXD + c0 + cc] : 0.f;
            cs[cc * 81 + l] = v;
        }
        __syncthreads();
#pragma unroll
        for (int kk = 0; kk < 32; kk++) {
            float wv[4], cv[5];
#pragma unroll
            for (int i = 0; i < 4; i++) wv[i] = ws2[kk * 65 + ob + i];
#pragma unroll
            for (int j = 0; j < 5; j++) cv[j] = cs[kk * 81 + lb + j];
#pragma unroll
            for (int i = 0; i < 4; i++)
#pragma unroll
                for (int j = 0; j < 5; j++) acc[i][j] += wv[i] * cv[j];
        }
        __syncthreads();
    }

#pragma unroll
    for (int i = 0; i < 4; i++) {
        int o = ot * 64 + ob + i;
        float bv = bias[o];
#pragma unroll
        for (int j = 0; j < 5; j++) {
            int l = lb + j;
            if (l < LCTX)
                g_ckv[((size_t)b * 1024 + o) * LCTX + l] = acc[i][j] + bv;
        }
    }
}

// ============================================================
// Flash attention v4: bf16 mma.m16n8k16.
// 256 thr / 8 warps, 128 q per block (16 q per warp),
// 128-key chunks processed as two 64-key halves (2 block barriers per chunk).
// smem (uint32 words, all bf16x2 packed along mma k-dim):
//   qs[128 q][36]   Q pairs along d
//   kt[128 t][36]   K pairs along d, word-XOR swizzle by (t>>3)&3
//   vt[ 64 d][68]   V pairs along t
//   ps[128 q][36]   P pairs along t (warp-private staging)
// ============================================================
#define QW 36
#define KW 36
#define VW 68
#define PW 36
#define FL4_SMEM ((128*QW + 128*KW + 64*VW + 128*PW) * 4)   // 72704 B

__global__ void __launch_bounds__(256, 2) flash4_kernel() {
    extern __shared__ uint32_t sm4[];
    uint32_t* qs = sm4;                   // 128*36
    uint32_t* kt = qs + 128 * QW;         // 128*36
    uint32_t* vt = kt + 128 * KW;         // 64*68
    uint32_t* ps = vt + 64 * VW;          // 128*36
    __nv_bfloat16* qsb = (__nv_bfloat16*)qs;
    __nv_bfloat16* ktb = (__nv_bfloat16*)kt;
    __nv_bfloat16* vtb = (__nv_bfloat16*)vt;

    int s0 = blockIdx.x * 128;
    int n = blockIdx.y, b = blockIdx.z;
    int tid = threadIdx.x;
    int warp = tid >> 5, lane = tid & 31;
    int g = lane >> 2, tig = lane & 3;
    int q0w = warp * 16;
    uint32_t* psw = ps + q0w * PW;

    const float* qbase = g_qkv + ((size_t)b * 1536 + n * 64) * 1024 + s0;
    const float* kck = g_ckv + ((size_t)b * 1024 + n * 64) * LCTX;
    const float* vck = g_ckv + ((size_t)b * 1024 + 512 + n * 64) * LCTX;
    const float* kim = g_qkv + ((size_t)b * 1536 + 512 + n * 64) * 1024;
    const float* vim = g_qkv + ((size_t)b * 1536 + 1024 + n * 64) * 1024;

    // ---- load Q[q][d] as bf16 (transpose from [d][s]) ----
    {
        int s = tid & 127, hi = tid >> 7;
#pragma unroll
        for (int p = 0; p < 32; p++) {
            int d = p * 2 + hi;
            qsb[s * (QW * 2) + d] = __float2bfloat16_rn(qbase[(size_t)d * 1024 + s]);
        }
    }

    float m0r = -1e30f, m1r = -1e30f, l0 = 0.f, l1 = 0.f;
    float o[8][4];
#pragma unroll
    for (int nt = 0; nt < 8; nt++)
#pragma unroll
        for (int r = 0; r < 4; r++) o[nt][r] = 0.f;

    int t2 = tid & 127, dh = tid >> 7;

    for (int c = 0; c < NCHB; c++) {
        int t0 = c * 128;
        // ---- load K (swizzled [t][d-pairs]) and V ([d][t-pairs]) ----
#pragma unroll
        for (int p = 0; p < 32; p++) {
            int d = p * 2 + dh;
            int gt = t0 + t2;
            float kv = 0.f, vv = 0.f;
            if (gt < LCTX) {
                kv = kck[d * LCTX + gt];
                vv = vck[d * LCTX + gt];
            } else if (gt < TKV) {
                kv = kim[(size_t)d * 1024 + (gt - LCTX)];
                vv = vim[(size_t)d * 1024 + (gt - LCTX)];
            }
            int wsw = (d >> 1) ^ ((t2 >> 3) & 3);
            ktb[t2 * (KW * 2) + wsw * 2 + (d & 1)] = __float2bfloat16_rn(kv);
            vtb[d * (VW * 2) + t2] = __float2bfloat16_rn(vv);
        }
        __syncthreads();

#pragma unroll
        for (int h = 0; h < 2; h++) {
            // ---- S = Q K^T (bf16 mma), S[16q x 64t] per warp ----
            float sfr[8][4];
#pragma unroll
            for (int nt = 0; nt < 8; nt++)
#pragma unroll
                for (int r = 0; r < 4; r++) sfr[nt][r] = 0.f;

#pragma unroll
            for (int ks = 0; ks < 4; ks++) {
                int w0 = ks * 8 + tig;
                uint32_t a0 = qs[(q0w + g) * QW + w0];
                uint32_t a1 = qs[(q0w + g + 8) * QW + w0];
                uint32_t a2 = qs[(q0w + g) * QW + w0 + 4];
                uint32_t a3 = qs[(q0w + g + 8) * QW + w0 + 4];
#pragma unroll
                for (int nt = 0; nt < 8; nt++) {
                    int t = h * 64 + nt * 8 + g;
                    int bw = w0 ^ (nt & 3);
                    uint32_t b0 = kt[t * KW + bw];
                    uint32_t b1 = kt[t * KW + bw + 4];
                    MMA_BF16(sfr[nt][0], sfr[nt][1], sfr[nt][2], sfr[nt][3],
                             a0, a1, a2, a3, b0, b1);
                }
            }

            // scale + mask
#pragma unroll
            for (int nt = 0; nt < 8; nt++)
#pragma unroll
                for (int r = 0; r < 4; r++) sfr[nt][r] *= 0.125f;
            if (t0 + h * 64 + 64 > TKV) {
#pragma unroll
                for (int nt = 0; nt < 8; nt++) {
                    int t = t0 + h * 64 + nt * 8 + tig * 2;
                    if (t >= TKV) { sfr[nt][0] = -1e30f; sfr[nt][2] = -1e30f; }
                    if (t + 1 >= TKV) { sfr[nt][1] = -1e30f; sfr[nt][3] = -1e30f; }
                }
            }

            // ---- online softmax (rows g and g+8; cols live in 4 tig lanes) ----
            float mx0 = -1e30f, mx1 = -1e30f;
#pragma unroll
            for (int nt = 0; nt < 8; nt++) {
                mx0 = fmaxf(mx0, fmaxf(sfr[nt][0], sfr[nt][1]));
                mx1 = fmaxf(mx1, fmaxf(sfr[nt][2], sfr[nt][3]));
            }
            mx0 = fmaxf(mx0, __shfl_xor_sync(0xffffffffu, mx0, 1));
            mx0 = fmaxf(mx0, __shfl_xor_sync(0xffffffffu, mx0, 2));
            mx1 = fmaxf(mx1, __shfl_xor_sync(0xffffffffu, mx1, 1));
            mx1 = fmaxf(mx1, __shfl_xor_sync(0xffffffffu, mx1, 2));

            float mn0 = fmaxf(m0r, mx0), mn1 = fmaxf(m1r, mx1);
            float sc0 = __expf(m0r - mn0), sc1 = __expf(m1r - mn1);
            m0r = mn0; m1r = mn1;

            float sum0 = 0.f, sum1 = 0.f;
#pragma unroll
            for (int nt = 0; nt < 8; nt++) {
                float p0 = __expf(sfr[nt][0] - mn0);
                float p1 = __expf(sfr[nt][1] - mn0);
                float p2 = __expf(sfr[nt][2] - mn1);
                float p3 = __expf(sfr[nt][3] - mn1);
                sum0 += p0 + p1; sum1 += p2 + p3;
                psw[(g) * PW + nt * 4 + tig] = pkbf2(p0, p1);
                psw[(g + 8) * PW + nt * 4 + tig] = pkbf2(p2, p3);
            }
            sum0 += __shfl_xor_sync(0xffffffffu, sum0, 1);
            sum0 += __shfl_xor_sync(0xffffffffu, sum0, 2);
            sum1 += __shfl_xor_sync(0xffffffffu, sum1, 1);
            sum1 += __shfl_xor_sync(0xffffffffu, sum1, 2);
            l0 = l0 * sc0 + sum0;
            l1 = l1 * sc1 + sum1;

#pragma unroll
            for (int nt = 0; nt < 8; nt++) {
                o[nt][0] *= sc0; o[nt][1] *= sc0;
                o[nt][2] *= sc1; o[nt][3] *= sc1;
            }
            __syncwarp();

            // ---- O += P V (bf16 mma), O[16q x 64d] per warp ----
#pragma unroll
            for (int ks = 0; ks < 4; ks++) {
                int w0 = ks * 8 + tig;
                uint32_t a0 = psw[(g) * PW + w0];
                uint32_t a1 = psw[(g + 8) * PW + w0];
                uint32_t a2 = psw[(g) * PW + w0 + 4];
                uint32_t a3 = psw[(g + 8) * PW + w0 + 4];
#pragma unroll
                for (int nt = 0; nt < 8; nt++) {
                    int d = nt * 8 + g;
                    uint32_t b0 = vt[d * VW + h * 32 + w0];
                    uint32_t b1 = vt[d * VW + h * 32 + w0 + 4];
                    MMA_BF16(o[nt][0], o[nt][1], o[nt][2], o[nt][3],
                             a0, a1, a2, a3, b0, b1);
                }
            }
            __syncwarp();
        }
        __syncthreads();
    }

    // ---- normalize + direct global store: O[q][d] -> g_attn[d][s] ----
    {
        float inv0 = 1.f / l0, inv1 = 1.f / l1;
        float* outp = g_attn + ((size_t)b * 512 + n * 64) * 1024 + s0;
        int sA = q0w + g, sB = q0w + g + 8;
#pragma unroll
        for (int nt = 0; nt < 8; nt++) {
            int d = nt * 8 + tig * 2;
            outp[(size_t)d * 1024 + sA] = o[nt][0] * inv0;
            outp[(size_t)(d + 1) * 1024 + sA] = o[nt][1] * inv0;
            outp[(size_t)d * 1024 + sB] = o[nt][2] * inv1;
            outp[(size_t)(d + 1) * 1024 + sB] = o[nt][3] * inv1;
        }
    }
}

// ============================================================
extern "C" void kernel_launch(void* const* d_in, const int* in_sizes, int n_in,
                              void* d_out, int out_size) {
    const float* x       = (const float*)d_in[0];
    const float* context = (const float*)d_in[1];
    const float* gamma   = (const float*)d_in[2];
    const float* beta    = (const float*)d_in[3];
    const float* qkv_w   = (const float*)d_in[4];
    const float* qkv_b   = (const float*)d_in[5];
    const float* ckv_w   = (const float*)d_in[6];
    const float* ckv_b   = (const float*)d_in[7];
    const float* proj_w  = (const float*)d_in[8];
    const float* proj_b  = (const float*)d_in[9];
    float* out = (float*)d_out;

    float *xn_p, *qkv_p, *attn_p;
    cudaGetSymbolAddress((void**)&xn_p, g_xn);
    cudaGetSymbolAddress((void**)&qkv_p, g_qkv);
    cudaGetSymbolAddress((void**)&attn_p, g_attn);

    // 1. GroupNorm
    gn_kernel<<<BATCH * 32, 256>>>(x, gamma, beta, xn_p);

    // 2. QKV projection (tf32 tensor cores)
    gemm_tf32<<<dim3(8, 12, BATCH), 256>>>(qkv_w, qkv_b, xn_p, nullptr, qkv_p, 1536, 1024, 512);

    // 3. Context KV projection
    ckv_kernel<<<dim3(16, BATCH), 256>>>(context, ckv_w, ckv_b);

    // 4. Flash attention v4 (bf16 tensor cores, 128-key chunks)
    cudaFuncSetAttribute(flash4_kernel, cudaFuncAttributeMaxDynamicSharedMemorySize, FL4_SMEM);
    flash4_kernel<<<dim3(8, HEADS, BATCH), 256, FL4_SMEM>>>();

    // 5. Output projection + bias + residual (tf32 tensor cores)
    gemm_tf32<<<dim3(8, 4, BATCH), 256>>>(proj_w, proj_b, attn_p, x, out, 512, 1024, 512);
}

// round 9
// speedup vs baseline: 2.7573x; 1.1340x over previous
#include <cuda_runtime.h>
#include <cuda_bf16.h>
#include <math.h>
#include <stdint.h>

#define BATCH 8
#define DIMC 512
#define HW 1024
#define HEADS 8
#define HD 64
#define LCTX 77
#define CTXD 768
#define TKV 1101
#define TPAD 1152     // padded KV length (9 chunks of 128)
#define NCHB 9

// ---- scratch (device globals) ----
__device__ float g_xn[BATCH * DIMC * HW];
__device__ float g_qkv[BATCH * 3 * DIMC * HW];
__device__ float g_ckv[BATCH * 2 * DIMC * LCTX];
__device__ float g_attn[BATCH * DIMC * HW];
// packed bf16 KV: K [bn][t][32 words, swizzled, scale-folded], V [bn][d][576 words]
__device__ uint32_t g_kb[BATCH * HEADS * TPAD * 32];
__device__ uint32_t g_vb[BATCH * HEADS * 64 * (TPAD / 2)];

__device__ __forceinline__ float f2tf(float x) {
    uint32_t u = __float_as_uint(x);
    u = (u + 0x1000u) & 0xFFFFE000u;
    return __uint_as_float(u);
}
__device__ __forceinline__ uint32_t pkbf2(float lo, float hi) {
    __nv_bfloat162 v = __floats2bfloat162_rn(lo, hi);
    return *reinterpret_cast<uint32_t*>(&v);
}
__device__ __forceinline__ void cpasync16(uint32_t s, const void* g) {
    asm volatile("cp.async.cg.shared.global [%0], [%1], 16;" :: "r"(s), "l"(g));
}

#define MMA_TF32(c0,c1,c2,c3,a0,a1,a2,a3,b0,b1)                               \
    asm volatile(                                                              \
        "mma.sync.aligned.m16n8k8.row.col.f32.tf32.tf32.f32 "                  \
        "{%0,%1,%2,%3}, {%4,%5,%6,%7}, {%8,%9}, {%0,%1,%2,%3};"                \
        : "+f"(c0), "+f"(c1), "+f"(c2), "+f"(c3)                               \
        : "r"(a0), "r"(a1), "r"(a2), "r"(a3), "r"(b0), "r"(b1))

#define MMA_BF16(c0,c1,c2,c3,a0,a1,a2,a3,b0,b1)                               \
    asm volatile(                                                              \
        "mma.sync.aligned.m16n8k16.row.col.f32.bf16.bf16.f32 "                 \
        "{%0,%1,%2,%3}, {%4,%5,%6,%7}, {%8,%9}, {%0,%1,%2,%3};"                \
        : "+f"(c0), "+f"(c1), "+f"(c2), "+f"(c3)                               \
        : "r"(a0), "r"(a1), "r"(a2), "r"(a3), "r"(b0), "r"(b1))

// ============================================================
// GroupNorm
// ============================================================
__global__ void gn_kernel(const float* __restrict__ x, const float* __restrict__ gamma,
                          const float* __restrict__ beta, float* __restrict__ xn) {
    __shared__ float ssum[256], ssq[256];
    int bg = blockIdx.x;
    int b = bg >> 5, g = bg & 31;
    const float* xp = x + ((size_t)b * DIMC + g * 16) * HW;
    float* xo = xn + ((size_t)b * DIMC + g * 16) * HW;
    int tid = threadIdx.x;

    float s = 0.f, sq = 0.f;
#pragma unroll
    for (int i = 0; i < 64; i++) {
        float v = xp[tid + i * 256];
        s += v; sq += v * v;
    }
    ssum[tid] = s; ssq[tid] = sq;
    __syncthreads();
    for (int off = 128; off > 0; off >>= 1) {
        if (tid < off) { ssum[tid] += ssum[tid + off]; ssq[tid] += ssq[tid + off]; }
        __syncthreads();
    }
    float mu = ssum[0] * (1.f / 16384.f);
    float var = ssq[0] * (1.f / 16384.f) - mu * mu;
    float inv = rsqrtf(var + 1e-5f);
#pragma unroll
    for (int i = 0; i < 64; i++) {
        int idx = tid + i * 256;
        int c = g * 16 + (idx >> 10);
        xo[idx] = (xp[idx] - mu) * inv * gamma[c] + beta[c];
    }
}

// ============================================================
// tf32 tensor-core GEMM (validated)
// ============================================================
__global__ void __launch_bounds__(256) gemm_tf32(
        const float* __restrict__ W, const float* __restrict__ bias,
        const float* __restrict__ X, const float* __restrict__ res,
        float* __restrict__ C, int M, int N, int K) {
    __shared__ float ws[32 * 132];
    __shared__ float xs[32 * 132];

    int b = blockIdx.z;
    int m0 = blockIdx.y * 128, n0 = blockIdx.x * 128;
    const float* Xb = X + (size_t)b * K * N;
    int tid = threadIdx.x;
    int warp = tid >> 5, lane = tid & 31;
    int warpM = warp >> 2, warpN = warp & 3;
    int g = lane >> 2, tig = lane & 3;

    float c[4][4][4];
#pragma unroll
    for (int mt = 0; mt < 4; mt++)
#pragma unroll
        for (int nt = 0; nt < 4; nt++)
#pragma unroll
            for (int r = 0; r < 4; r++) c[mt][nt][r] = 0.f;

    int wr = tid >> 3;
    int wc4 = (tid & 7) * 4;
    int xkr = tid >> 5;
    int xn4 = (tid & 31) * 4;

    for (int k0 = 0; k0 < K; k0 += 32) {
#pragma unroll
        for (int p = 0; p < 4; p++) {
            int m = p * 32 + wr;
            float4 wv = *(const float4*)(W + (size_t)(m0 + m) * K + k0 + wc4);
            ws[(wc4 + 0) * 132 + m] = f2tf(wv.x);
            ws[(wc4 + 1) * 132 + m] = f2tf(wv.y);
            ws[(wc4 + 2) * 132 + m] = f2tf(wv.z);
            ws[(wc4 + 3) * 132 + m] = f2tf(wv.w);
        }
#pragma unroll
        for (int p = 0; p < 4; p++) {
            int k = p * 8 + xkr;
            float4 xv = *(const float4*)(Xb + (size_t)(k0 + k) * N + n0 + xn4);
            float4 t;
            t.x = f2tf(xv.x); t.y = f2tf(xv.y); t.z = f2tf(xv.z); t.w = f2tf(xv.w);
            *(float4*)&xs[k * 132 + xn4] = t;
        }
        __syncthreads();

#pragma unroll
        for (int ks = 0; ks < 4; ks++) {
            int k8 = ks * 8;
            uint32_t a[4][4], bb[4][2];
#pragma unroll
            for (int mt = 0; mt < 4; mt++) {
                int mo = warpM * 64 + mt * 16;
                a[mt][0] = __float_as_uint(ws[(k8 + tig) * 132 + mo + g]);
                a[mt][1] = __float_as_uint(ws[(k8 + tig) * 132 + mo + g + 8]);
                a[mt][2] = __float_as_uint(ws[(k8 + tig + 4) * 132 + mo + g]);
                a[mt][3] = __float_as_uint(ws[(k8 + tig + 4) * 132 + mo + g + 8]);
            }
#pragma unroll
            for (int nt = 0; nt < 4; nt++) {
                int no = warpN * 32 + nt * 8;
                bb[nt][0] = __float_as_uint(xs[(k8 + tig) * 132 + no + g]);
                bb[nt][1] = __float_as_uint(xs[(k8 + tig + 4) * 132 + no + g]);
            }
#pragma unroll
            for (int mt = 0; mt < 4; mt++)
#pragma unroll
                for (int nt = 0; nt < 4; nt++)
                    MMA_TF32(c[mt][nt][0], c[mt][nt][1], c[mt][nt][2], c[mt][nt][3],
                             a[mt][0], a[mt][1], a[mt][2], a[mt][3],
                             bb[nt][0], bb[nt][1]);
        }
        __syncthreads();
    }

#pragma unroll
    for (int mt = 0; mt < 4; mt++) {
#pragma unroll
        for (int half = 0; half < 2; half++) {
            int m = m0 + warpM * 64 + mt * 16 + g + half * 8;
            float bv = bias[m];
            size_t rowoff = ((size_t)b * M + m) * N;
#pragma unroll
            for (int nt = 0; nt < 4; nt++) {
                int n = n0 + warpN * 32 + nt * 8 + tig * 2;
                float v0 = c[mt][nt][half * 2 + 0] + bv;
                float v1 = c[mt][nt][half * 2 + 1] + bv;
                if (res) {
                    v0 += res[rowoff + n];
                    v1 += res[rowoff + n + 1];
                }
                C[rowoff + n] = v0;
                C[rowoff + n + 1] = v1;
            }
        }
    }
}

// ============================================================
// ckv GEMM (fp32, small)
// ============================================================
__global__ void ckv_kernel(const float* __restrict__ ctx, const float* __restrict__ W,
                           const float* __restrict__ bias) {
    __shared__ float ws2[32 * 65];
    __shared__ float cs[32 * 81];
    int ot = blockIdx.x, b = blockIdx.y;
    int tid = threadIdx.x;
    int tx = tid & 15, tg = tid >> 4;
    int cc = tid & 31, rr = tid >> 5;
    int ob = tg * 4, lb = tx * 5;

    float acc[4][5];
#pragma unroll
    for (int i = 0; i < 4; i++)
#pragma unroll
        for (int j = 0; j < 5; j++) acc[i][j] = 0.f;

    for (int c0 = 0; c0 < CTXD; c0 += 32) {
#pragma unroll
        for (int p = 0; p < 8; p++) {
            int o = p * 8 + rr;
            ws2[cc * 65 + o] = W[(size_t)(ot * 64 + o) * CTXD + c0 + cc];
        }
#pragma unroll
        for (int p = 0; p < 10; p++) {
            int l = p * 8 + rr;
            float v = (l < LCTX) ? ctx[((size_t)b * LCTX + l) * CTXD + c0 + cc] : 0.f;
            cs[cc * 81 + l] = v;
        }
        __syncthreads();
#pragma unroll
        for (int kk = 0; kk < 32; kk++) {
            float wv[4], cv[5];
#pragma unroll
            for (int i = 0; i < 4; i++) wv[i] = ws2[kk * 65 + ob + i];
#pragma unroll
            for (int j = 0; j < 5; j++) cv[j] = cs[kk * 81 + lb + j];
#pragma unroll
            for (int i = 0; i < 4; i++)
#pragma unroll
                for (int j = 0; j < 5; j++) acc[i][j] += wv[i] * cv[j];
        }
        __syncthreads();
    }

#pragma unroll
    for (int i = 0; i < 4; i++) {
        int o = ot * 64 + ob + i;
        float bv = bias[o];
#pragma unroll
        for (int j = 0; j < 5; j++) {
            int l = lb + j;
            if (l < LCTX)
                g_ckv[((size_t)b * 1024 + o) * LCTX + l] = acc[i][j] + bv;
        }
    }
}

// ============================================================
// packk: build g_kb[bn][t][32w] bf16, swizzled, logit scale folded.
// SCALE^2 = HD^-0.5 = 0.125 (exact power of 2 -> exact in bf16).
// grid (18, HEADS, BATCH), 256 thr. 64-t tile via smem transpose.
// ============================================================
__global__ void packk_kernel() {
    __shared__ unsigned short ks[64][66];
    int tt = blockIdx.x, n = blockIdx.y, b = blockIdx.z;
    int tid = threadIdx.x;
    const float* kck = g_ckv + ((size_t)b * 1024 + n * 64) * LCTX;
    const float* kim = g_qkv + ((size_t)b * 1536 + 512 + n * 64) * 1024;
    int tl = tid & 63, dh = tid >> 6;
    int t0 = tt * 64;
#pragma unroll
    for (int p = 0; p < 16; p++) {
        int d = p * 4 + dh;
        int gt = t0 + tl;
        float kv = 0.f;
        if (gt < LCTX) kv = kck[d * LCTX + gt];
        else if (gt < TKV) kv = kim[(size_t)d * 1024 + (gt - LCTX)];
        __nv_bfloat16 h = __float2bfloat16_rn(kv * 0.125f);   // FIXED: 1/8, not 1/64
        ks[d][tl] = *reinterpret_cast<unsigned short*>(&h);
    }
    __syncthreads();

    int row = tid >> 2, q = tid & 3;
    int t = t0 + row;
    int s = (t >> 3) & 3;
    uint32_t* outw = g_kb + ((size_t)(b * HEADS + n) * TPAD + t) * 32;
#pragma unroll
    for (int half = 0; half < 2; half++) {
        int w0 = q * 4 + half * 16;
        uint32_t wv[4];
#pragma unroll
        for (int j = 0; j < 4; j++) {
            int p = (w0 + j) ^ s;
            wv[j] = (uint32_t)ks[2 * p][row] | ((uint32_t)ks[2 * p + 1][row] << 16);
        }
        uint4 v = {wv[0], wv[1], wv[2], wv[3]};
        *(uint4*)(outw + w0) = v;
    }
}

// ============================================================
// packv: build g_vb[bn][d][576w] bf16 ([d][t] pairs).
// ============================================================
__global__ void packv_kernel() {
    int n = blockIdx.x, b = blockIdx.y;
    int tid = threadIdx.x;
    const float* vck = g_ckv + ((size_t)b * 1024 + 512 + n * 64) * LCTX;
    const float* vim = g_qkv + ((size_t)b * 1536 + 1024 + n * 64) * 1024;
    uint32_t* outw = g_vb + (size_t)(b * HEADS + n) * 64 * (TPAD / 2);
    for (int d = 0; d < 64; d++) {
        for (int tp = tid; tp < TPAD / 2; tp += 256) {
            int t = tp * 2;
            float v0 = 0.f, v1 = 0.f;
            if (t < LCTX) v0 = vck[d * LCTX + t];
            else if (t < TKV) v0 = vim[(size_t)d * 1024 + (t - LCTX)];
            if (t + 1 < LCTX) v1 = vck[d * LCTX + t + 1];
            else if (t + 1 < TKV) v1 = vim[(size_t)d * 1024 + (t + 1 - LCTX)];
            outw[(size_t)d * (TPAD / 2) + tp] = pkbf2(v0, v1);
        }
    }
}

// ============================================================
// Flash attention v5: bf16 mma + packed KV + double-buffered cp.async.
// ============================================================
#define QW 36
#define KW 36
#define VW 68
#define PW 36
#define FL5_WORDS (128*QW + 2*(128*KW + 64*VW) + 128*PW)
#define FL5_SMEM (FL5_WORDS * 4)   // 108544 B

__global__ void __launch_bounds__(256, 2) flash5_kernel() {
    extern __shared__ uint32_t sm5[];
    uint32_t* qs = sm5;
    uint32_t* ktb[2] = { qs + 128 * QW, qs + 128 * QW + 128 * KW };
    uint32_t* vtb[2] = { ktb[1] + 128 * KW, ktb[1] + 128 * KW + 64 * VW };
    uint32_t* ps = vtb[1] + 64 * VW;
    __nv_bfloat16* qsb = (__nv_bfloat16*)qs;

    int s0 = blockIdx.x * 128;
    int n = blockIdx.y, b = blockIdx.z;
    int bn = b * HEADS + n;
    int tid = threadIdx.x;
    int warp = tid >> 5, lane = tid & 31;
    int g = lane >> 2, tig = lane & 3;
    int q0w = warp * 16;
    uint32_t* psw = ps + q0w * PW;

    uint32_t kts[2], vts[2];
    kts[0] = (uint32_t)__cvta_generic_to_shared(ktb[0]);
    kts[1] = (uint32_t)__cvta_generic_to_shared(ktb[1]);
    vts[0] = (uint32_t)__cvta_generic_to_shared(vtb[0]);
    vts[1] = (uint32_t)__cvta_generic_to_shared(vtb[1]);

    const uint32_t* gk = g_kb + (size_t)bn * TPAD * 32;
    const uint32_t* gv = g_vb + (size_t)bn * 64 * (TPAD / 2);

    int ktrow = tid >> 1, ktq = tid & 1;
    int vdrow = tid >> 2, vwq = tid & 3;

    const float* qbase = g_qkv + ((size_t)b * 1536 + n * 64) * 1024 + s0;
    {
        int s = tid & 127, hi = tid >> 7;
#pragma unroll
        for (int p = 0; p < 32; p++) {
            int d = p * 2 + hi;
            qsb[s * (QW * 2) + d] = __float2bfloat16_rn(qbase[(size_t)d * 1024 + s]);
        }
    }

#define ISSUE_CHUNK(c)                                                         \
    do {                                                                       \
        int _bb = (c) & 1;                                                     \
        const uint32_t* _gkc = gk + ((size_t)(c) * 128 + ktrow) * 32 + ktq * 16; \
        uint32_t _kd = kts[_bb] + (ktrow * KW + ktq * 16) * 4;                 \
        cpasync16(_kd + 0,  _gkc + 0);                                         \
        cpasync16(_kd + 16, _gkc + 4);                                         \
        cpasync16(_kd + 32, _gkc + 8);                                         \
        cpasync16(_kd + 48, _gkc + 12);                                        \
        const uint32_t* _gvc = gv + (size_t)vdrow * (TPAD / 2) + (c) * 64 + vwq * 16; \
        uint32_t _vd = vts[_bb] + (vdrow * VW + vwq * 16) * 4;                 \
        cpasync16(_vd + 0,  _gvc + 0);                                         \
        cpasync16(_vd + 16, _gvc + 4);                                         \
        cpasync16(_vd + 32, _gvc + 8);                                         \
        cpasync16(_vd + 48, _gvc + 12);                                        \
        asm volatile("cp.async.commit_group;");                                \
    } while (0)

    ISSUE_CHUNK(0);

    float m0r = -1e30f, m1r = -1e30f, l0 = 0.f, l1 = 0.f;
    float o[8][4];
#pragma unroll
    for (int nt = 0; nt < 8; nt++)
#pragma unroll
        for (int r = 0; r < 4; r++) o[nt][r] = 0.f;

    for (int c = 0; c < NCHB; c++) {
        if (c + 1 < NCHB) {
            ISSUE_CHUNK(c + 1);
            asm volatile("cp.async.wait_group 1;");
        } else {
            asm volatile("cp.async.wait_group 0;");
        }
        __syncthreads();

        uint32_t* kt = ktb[c & 1];
        uint32_t* vt = vtb[c & 1];
        int t0 = c * 128;

#pragma unroll
        for (int h = 0; h < 2; h++) {
            float sfr[8][4];
#pragma unroll
            for (int nt = 0; nt < 8; nt++)
#pragma unroll
                for (int r = 0; r < 4; r++) sfr[nt][r] = 0.f;

#pragma unroll
            for (int ks = 0; ks < 4; ks++) {
                int w0 = ks * 8 + tig;
                uint32_t a0 = qs[(q0w + g) * QW + w0];
                uint32_t a1 = qs[(q0w + g + 8) * QW + w0];
                uint32_t a2 = qs[(q0w + g) * QW + w0 + 4];
                uint32_t a3 = qs[(q0w + g + 8) * QW + w0 + 4];
#pragma unroll
                for (int nt = 0; nt < 8; nt++) {
                    int t = h * 64 + nt * 8 + g;
                    int bw = w0 ^ (nt & 3);
                    uint32_t b0 = kt[t * KW + bw];
                    uint32_t b1 = kt[t * KW + bw + 4];
                    MMA_BF16(sfr[nt][0], sfr[nt][1], sfr[nt][2], sfr[nt][3],
                             a0, a1, a2, a3, b0, b1);
                }
            }

            if (t0 + h * 64 + 64 > TKV) {
#pragma unroll
                for (int nt = 0; nt < 8; nt++) {
                    int t = t0 + h * 64 + nt * 8 + tig * 2;
                    if (t >= TKV) { sfr[nt][0] = -1e30f; sfr[nt][2] = -1e30f; }
                    if (t + 1 >= TKV) { sfr[nt][1] = -1e30f; sfr[nt][3] = -1e30f; }
                }
            }

            float mx0 = -1e30f, mx1 = -1e30f;
#pragma unroll
            for (int nt = 0; nt < 8; nt++) {
                mx0 = fmaxf(mx0, fmaxf(sfr[nt][0], sfr[nt][1]));
                mx1 = fmaxf(mx1, fmaxf(sfr[nt][2], sfr[nt][3]));
            }
            mx0 = fmaxf(mx0, __shfl_xor_sync(0xffffffffu, mx0, 1));
            mx0 = fmaxf(mx0, __shfl_xor_sync(0xffffffffu, mx0, 2));
            mx1 = fmaxf(mx1, __shfl_xor_sync(0xffffffffu, mx1, 1));
            mx1 = fmaxf(mx1, __shfl_xor_sync(0xffffffffu, mx1, 2));

            float mn0 = fmaxf(m0r, mx0), mn1 = fmaxf(m1r, mx1);
            float sc0 = __expf(m0r - mn0), sc1 = __expf(m1r - mn1);
            m0r = mn0; m1r = mn1;

            float sum0 = 0.f, sum1 = 0.f;
#pragma unroll
            for (int nt = 0; nt < 8; nt++) {
                float p0 = __expf(sfr[nt][0] - mn0);
                float p1 = __expf(sfr[nt][1] - mn0);
                float p2 = __expf(sfr[nt][2] - mn1);
                float p3 = __expf(sfr[nt][3] - mn1);
                sum0 += p0 + p1; sum1 += p2 + p3;
                psw[(g) * PW + nt * 4 + tig] = pkbf2(p0, p1);
                psw[(g + 8) * PW + nt * 4 + tig] = pkbf2(p2, p3);
            }
            sum0 += __shfl_xor_sync(0xffffffffu, sum0, 1);
            sum0 += __shfl_xor_sync(0xffffffffu, sum0, 2);
            sum1 += __shfl_xor_sync(0xffffffffu, sum1, 1);
            sum1 += __shfl_xor_sync(0xffffffffu, sum1, 2);
            l0 = l0 * sc0 + sum0;
            l1 = l1 * sc1 + sum1;

#pragma unroll
            for (int nt = 0; nt < 8; nt++) {
                o[nt][0] *= sc0; o[nt][1] *= sc0;
                o[nt][2] *= sc1; o[nt][3] *= sc1;
            }
            __syncwarp();

#pragma unroll
            for (int ks = 0; ks < 4; ks++) {
                int w0 = ks * 8 + tig;
                uint32_t a0 = psw[(g) * PW + w0];
                uint32_t a1 = psw[(g + 8) * PW + w0];
                uint32_t a2 = psw[(g) * PW + w0 + 4];
                uint32_t a3 = psw[(g + 8) * PW + w0 + 4];
#pragma unroll
                for (int nt = 0; nt < 8; nt++) {
                    int d = nt * 8 + g;
                    uint32_t b0 = vt[d * VW + h * 32 + w0];
                    uint32_t b1 = vt[d * VW + h * 32 + w0 + 4];
                    MMA_BF16(o[nt][0], o[nt][1], o[nt][2], o[nt][3],
                             a0, a1, a2, a3, b0, b1);
                }
            }
            __syncwarp();
        }
        __syncthreads();
    }

    {
        float inv0 = 1.f / l0, inv1 = 1.f / l1;
        float* outp = g_attn + ((size_t)b * 512 + n * 64) * 1024 + s0;
        int sA = q0w + g, sB = q0w + g + 8;
#pragma unroll
        for (int nt = 0; nt < 8; nt++) {
            int d = nt * 8 + tig * 2;
            outp[(size_t)d * 1024 + sA] = o[nt][0] * inv0;
            outp[(size_t)(d + 1) * 1024 + sA] = o[nt][1] * inv0;
            outp[(size_t)d * 1024 + sB] = o[nt][2] * inv1;
            outp[(size_t)(d + 1) * 1024 + sB] = o[nt][3] * inv1;
        }
    }
}

// ============================================================
extern "C" void kernel_launch(void* const* d_in, const int* in_sizes, int n_in,
                              void* d_out, int out_size) {
    const float* x       = (const float*)d_in[0];
    const float* context = (const float*)d_in[1];
    const float* gamma   = (const float*)d_in[2];
    const float* beta    = (const float*)d_in[3];
    const float* qkv_w   = (const float*)d_in[4];
    const float* qkv_b   = (const float*)d_in[5];
    const float* ckv_w   = (const float*)d_in[6];
    const float* ckv_b   = (const float*)d_in[7];
    const float* proj_w  = (const float*)d_in[8];
    const float* proj_b  = (const float*)d_in[9];
    float* out = (float*)d_out;

    float *xn_p, *qkv_p, *attn_p;
    cudaGetSymbolAddress((void**)&xn_p, g_xn);
    cudaGetSymbolAddress((void**)&qkv_p, g_qkv);
    cudaGetSymbolAddress((void**)&attn_p, g_attn);

    // 1. GroupNorm
    gn_kernel<<<BATCH * 32, 256>>>(x, gamma, beta, xn_p);

    // 2. QKV projection (tf32 tensor cores)
    gemm_tf32<<<dim3(8, 12, BATCH), 256>>>(qkv_w, qkv_b, xn_p, nullptr, qkv_p, 1536, 1024, 512);

    // 3. Context KV projection
    ckv_kernel<<<dim3(16, BATCH), 256>>>(context, ckv_w, ckv_b);

    // 4a. Pack K/V to bf16 (swizzled K, 0.125 logit scale folded)
    packk_kernel<<<dim3(NCHB * 2, HEADS, BATCH), 256>>>();
    packv_kernel<<<dim3(HEADS, BATCH), 256>>>();

    // 4b. Flash attention v5
    cudaFuncSetAttribute(flash5_kernel, cudaFuncAttributeMaxDynamicSharedMemorySize, FL5_SMEM);
    flash5_kernel<<<dim3(8, HEADS, BATCH), 256, FL5_SMEM>>>();

    // 5. Output projection + bias + residual (tf32 tensor cores)
    gemm_tf32<<<dim3(8, 4, BATCH), 256>>>(proj_w, proj_b, attn_p, x, out, 512, 1024, 512);
}

// round 10
// speedup vs baseline: 2.8107x; 1.0194x over previous
#include <cuda_runtime.h>
#include <cuda_bf16.h>
#include <math.h>
#include <stdint.h>

#define BATCH 8
#define DIMC 512
#define HW 1024
#define HEADS 8
#define HD 64
#define LCTX 77
#define CTXD 768
#define TKV 1101
#define TPAD 1152     // padded KV length (9 chunks of 128)
#define NCHB 9

// ---- scratch (device globals) ----
__device__ float g_xn[BATCH * DIMC * HW];
__device__ float g_qkv[BATCH * 3 * DIMC * HW];
__device__ float g_ckv[BATCH * 2 * DIMC * LCTX];
__device__ float g_attn[BATCH * DIMC * HW];
// packed bf16 KV: K [bn][t][32 words, swizzled, scale-folded], V [bn][d][576 words]
__device__ uint32_t g_kb[BATCH * HEADS * TPAD * 32];
__device__ uint32_t g_vb[BATCH * HEADS * 64 * (TPAD / 2)];

__device__ __forceinline__ float f2tf(float x) {
    uint32_t u = __float_as_uint(x);
    u = (u + 0x1000u) & 0xFFFFE000u;
    return __uint_as_float(u);
}
__device__ __forceinline__ uint32_t pkbf2(float lo, float hi) {
    __nv_bfloat162 v = __floats2bfloat162_rn(lo, hi);
    return *reinterpret_cast<uint32_t*>(&v);
}
__device__ __forceinline__ void cpasync16(uint32_t s, const void* g) {
    asm volatile("cp.async.cg.shared.global [%0], [%1], 16;" :: "r"(s), "l"(g));
}

#define MMA_TF32(c0,c1,c2,c3,a0,a1,a2,a3,b0,b1)                               \
    asm volatile(                                                              \
        "mma.sync.aligned.m16n8k8.row.col.f32.tf32.tf32.f32 "                  \
        "{%0,%1,%2,%3}, {%4,%5,%6,%7}, {%8,%9}, {%0,%1,%2,%3};"                \
        : "+f"(c0), "+f"(c1), "+f"(c2), "+f"(c3)                               \
        : "r"(a0), "r"(a1), "r"(a2), "r"(a3), "r"(b0), "r"(b1))

#define MMA_BF16(c0,c1,c2,c3,a0,a1,a2,a3,b0,b1)                               \
    asm volatile(                                                              \
        "mma.sync.aligned.m16n8k16.row.col.f32.bf16.bf16.f32 "                 \
        "{%0,%1,%2,%3}, {%4,%5,%6,%7}, {%8,%9}, {%0,%1,%2,%3};"                \
        : "+f"(c0), "+f"(c1), "+f"(c2), "+f"(c3)                               \
        : "r"(a0), "r"(a1), "r"(a2), "r"(a3), "r"(b0), "r"(b1))

// ============================================================
// GroupNorm
// ============================================================
__global__ void gn_kernel(const float* __restrict__ x, const float* __restrict__ gamma,
                          const float* __restrict__ beta, float* __restrict__ xn) {
    __shared__ float ssum[256], ssq[256];
    int bg = blockIdx.x;
    int b = bg >> 5, g = bg & 31;
    const float* xp = x + ((size_t)b * DIMC + g * 16) * HW;
    float* xo = xn + ((size_t)b * DIMC + g * 16) * HW;
    int tid = threadIdx.x;

    float s = 0.f, sq = 0.f;
#pragma unroll
    for (int i = 0; i < 64; i++) {
        float v = xp[tid + i * 256];
        s += v; sq += v * v;
    }
    ssum[tid] = s; ssq[tid] = sq;
    __syncthreads();
    for (int off = 128; off > 0; off >>= 1) {
        if (tid < off) { ssum[tid] += ssum[tid + off]; ssq[tid] += ssq[tid + off]; }
        __syncthreads();
    }
    float mu = ssum[0] * (1.f / 16384.f);
    float var = ssq[0] * (1.f / 16384.f) - mu * mu;
    float inv = rsqrtf(var + 1e-5f);
#pragma unroll
    for (int i = 0; i < 64; i++) {
        int idx = tid + i * 256;
        int c = g * 16 + (idx >> 10);
        xo[idx] = (xp[idx] - mu) * inv * gamma[c] + beta[c];
    }
}

// ============================================================
// tf32 tensor-core GEMM (validated)
// ============================================================
__global__ void __launch_bounds__(256) gemm_tf32(
        const float* __restrict__ W, const float* __restrict__ bias,
        const float* __restrict__ X, const float* __restrict__ res,
        float* __restrict__ C, int M, int N, int K) {
    __shared__ float ws[32 * 132];
    __shared__ float xs[32 * 132];

    int b = blockIdx.z;
    int m0 = blockIdx.y * 128, n0 = blockIdx.x * 128;
    const float* Xb = X + (size_t)b * K * N;
    int tid = threadIdx.x;
    int warp = tid >> 5, lane = tid & 31;
    int warpM = warp >> 2, warpN = warp & 3;
    int g = lane >> 2, tig = lane & 3;

    float c[4][4][4];
#pragma unroll
    for (int mt = 0; mt < 4; mt++)
#pragma unroll
        for (int nt = 0; nt < 4; nt++)
#pragma unroll
            for (int r = 0; r < 4; r++) c[mt][nt][r] = 0.f;

    int wr = tid >> 3;
    int wc4 = (tid & 7) * 4;
    int xkr = tid >> 5;
    int xn4 = (tid & 31) * 4;

    for (int k0 = 0; k0 < K; k0 += 32) {
#pragma unroll
        for (int p = 0; p < 4; p++) {
            int m = p * 32 + wr;
            float4 wv = *(const float4*)(W + (size_t)(m0 + m) * K + k0 + wc4);
            ws[(wc4 + 0) * 132 + m] = f2tf(wv.x);
            ws[(wc4 + 1) * 132 + m] = f2tf(wv.y);
            ws[(wc4 + 2) * 132 + m] = f2tf(wv.z);
            ws[(wc4 + 3) * 132 + m] = f2tf(wv.w);
        }
#pragma unroll
        for (int p = 0; p < 4; p++) {
            int k = p * 8 + xkr;
            float4 xv = *(const float4*)(Xb + (size_t)(k0 + k) * N + n0 + xn4);
            float4 t;
            t.x = f2tf(xv.x); t.y = f2tf(xv.y); t.z = f2tf(xv.z); t.w = f2tf(xv.w);
            *(float4*)&xs[k * 132 + xn4] = t;
        }
        __syncthreads();

#pragma unroll
        for (int ks = 0; ks < 4; ks++) {
            int k8 = ks * 8;
            uint32_t a[4][4], bb[4][2];
#pragma unroll
            for (int mt = 0; mt < 4; mt++) {
                int mo = warpM * 64 + mt * 16;
                a[mt][0] = __float_as_uint(ws[(k8 + tig) * 132 + mo + g]);
                a[mt][1] = __float_as_uint(ws[(k8 + tig) * 132 + mo + g + 8]);
                a[mt][2] = __float_as_uint(ws[(k8 + tig + 4) * 132 + mo + g]);
                a[mt][3] = __float_as_uint(ws[(k8 + tig + 4) * 132 + mo + g + 8]);
            }
#pragma unroll
            for (int nt = 0; nt < 4; nt++) {
                int no = warpN * 32 + nt * 8;
                bb[nt][0] = __float_as_uint(xs[(k8 + tig) * 132 + no + g]);
                bb[nt][1] = __float_as_uint(xs[(k8 + tig + 4) * 132 + no + g]);
            }
#pragma unroll
            for (int mt = 0; mt < 4; mt++)
#pragma unroll
                for (int nt = 0; nt < 4; nt++)
                    MMA_TF32(c[mt][nt][0], c[mt][nt][1], c[mt][nt][2], c[mt][nt][3],
                             a[mt][0], a[mt][1], a[mt][2], a[mt][3],
                             bb[nt][0], bb[nt][1]);
        }
        __syncthreads();
    }

#pragma unroll
    for (int mt = 0; mt < 4; mt++) {
#pragma unroll
        for (int half = 0; half < 2; half++) {
            int m = m0 + warpM * 64 + mt * 16 + g + half * 8;
            float bv = bias[m];
            size_t rowoff = ((size_t)b * M + m) * N;
#pragma unroll
            for (int nt = 0; nt < 4; nt++) {
                int n = n0 + warpN * 32 + nt * 8 + tig * 2;
                float v0 = c[mt][nt][half * 2 + 0] + bv;
                float v1 = c[mt][nt][half * 2 + 1] + bv;
                if (res) {
                    v0 += res[rowoff + n];
                    v1 += res[rowoff + n + 1];
                }
                C[rowoff + n] = v0;
                C[rowoff + n + 1] = v1;
            }
        }
    }
}

// ============================================================
// ckv GEMM (fp32, small)
// ============================================================
__global__ void ckv_kernel(const float* __restrict__ ctx, const float* __restrict__ W,
                           const float* __restrict__ bias) {
    __shared__ float ws2[32 * 65];
    __shared__ float cs[32 * 81];
    int ot = blockIdx.x, b = blockIdx.y;
    int tid = threadIdx.x;
    int tx = tid & 15, tg = tid >> 4;
    int cc = tid & 31, rr = tid >> 5;
    int ob = tg * 4, lb = tx * 5;

    float acc[4][5];
#pragma unroll
    for (int i = 0; i < 4; i++)
#pragma unroll
        for (int j = 0; j < 5; j++) acc[i][j] = 0.f;

    for (int c0 = 0; c0 < CTXD; c0 += 32) {
#pragma unroll
        for (int p = 0; p < 8; p++) {
            int o = p * 8 + rr;
            ws2[cc * 65 + o] = W[(size_t)(ot * 64 + o) * CTXD + c0 + cc];
        }
#pragma unroll
        for (int p = 0; p < 10; p++) {
            int l = p * 8 + rr;
            float v = (l < LCTX) ? ctx[((size_t)b * LCTX + l) * CTXD + c0 + cc] : 0.f;
            cs[cc * 81 + l] = v;
        }
        __syncthreads();
#pragma unroll
        for (int kk = 0; kk < 32; kk++) {
            float wv[4], cv[5];
#pragma unroll
            for (int i = 0; i < 4; i++) wv[i] = ws2[kk * 65 + ob + i];
#pragma unroll
            for (int j = 0; j < 5; j++) cv[j] = cs[kk * 81 + lb + j];
#pragma unroll
            for (int i = 0; i < 4; i++)
#pragma unroll
                for (int j = 0; j < 5; j++) acc[i][j] += wv[i] * cv[j];
        }
        __syncthreads();
    }

#pragma unroll
    for (int i = 0; i < 4; i++) {
        int o = ot * 64 + ob + i;
        float bv = bias[o];
#pragma unroll
        for (int j = 0; j < 5; j++) {
            int l = lb + j;
            if (l < LCTX)
                g_ckv[((size_t)b * 1024 + o) * LCTX + l] = acc[i][j] + bv;
        }
    }
}

// ============================================================
// packk: g_kb[bn][t][32w] bf16, swizzled, 0.125 logit scale folded.
// ============================================================
__global__ void packk_kernel() {
    __shared__ unsigned short ks[64][66];
    int tt = blockIdx.x, n = blockIdx.y, b = blockIdx.z;
    int tid = threadIdx.x;
    const float* kck = g_ckv + ((size_t)b * 1024 + n * 64) * LCTX;
    const float* kim = g_qkv + ((size_t)b * 1536 + 512 + n * 64) * 1024;
    int tl = tid & 63, dh = tid >> 6;
    int t0 = tt * 64;
#pragma unroll
    for (int p = 0; p < 16; p++) {
        int d = p * 4 + dh;
        int gt = t0 + tl;
        float kv = 0.f;
        if (gt < LCTX) kv = kck[d * LCTX + gt];
        else if (gt < TKV) kv = kim[(size_t)d * 1024 + (gt - LCTX)];
        __nv_bfloat16 h = __float2bfloat16_rn(kv * 0.125f);
        ks[d][tl] = *reinterpret_cast<unsigned short*>(&h);
    }
    __syncthreads();

    int row = tid >> 2, q = tid & 3;
    int t = t0 + row;
    int s = (t >> 3) & 3;
    uint32_t* outw = g_kb + ((size_t)(b * HEADS + n) * TPAD + t) * 32;
#pragma unroll
    for (int half = 0; half < 2; half++) {
        int w0 = q * 4 + half * 16;
        uint32_t wv[4];
#pragma unroll
        for (int j = 0; j < 4; j++) {
            int p = (w0 + j) ^ s;
            wv[j] = (uint32_t)ks[2 * p][row] | ((uint32_t)ks[2 * p + 1][row] << 16);
        }
        uint4 v = {wv[0], wv[1], wv[2], wv[3]};
        *(uint4*)(outw + w0) = v;
    }
}

// ============================================================
// packv: g_vb[bn][d][576w] bf16 ([d][t] pairs).
// ============================================================
__global__ void packv_kernel() {
    int n = blockIdx.x, b = blockIdx.y;
    int tid = threadIdx.x;
    const float* vck = g_ckv + ((size_t)b * 1024 + 512 + n * 64) * LCTX;
    const float* vim = g_qkv + ((size_t)b * 1536 + 1024 + n * 64) * 1024;
    uint32_t* outw = g_vb + (size_t)(b * HEADS + n) * 64 * (TPAD / 2);
    for (int d = 0; d < 64; d++) {
        for (int tp = tid; tp < TPAD / 2; tp += 256) {
            int t = tp * 2;
            float v0 = 0.f, v1 = 0.f;
            if (t < LCTX) v0 = vck[d * LCTX + t];
            else if (t < TKV) v0 = vim[(size_t)d * 1024 + (t - LCTX)];
            if (t + 1 < LCTX) v1 = vck[d * LCTX + t + 1];
            else if (t + 1 < TKV) v1 = vim[(size_t)d * 1024 + (t + 1 - LCTX)];
            outw[(size_t)d * (TPAD / 2) + tp] = pkbf2(v0, v1);
        }
    }
}

// ============================================================
// Flash attention v6: bf16 mma, packed KV, cp.async double buffer,
// and C->A fragment identity for P (no smem round-trip).
// smem words: qs[128*36], kt[2][128*36], vt[2][64*68]  = 90112 B
// ============================================================
#define QW 36
#define KW 36
#define VW 68
#define FL6_WORDS (128*QW + 2*(128*KW + 64*VW))
#define FL6_SMEM (FL6_WORDS * 4)   // 90112 B

__global__ void __launch_bounds__(256, 2) flash6_kernel() {
    extern __shared__ uint32_t sm6[];
    uint32_t* qs = sm6;
    uint32_t* ktb[2] = { qs + 128 * QW, qs + 128 * QW + 128 * KW };
    uint32_t* vtb[2] = { ktb[1] + 128 * KW, ktb[1] + 128 * KW + 64 * VW };
    __nv_bfloat16* qsb = (__nv_bfloat16*)qs;

    int s0 = blockIdx.x * 128;
    int n = blockIdx.y, b = blockIdx.z;
    int bn = b * HEADS + n;
    int tid = threadIdx.x;
    int warp = tid >> 5, lane = tid & 31;
    int g = lane >> 2, tig = lane & 3;
    int q0w = warp * 16;

    uint32_t kts[2], vts[2];
    kts[0] = (uint32_t)__cvta_generic_to_shared(ktb[0]);
    kts[1] = (uint32_t)__cvta_generic_to_shared(ktb[1]);
    vts[0] = (uint32_t)__cvta_generic_to_shared(vtb[0]);
    vts[1] = (uint32_t)__cvta_generic_to_shared(vtb[1]);

    const uint32_t* gk = g_kb + (size_t)bn * TPAD * 32;
    const uint32_t* gv = g_vb + (size_t)bn * 64 * (TPAD / 2);

    int ktrow = tid >> 1, ktq = tid & 1;
    int vdrow = tid >> 2, vwq = tid & 3;

    const float* qbase = g_qkv + ((size_t)b * 1536 + n * 64) * 1024 + s0;
    {
        int s = tid & 127, hi = tid >> 7;
#pragma unroll
        for (int p = 0; p < 32; p++) {
            int d = p * 2 + hi;
            qsb[s * (QW * 2) + d] = __float2bfloat16_rn(qbase[(size_t)d * 1024 + s]);
        }
    }

#define ISSUE_CHUNK(c)                                                         \
    do {                                                                       \
        int _bb = (c) & 1;                                                     \
        const uint32_t* _gkc = gk + ((size_t)(c) * 128 + ktrow) * 32 + ktq * 16; \
        uint32_t _kd = kts[_bb] + (ktrow * KW + ktq * 16) * 4;                 \
        cpasync16(_kd + 0,  _gkc + 0);                                         \
        cpasync16(_kd + 16, _gkc + 4);                                         \
        cpasync16(_kd + 32, _gkc + 8);                                         \
        cpasync16(_kd + 48, _gkc + 12);                                        \
        const uint32_t* _gvc = gv + (size_t)vdrow * (TPAD / 2) + (c) * 64 + vwq * 16; \
        uint32_t _vd = vts[_bb] + (vdrow * VW + vwq * 16) * 4;                 \
        cpasync16(_vd + 0,  _gvc + 0);                                         \
        cpasync16(_vd + 16, _gvc + 4);                                         \
        cpasync16(_vd + 32, _gvc + 8);                                         \
        cpasync16(_vd + 48, _gvc + 12);                                        \
        asm volatile("cp.async.commit_group;");                                \
    } while (0)

    ISSUE_CHUNK(0);

    float m0r = -1e30f, m1r = -1e30f, l0 = 0.f, l1 = 0.f;
    float o[8][4];
#pragma unroll
    for (int nt = 0; nt < 8; nt++)
#pragma unroll
        for (int r = 0; r < 4; r++) o[nt][r] = 0.f;

    for (int c = 0; c < NCHB; c++) {
        if (c + 1 < NCHB) {
            ISSUE_CHUNK(c + 1);
            asm volatile("cp.async.wait_group 1;");
        } else {
            asm volatile("cp.async.wait_group 0;");
        }
        __syncthreads();

        uint32_t* kt = ktb[c & 1];
        uint32_t* vt = vtb[c & 1];
        int t0 = c * 128;

#pragma unroll
        for (int h = 0; h < 2; h++) {
            // ---- S = Q K^T (scale pre-folded into K) ----
            float sfr[8][4];
#pragma unroll
            for (int nt = 0; nt < 8; nt++)
#pragma unroll
                for (int r = 0; r < 4; r++) sfr[nt][r] = 0.f;

#pragma unroll
            for (int ks = 0; ks < 4; ks++) {
                int w0 = ks * 8 + tig;
                uint32_t a0 = qs[(q0w + g) * QW + w0];
                uint32_t a1 = qs[(q0w + g + 8) * QW + w0];
                uint32_t a2 = qs[(q0w + g) * QW + w0 + 4];
                uint32_t a3 = qs[(q0w + g + 8) * QW + w0 + 4];
#pragma unroll
                for (int nt = 0; nt < 8; nt++) {
                    int t = h * 64 + nt * 8 + g;
                    int bw = w0 ^ (nt & 3);
                    uint32_t b0 = kt[t * KW + bw];
                    uint32_t b1 = kt[t * KW + bw + 4];
                    MMA_BF16(sfr[nt][0], sfr[nt][1], sfr[nt][2], sfr[nt][3],
                             a0, a1, a2, a3, b0, b1);
                }
            }

            // mask (last chunk only)
            if (t0 + h * 64 + 64 > TKV) {
#pragma unroll
                for (int nt = 0; nt < 8; nt++) {
                    int t = t0 + h * 64 + nt * 8 + tig * 2;
                    if (t >= TKV) { sfr[nt][0] = -1e30f; sfr[nt][2] = -1e30f; }
                    if (t + 1 >= TKV) { sfr[nt][1] = -1e30f; sfr[nt][3] = -1e30f; }
                }
            }

            // ---- online softmax (rows g, g+8; cols across 4 tig lanes) ----
            float mx0 = -1e30f, mx1 = -1e30f;
#pragma unroll
            for (int nt = 0; nt < 8; nt++) {
                mx0 = fmaxf(mx0, fmaxf(sfr[nt][0], sfr[nt][1]));
                mx1 = fmaxf(mx1, fmaxf(sfr[nt][2], sfr[nt][3]));
            }
            mx0 = fmaxf(mx0, __shfl_xor_sync(0xffffffffu, mx0, 1));
            mx0 = fmaxf(mx0, __shfl_xor_sync(0xffffffffu, mx0, 2));
            mx1 = fmaxf(mx1, __shfl_xor_sync(0xffffffffu, mx1, 1));
            mx1 = fmaxf(mx1, __shfl_xor_sync(0xffffffffu, mx1, 2));

            float mn0 = fmaxf(m0r, mx0), mn1 = fmaxf(m1r, mx1);
            float sc0 = __expf(m0r - mn0), sc1 = __expf(m1r - mn1);
            m0r = mn0; m1r = mn1;

            float sum0 = 0.f, sum1 = 0.f;
#pragma unroll
            for (int nt = 0; nt < 8; nt++) {
                sfr[nt][0] = __expf(sfr[nt][0] - mn0);
                sfr[nt][1] = __expf(sfr[nt][1] - mn0);
                sfr[nt][2] = __expf(sfr[nt][2] - mn1);
                sfr[nt][3] = __expf(sfr[nt][3] - mn1);
                sum0 += sfr[nt][0] + sfr[nt][1];
                sum1 += sfr[nt][2] + sfr[nt][3];
            }
            sum0 += __shfl_xor_sync(0xffffffffu, sum0, 1);
            sum0 += __shfl_xor_sync(0xffffffffu, sum0, 2);
            sum1 += __shfl_xor_sync(0xffffffffu, sum1, 1);
            sum1 += __shfl_xor_sync(0xffffffffu, sum1, 2);
            l0 = l0 * sc0 + sum0;
            l1 = l1 * sc1 + sum1;

#pragma unroll
            for (int nt = 0; nt < 8; nt++) {
                o[nt][0] *= sc0; o[nt][1] *= sc0;
                o[nt][2] *= sc1; o[nt][3] *= sc1;
            }

            // ---- O += P V : P fragments built directly from S C-fragments ----
            // A tile over t in [16ks,16ks+16): a0=pk(S[2ks].c0,c1) (row g),
            // a1=pk(S[2ks].c2,c3) (row g+8), a2/a3 = same for tile 2ks+1.
#pragma unroll
            for (int ks = 0; ks < 4; ks++) {
                uint32_t a0 = pkbf2(sfr[2 * ks][0], sfr[2 * ks][1]);
                uint32_t a1 = pkbf2(sfr[2 * ks][2], sfr[2 * ks][3]);
                uint32_t a2 = pkbf2(sfr[2 * ks + 1][0], sfr[2 * ks + 1][1]);
                uint32_t a3 = pkbf2(sfr[2 * ks + 1][2], sfr[2 * ks + 1][3]);
                int w0 = ks * 8 + tig;
#pragma unroll
                for (int nt = 0; nt < 8; nt++) {
                    int d = nt * 8 + g;
                    uint32_t b0 = vt[d * VW + h * 32 + w0];
                    uint32_t b1 = vt[d * VW + h * 32 + w0 + 4];
                    MMA_BF16(o[nt][0], o[nt][1], o[nt][2], o[nt][3],
                             a0, a1, a2, a3, b0, b1);
                }
            }
        }
        __syncthreads();
    }

    // ---- normalize + direct global store ----
    {
        float inv0 = 1.f / l0, inv1 = 1.f / l1;
        float* outp = g_attn + ((size_t)b * 512 + n * 64) * 1024 + s0;
        int sA = q0w + g, sB = q0w + g + 8;
#pragma unroll
        for (int nt = 0; nt < 8; nt++) {
            int d = nt * 8 + tig * 2;
            outp[(size_t)d * 1024 + sA] = o[nt][0] * inv0;
            outp[(size_t)(d + 1) * 1024 + sA] = o[nt][1] * inv0;
            outp[(size_t)d * 1024 + sB] = o[nt][2] * inv1;
            outp[(size_t)(d + 1) * 1024 + sB] = o[nt][3] * inv1;
        }
    }
}

// ============================================================
extern "C" void kernel_launch(void* const* d_in, const int* in_sizes, int n_in,
                              void* d_out, int out_size) {
    const float* x       = (const float*)d_in[0];
    const float* context = (const float*)d_in[1];
    const float* gamma   = (const float*)d_in[2];
    const float* beta    = (const float*)d_in[3];
    const float* qkv_w   = (const float*)d_in[4];
    const float* qkv_b   = (const float*)d_in[5];
    const float* ckv_w   = (const float*)d_in[6];
    const float* ckv_b   = (const float*)d_in[7];
    const float* proj_w  = (const float*)d_in[8];
    const float* proj_b  = (const float*)d_in[9];
    float* out = (float*)d_out;

    float *xn_p, *qkv_p, *attn_p;
    cudaGetSymbolAddress((void**)&xn_p, g_xn);
    cudaGetSymbolAddress((void**)&qkv_p, g_qkv);
    cudaGetSymbolAddress((void**)&attn_p, g_attn);

    // 1. GroupNorm
    gn_kernel<<<BATCH * 32, 256>>>(x, gamma, beta, xn_p);

    // 2. QKV projection (tf32 tensor cores)
    gemm_tf32<<<dim3(8, 12, BATCH), 256>>>(qkv_w, qkv_b, xn_p, nullptr, qkv_p, 1536, 1024, 512);

    // 3. Context KV projection
    ckv_kernel<<<dim3(16, BATCH), 256>>>(context, ckv_w, ckv_b);

    // 4a. Pack K/V to bf16 (swizzled K, 0.125 logit scale folded)
    packk_kernel<<<dim3(NCHB * 2, HEADS, BATCH), 256>>>();
    packv_kernel<<<dim3(HEADS, BATCH), 256>>>();

    // 4b. Flash attention v6
    cudaFuncSetAttribute(flash6_kernel, cudaFuncAttributeMaxDynamicSharedMemorySize, FL6_SMEM);
    flash6_kernel<<<dim3(8, HEADS, BATCH), 256, FL6_SMEM>>>();

    // 5. Output projection + bias + residual (tf32 tensor cores)
    gemm_tf32<<<dim3(8, 4, BATCH), 256>>>(proj_w, proj_b, attn_p, x, out, 512, 1024, 512);
}

// round 11
// speedup vs baseline: 3.4358x; 1.2224x over previous
#include <cuda_runtime.h>
#include <cuda_bf16.h>
#include <math.h>
#include <stdint.h>

#define BATCH 8
#define DIMC 512
#define HW 1024
#define HEADS 8
#define HD 64
#define LCTX 77
#define CTXD 768
#define TKV 1101
#define TPAD 1152     // padded KV length (9 chunks of 128)
#define NCHB 9

// ---- scratch (device globals) ----
__device__ float g_xn[BATCH * DIMC * HW];
__device__ float g_qkv[BATCH * 3 * DIMC * HW];
__device__ float g_ckv[BATCH * 2 * DIMC * LCTX];
__device__ float g_attn[BATCH * DIMC * HW];
__device__ uint32_t g_kb[BATCH * HEADS * TPAD * 32];
__device__ uint32_t g_vb[BATCH * HEADS * 64 * (TPAD / 2)];

__device__ __forceinline__ float f2tf(float x) {
    uint32_t u = __float_as_uint(x);
    u = (u + 0x1000u) & 0xFFFFE000u;
    return __uint_as_float(u);
}
__device__ __forceinline__ uint32_t pkbf2(float lo, float hi) {
    __nv_bfloat162 v = __floats2bfloat162_rn(lo, hi);
    return *reinterpret_cast<uint32_t*>(&v);
}
__device__ __forceinline__ void cpasync16(uint32_t s, const void* g) {
    asm volatile("cp.async.cg.shared.global [%0], [%1], 16;" :: "r"(s), "l"(g));
}
__device__ __forceinline__ uint32_t smaddr(const void* p) {
    return (uint32_t)__cvta_generic_to_shared(p);
}

#define MMA_TF32(c0,c1,c2,c3,a0,a1,a2,a3,b0,b1)                               \
    asm volatile(                                                              \
        "mma.sync.aligned.m16n8k8.row.col.f32.tf32.tf32.f32 "                  \
        "{%0,%1,%2,%3}, {%4,%5,%6,%7}, {%8,%9}, {%0,%1,%2,%3};"                \
        : "+f"(c0), "+f"(c1), "+f"(c2), "+f"(c3)                               \
        : "r"(a0), "r"(a1), "r"(a2), "r"(a3), "r"(b0), "r"(b1))

#define MMA_BF16(c0,c1,c2,c3,a0,a1,a2,a3,b0,b1)                               \
    asm volatile(                                                              \
        "mma.sync.aligned.m16n8k16.row.col.f32.bf16.bf16.f32 "                 \
        "{%0,%1,%2,%3}, {%4,%5,%6,%7}, {%8,%9}, {%0,%1,%2,%3};"                \
        : "+f"(c0), "+f"(c1), "+f"(c2), "+f"(c3)                               \
        : "r"(a0), "r"(a1), "r"(a2), "r"(a3), "r"(b0), "r"(b1))

// ============================================================
// GroupNorm
// ============================================================
__global__ void gn_kernel(const float* __restrict__ x, const float* __restrict__ gamma,
                          const float* __restrict__ beta, float* __restrict__ xn) {
    __shared__ float ssum[256], ssq[256];
    int bg = blockIdx.x;
    int b = bg >> 5, g = bg & 31;
    const float* xp = x + ((size_t)b * DIMC + g * 16) * HW;
    float* xo = xn + ((size_t)b * DIMC + g * 16) * HW;
    int tid = threadIdx.x;

    float s = 0.f, sq = 0.f;
#pragma unroll
    for (int i = 0; i < 64; i++) {
        float v = xp[tid + i * 256];
        s += v; sq += v * v;
    }
    ssum[tid] = s; ssq[tid] = sq;
    __syncthreads();
    for (int off = 128; off > 0; off >>= 1) {
        if (tid < off) { ssum[tid] += ssum[tid + off]; ssq[tid] += ssq[tid + off]; }
        __syncthreads();
    }
    float mu = ssum[0] * (1.f / 16384.f);
    float var = ssq[0] * (1.f / 16384.f) - mu * mu;
    float inv = rsqrtf(var + 1e-5f);
#pragma unroll
    for (int i = 0; i < 64; i++) {
        int idx = tid + i * 256;
        int c = g * 16 + (idx >> 10);
        xo[idx] = (xp[idx] - mu) * inv * gamma[c] + beta[c];
    }
}

// ============================================================
// bf16 tensor-core GEMM (m16n8k16): C = W X + bias (+res)
// 128x128 tile, BK=32, 256 thr, warp tile 64x32.
// A: bf16 pairs [m][20 words] (pad-20 conflict-free fragment reads)
// B: row-major bf16 [k][136], fragments via ldmatrix.x2.trans
// ============================================================
__global__ void __launch_bounds__(256) gemm_bf16(
        const float* __restrict__ W, const float* __restrict__ bias,
        const float* __restrict__ X, const float* __restrict__ res,
        float* __restrict__ C, int M, int N, int K) {
    __shared__ uint32_t wsb[128 * 20];          // 10240 B
    __shared__ __nv_bfloat16 xsb[32][136];      //  8704 B

    int b = blockIdx.z;
    int m0 = blockIdx.y * 128, n0 = blockIdx.x * 128;
    const float* Xb = X + (size_t)b * K * N;
    int tid = threadIdx.x;
    int warp = tid >> 5, lane = tid & 31;
    int warpM = warp >> 2, warpN = warp & 3;
    int g = lane >> 2, tig = lane & 3;

    float c[4][4][4];
#pragma unroll
    for (int mt = 0; mt < 4; mt++)
#pragma unroll
        for (int nt = 0; nt < 4; nt++)
#pragma unroll
            for (int r = 0; r < 4; r++) c[mt][nt][r] = 0.f;

    int wrow = tid >> 1, wseg = tid & 1;      // W: row 0..127, 16-float seg
    int xk = tid >> 3, xn16 = (tid & 7) * 16; // X: k-row 0..31, 16-n seg

    for (int k0 = 0; k0 < K; k0 += 32) {
        // stage W[m0+wrow][k0+wseg*16 .. +16) -> bf16 pairs
        {
            const float* wp = W + (size_t)(m0 + wrow) * K + k0 + wseg * 16;
            float4 f0 = *(const float4*)(wp + 0);
            float4 f1 = *(const float4*)(wp + 4);
            float4 f2 = *(const float4*)(wp + 8);
            float4 f3 = *(const float4*)(wp + 12);
            uint32_t* wd = wsb + wrow * 20 + wseg * 8;
            wd[0] = pkbf2(f0.x, f0.y); wd[1] = pkbf2(f0.z, f0.w);
            wd[2] = pkbf2(f1.x, f1.y); wd[3] = pkbf2(f1.z, f1.w);
            wd[4] = pkbf2(f2.x, f2.y); wd[5] = pkbf2(f2.z, f2.w);
            wd[6] = pkbf2(f3.x, f3.y); wd[7] = pkbf2(f3.z, f3.w);
        }
        // stage X[k0+xk][n0+xn16 .. +16) -> bf16 row-major
        {
            const float* xp = Xb + (size_t)(k0 + xk) * N + n0 + xn16;
            float4 f0 = *(const float4*)(xp + 0);
            float4 f1 = *(const float4*)(xp + 4);
            float4 f2 = *(const float4*)(xp + 8);
            float4 f3 = *(const float4*)(xp + 12);
            uint32_t* xd = (uint32_t*)&xsb[xk][xn16];
            xd[0] = pkbf2(f0.x, f0.y); xd[1] = pkbf2(f0.z, f0.w);
            xd[2] = pkbf2(f1.x, f1.y); xd[3] = pkbf2(f1.z, f1.w);
            xd[4] = pkbf2(f2.x, f2.y); xd[5] = pkbf2(f2.z, f2.w);
            xd[6] = pkbf2(f3.x, f3.y); xd[7] = pkbf2(f3.z, f3.w);
        }
        __syncthreads();

#pragma unroll
        for (int ks = 0; ks < 2; ks++) {
            // B fragments: ldmatrix.x2.trans per n8 tile
            uint32_t bfr[4][2];
#pragma unroll
            for (int nt = 0; nt < 4; nt++) {
                int no = warpN * 32 + nt * 8;
                uint32_t addr = smaddr(&xsb[ks * 16 + (lane & 15)][no]);
                asm volatile(
                    "ldmatrix.sync.aligned.m8n8.x2.trans.shared.b16 {%0,%1}, [%2];"
                    : "=r"(bfr[nt][0]), "=r"(bfr[nt][1]) : "r"(addr));
            }
#pragma unroll
            for (int mt = 0; mt < 4; mt++) {
                int mo = warpM * 64 + mt * 16;
                uint32_t a0 = wsb[(mo + g) * 20 + ks * 8 + tig];
                uint32_t a1 = wsb[(mo + g + 8) * 20 + ks * 8 + tig];
                uint32_t a2 = wsb[(mo + g) * 20 + ks * 8 + tig + 4];
                uint32_t a3 = wsb[(mo + g + 8) * 20 + ks * 8 + tig + 4];
#pragma unroll
                for (int nt = 0; nt < 4; nt++)
                    MMA_BF16(c[mt][nt][0], c[mt][nt][1], c[mt][nt][2], c[mt][nt][3],
                             a0, a1, a2, a3, bfr[nt][0], bfr[nt][1]);
            }
        }
        __syncthreads();
    }

#pragma unroll
    for (int mt = 0; mt < 4; mt++) {
#pragma unroll
        for (int half = 0; half < 2; half++) {
            int m = m0 + warpM * 64 + mt * 16 + g + half * 8;
            float bv = bias[m];
            size_t rowoff = ((size_t)b * M + m) * N;
#pragma unroll
            for (int nt = 0; nt < 4; nt++) {
                int n = n0 + warpN * 32 + nt * 8 + tig * 2;
                float v0 = c[mt][nt][half * 2 + 0] + bv;
                float v1 = c[mt][nt][half * 2 + 1] + bv;
                if (res) {
                    v0 += res[rowoff + n];
                    v1 += res[rowoff + n + 1];
                }
                C[rowoff + n] = v0;
                C[rowoff + n + 1] = v1;
            }
        }
    }
}

// ============================================================
// tf32 tensor-core GEMM (validated; used for proj)
// ============================================================
__global__ void __launch_bounds__(256) gemm_tf32(
        const float* __restrict__ W, const float* __restrict__ bias,
        const float* __restrict__ X, const float* __restrict__ res,
        float* __restrict__ C, int M, int N, int K) {
    __shared__ float ws[32 * 132];
    __shared__ float xs[32 * 132];

    int b = blockIdx.z;
    int m0 = blockIdx.y * 128, n0 = blockIdx.x * 128;
    const float* Xb = X + (size_t)b * K * N;
    int tid = threadIdx.x;
    int warp = tid >> 5, lane = tid & 31;
    int warpM = warp >> 2, warpN = warp & 3;
    int g = lane >> 2, tig = lane & 3;

    float c[4][4][4];
#pragma unroll
    for (int mt = 0; mt < 4; mt++)
#pragma unroll
        for (int nt = 0; nt < 4; nt++)
#pragma unroll
            for (int r = 0; r < 4; r++) c[mt][nt][r] = 0.f;

    int wr = tid >> 3;
    int wc4 = (tid & 7) * 4;
    int xkr = tid >> 5;
    int xn4 = (tid & 31) * 4;

    for (int k0 = 0; k0 < K; k0 += 32) {
#pragma unroll
        for (int p = 0; p < 4; p++) {
            int m = p * 32 + wr;
            float4 wv = *(const float4*)(W + (size_t)(m0 + m) * K + k0 + wc4);
            ws[(wc4 + 0) * 132 + m] = f2tf(wv.x);
            ws[(wc4 + 1) * 132 + m] = f2tf(wv.y);
            ws[(wc4 + 2) * 132 + m] = f2tf(wv.z);
            ws[(wc4 + 3) * 132 + m] = f2tf(wv.w);
        }
#pragma unroll
        for (int p = 0; p < 4; p++) {
            int k = p * 8 + xkr;
            float4 xv = *(const float4*)(Xb + (size_t)(k0 + k) * N + n0 + xn4);
            float4 t;
            t.x = f2tf(xv.x); t.y = f2tf(xv.y); t.z = f2tf(xv.z); t.w = f2tf(xv.w);
            *(float4*)&xs[k * 132 + xn4] = t;
        }
        __syncthreads();

#pragma unroll
        for (int ks = 0; ks < 4; ks++) {
            int k8 = ks * 8;
            uint32_t a[4][4], bb[4][2];
#pragma unroll
            for (int mt = 0; mt < 4; mt++) {
                int mo = warpM * 64 + mt * 16;
                a[mt][0] = __float_as_uint(ws[(k8 + tig) * 132 + mo + g]);
                a[mt][1] = __float_as_uint(ws[(k8 + tig) * 132 + mo + g + 8]);
                a[mt][2] = __float_as_uint(ws[(k8 + tig + 4) * 132 + mo + g]);
                a[mt][3] = __float_as_uint(ws[(k8 + tig + 4) * 132 + mo + g + 8]);
            }
#pragma unroll
            for (int nt = 0; nt < 4; nt++) {
                int no = warpN * 32 + nt * 8;
                bb[nt][0] = __float_as_uint(xs[(k8 + tig) * 132 + no + g]);
                bb[nt][1] = __float_as_uint(xs[(k8 + tig + 4) * 132 + no + g]);
            }
#pragma unroll
            for (int mt = 0; mt < 4; mt++)
#pragma unroll
                for (int nt = 0; nt < 4; nt++)
                    MMA_TF32(c[mt][nt][0], c[mt][nt][1], c[mt][nt][2], c[mt][nt][3],
                             a[mt][0], a[mt][1], a[mt][2], a[mt][3],
                             bb[nt][0], bb[nt][1]);
        }
        __syncthreads();
    }

#pragma unroll
    for (int mt = 0; mt < 4; mt++) {
#pragma unroll
        for (int half = 0; half < 2; half++) {
            int m = m0 + warpM * 64 + mt * 16 + g + half * 8;
            float bv = bias[m];
            size_t rowoff = ((size_t)b * M + m) * N;
#pragma unroll
            for (int nt = 0; nt < 4; nt++) {
                int n = n0 + warpN * 32 + nt * 8 + tig * 2;
                float v0 = c[mt][nt][half * 2 + 0] + bv;
                float v1 = c[mt][nt][half * 2 + 1] + bv;
                if (res) {
                    v0 += res[rowoff + n];
                    v1 += res[rowoff + n + 1];
                }
                C[rowoff + n] = v0;
                C[rowoff + n + 1] = v1;
            }
        }
    }
}

// ============================================================
// ckv GEMM (fp32, small)
// ============================================================
__global__ void ckv_kernel(const float* __restrict__ ctx, const float* __restrict__ W,
                           const float* __restrict__ bias) {
    __shared__ float ws2[32 * 65];
    __shared__ float cs[32 * 81];
    int ot = blockIdx.x, b = blockIdx.y;
    int tid = threadIdx.x;
    int tx = tid & 15, tg = tid >> 4;
    int cc = tid & 31, rr = tid >> 5;
    int ob = tg * 4, lb = tx * 5;

    float acc[4][5];
#pragma unroll
    for (int i = 0; i < 4; i++)
#pragma unroll
        for (int j = 0; j < 5; j++) acc[i][j] = 0.f;

    for (int c0 = 0; c0 < CTXD; c0 += 32) {
#pragma unroll
        for (int p = 0; p < 8; p++) {
            int o = p * 8 + rr;
            ws2[cc * 65 + o] = W[(size_t)(ot * 64 + o) * CTXD + c0 + cc];
        }
#pragma unroll
        for (int p = 0; p < 10; p++) {
            int l = p * 8 + rr;
            float v = (l < LCTX) ? ctx[((size_t)b * LCTX + l) * CTXD + c0 + cc] : 0.f;
            cs[cc * 81 + l] = v;
        }
        __syncthreads();
#pragma unroll
        for (int kk = 0; kk < 32; kk++) {
            float wv[4], cv[5];
#pragma unroll
            for (int i = 0; i < 4; i++) wv[i] = ws2[kk * 65 + ob + i];
#pragma unroll
            for (int j = 0; j < 5; j++) cv[j] = cs[kk * 81 + lb + j];
#pragma unroll
            for (int i = 0; i < 4; i++)
#pragma unroll
                for (int j = 0; j < 5; j++) acc[i][j] += wv[i] * cv[j];
        }
        __syncthreads();
    }

#pragma unroll
    for (int i = 0; i < 4; i++) {
        int o = ot * 64 + ob + i;
        float bv = bias[o];
#pragma unroll
        for (int j = 0; j < 5; j++) {
            int l = lb + j;
            if (l < LCTX)
                g_ckv[((size_t)b * 1024 + o) * LCTX + l] = acc[i][j] + bv;
        }
    }
}

// ============================================================
// packk: g_kb[bn][t][32w] bf16, swizzled, 0.125 logit scale folded.
// ============================================================
__global__ void packk_kernel() {
    __shared__ unsigned short ks[64][66];
    int tt = blockIdx.x, n = blockIdx.y, b = blockIdx.z;
    int tid = threadIdx.x;
    const float* kck = g_ckv + ((size_t)b * 1024 + n * 64) * LCTX;
    const float* kim = g_qkv + ((size_t)b * 1536 + 512 + n * 64) * 1024;
    int tl = tid & 63, dh = tid >> 6;
    int t0 = tt * 64;
#pragma unroll
    for (int p = 0; p < 16; p++) {
        int d = p * 4 + dh;
        int gt = t0 + tl;
        float kv = 0.f;
        if (gt < LCTX) kv = kck[d * LCTX + gt];
        else if (gt < TKV) kv = kim[(size_t)d * 1024 + (gt - LCTX)];
        __nv_bfloat16 h = __float2bfloat16_rn(kv * 0.125f);
        ks[d][tl] = *reinterpret_cast<unsigned short*>(&h);
    }
    __syncthreads();

    int row = tid >> 2, q = tid & 3;
    int t = t0 + row;
    int s = (t >> 3) & 3;
    uint32_t* outw = g_kb + ((size_t)(b * HEADS + n) * TPAD + t) * 32;
#pragma unroll
    for (int half = 0; half < 2; half++) {
        int w0 = q * 4 + half * 16;
        uint32_t wv[4];
#pragma unroll
        for (int j = 0; j < 4; j++) {
            int p = (w0 + j) ^ s;
            wv[j] = (uint32_t)ks[2 * p][row] | ((uint32_t)ks[2 * p + 1][row] << 16);
        }
        uint4 v = {wv[0], wv[1], wv[2], wv[3]};
        *(uint4*)(outw + w0) = v;
    }
}

// ============================================================
// packv: g_vb[bn][d][576w] bf16 ([d][t] pairs). grid (9, HEADS, BATCH).
// ============================================================
__global__ void packv_kernel() {
    int ck = blockIdx.x, n = blockIdx.y, b = blockIdx.z;
    int tid = threadIdx.x;
    const float* vck = g_ckv + ((size_t)b * 1024 + 512 + n * 64) * LCTX;
    const float* vim = g_qkv + ((size_t)b * 1536 + 1024 + n * 64) * 1024;
    uint32_t* outw = g_vb + (size_t)(b * HEADS + n) * 64 * (TPAD / 2);
    int d = tid >> 2, wq = (tid & 3) * 16;
#pragma unroll
    for (int j = 0; j < 16; j++) {
        int tp = ck * 64 + wq + j;
        int t = tp * 2;
        float v0 = 0.f, v1 = 0.f;
        if (t < LCTX) v0 = vck[d * LCTX + t];
        else if (t < TKV) v0 = vim[(size_t)d * 1024 + (t - LCTX)];
        if (t + 1 < LCTX) v1 = vck[d * LCTX + t + 1];
        else if (t + 1 < TKV) v1 = vim[(size_t)d * 1024 + (t + 1 - LCTX)];
        outw[(size_t)d * (TPAD / 2) + tp] = pkbf2(v0, v1);
    }
}

// ============================================================
// Flash attention v6 (validated R10): bf16 mma, packed KV,
// cp.async double buffer, C->A fragment identity for P.
// ============================================================
#define QW 36
#define KW 36
#define VW 68
#define FL6_WORDS (128*QW + 2*(128*KW + 64*VW))
#define FL6_SMEM (FL6_WORDS * 4)   // 90112 B

__global__ void __launch_bounds__(256, 2) flash6_kernel() {
    extern __shared__ uint32_t sm6[];
    uint32_t* qs = sm6;
    uint32_t* ktb[2] = { qs + 128 * QW, qs + 128 * QW + 128 * KW };
    uint32_t* vtb[2] = { ktb[1] + 128 * KW, ktb[1] + 128 * KW + 64 * VW };
    __nv_bfloat16* qsb = (__nv_bfloat16*)qs;

    int s0 = blockIdx.x * 128;
    int n = blockIdx.y, b = blockIdx.z;
    int bn = b * HEADS + n;
    int tid = threadIdx.x;
    int warp = tid >> 5, lane = tid & 31;
    int g = lane >> 2, tig = lane & 3;
    int q0w = warp * 16;

    uint32_t kts[2], vts[2];
    kts[0] = smaddr(ktb[0]);
    kts[1] = smaddr(ktb[1]);
    vts[0] = smaddr(vtb[0]);
    vts[1] = smaddr(vtb[1]);

    const uint32_t* gk = g_kb + (size_t)bn * TPAD * 32;
    const uint32_t* gv = g_vb + (size_t)bn * 64 * (TPAD / 2);

    int ktrow = tid >> 1, ktq = tid & 1;
    int vdrow = tid >> 2, vwq = tid & 3;

    const float* qbase = g_qkv + ((size_t)b * 1536 + n * 64) * 1024 + s0;
    {
        int s = tid & 127, hi = tid >> 7;
#pragma unroll
        for (int p = 0; p < 32; p++) {
            int d = p * 2 + hi;
            qsb[s * (QW * 2) + d] = __float2bfloat16_rn(qbase[(size_t)d * 1024 + s]);
        }
    }

#define ISSUE_CHUNK(c)                                                         \
    do {                                                                       \
        int _bb = (c) & 1;                                                     \
        const uint32_t* _gkc = gk + ((size_t)(c) * 128 + ktrow) * 32 + ktq * 16; \
        uint32_t _kd = kts[_bb] + (ktrow * KW + ktq * 16) * 4;                 \
        cpasync16(_kd + 0,  _gkc + 0);                                         \
        cpasync16(_kd + 16, _gkc + 4);                                         \
        cpasync16(_kd + 32, _gkc + 8);                                         \
        cpasync16(_kd + 48, _gkc + 12);                                        \
        const uint32_t* _gvc = gv + (size_t)vdrow * (TPAD / 2) + (c) * 64 + vwq * 16; \
        uint32_t _vd = vts[_bb] + (vdrow * VW + vwq * 16) * 4;                 \
        cpasync16(_vd + 0,  _gvc + 0);                                         \
        cpasync16(_vd + 16, _gvc + 4);                                         \
        cpasync16(_vd + 32, _gvc + 8);                                         \
        cpasync16(_vd + 48, _gvc + 12);                                        \
        asm volatile("cp.async.commit_group;");                                \
    } while (0)

    ISSUE_CHUNK(0);

    float m0r = -1e30f, m1r = -1e30f, l0 = 0.f, l1 = 0.f;
    float o[8][4];
#pragma unroll
    for (int nt = 0; nt < 8; nt++)
#pragma unroll
        for (int r = 0; r < 4; r++) o[nt][r] = 0.f;

    for (int c = 0; c < NCHB; c++) {
        if (c + 1 < NCHB) {
            ISSUE_CHUNK(c + 1);
            asm volatile("cp.async.wait_group 1;");
        } else {
            asm volatile("cp.async.wait_group 0;");
        }
        __syncthreads();

        uint32_t* kt = ktb[c & 1];
        uint32_t* vt = vtb[c & 1];
        int t0 = c * 128;

#pragma unroll
        for (int h = 0; h < 2; h++) {
            float sfr[8][4];
#pragma unroll
            for (int nt = 0; nt < 8; nt++)
#pragma unroll
                for (int r = 0; r < 4; r++) sfr[nt][r] = 0.f;

#pragma unroll
            for (int ks = 0; ks < 4; ks++) {
                int w0 = ks * 8 + tig;
                uint32_t a0 = qs[(q0w + g) * QW + w0];
                uint32_t a1 = qs[(q0w + g + 8) * QW + w0];
                uint32_t a2 = qs[(q0w + g) * QW + w0 + 4];
                uint32_t a3 = qs[(q0w + g + 8) * QW + w0 + 4];
#pragma unroll
                for (int nt = 0; nt < 8; nt++) {
                    int t = h * 64 + nt * 8 + g;
                    int bw = w0 ^ (nt & 3);
                    uint32_t b0 = kt[t * KW + bw];
                    uint32_t b1 = kt[t * KW + bw + 4];
                    MMA_BF16(sfr[nt][0], sfr[nt][1], sfr[nt][2], sfr[nt][3],
                             a0, a1, a2, a3, b0, b1);
                }
            }

            if (t0 + h * 64 + 64 > TKV) {
#pragma unroll
                for (int nt = 0; nt < 8; nt++) {
                    int t = t0 + h * 64 + nt * 8 + tig * 2;
                    if (t >= TKV) { sfr[nt][0] = -1e30f; sfr[nt][2] = -1e30f; }
                    if (t + 1 >= TKV) { sfr[nt][1] = -1e30f; sfr[nt][3] = -1e30f; }
                }
            }

            float mx0 = -1e30f, mx1 = -1e30f;
#pragma unroll
            for (int nt = 0; nt < 8; nt++) {
                mx0 = fmaxf(mx0, fmaxf(sfr[nt][0], sfr[nt][1]));
                mx1 = fmaxf(mx1, fmaxf(sfr[nt][2], sfr[nt][3]));
            }
            mx0 = fmaxf(mx0, __shfl_xor_sync(0xffffffffu, mx0, 1));
            mx0 = fmaxf(mx0, __shfl_xor_sync(0xffffffffu, mx0, 2));
            mx1 = fmaxf(mx1, __shfl_xor_sync(0xffffffffu, mx1, 1));
            mx1 = fmaxf(mx1, __shfl_xor_sync(0xffffffffu, mx1, 2));

            float mn0 = fmaxf(m0r, mx0), mn1 = fmaxf(m1r, mx1);
            float sc0 = __expf(m0r - mn0), sc1 = __expf(m1r - mn1);
            m0r = mn0; m1r = mn1;

            float sum0 = 0.f, sum1 = 0.f;
#pragma unroll
            for (int nt = 0; nt < 8; nt++) {
                sfr[nt][0] = __expf(sfr[nt][0] - mn0);
                sfr[nt][1] = __expf(sfr[nt][1] - mn0);
                sfr[nt][2] = __expf(sfr[nt][2] - mn1);
                sfr[nt][3] = __expf(sfr[nt][3] - mn1);
                sum0 += sfr[nt][0] + sfr[nt][1];
                sum1 += sfr[nt][2] + sfr[nt][3];
            }
            sum0 += __shfl_xor_sync(0xffffffffu, sum0, 1);
            sum0 += __shfl_xor_sync(0xffffffffu, sum0, 2);
            sum1 += __shfl_xor_sync(0xffffffffu, sum1, 1);
            sum1 += __shfl_xor_sync(0xffffffffu, sum1, 2);
            l0 = l0 * sc0 + sum0;
            l1 = l1 * sc1 + sum1;

#pragma unroll
            for (int nt = 0; nt < 8; nt++) {
                o[nt][0] *= sc0; o[nt][1] *= sc0;
                o[nt][2] *= sc1; o[nt][3] *= sc1;
            }

#pragma unroll
            for (int ks = 0; ks < 4; ks++) {
                uint32_t a0 = pkbf2(sfr[2 * ks][0], sfr[2 * ks][1]);
                uint32_t a1 = pkbf2(sfr[2 * ks][2], sfr[2 * ks][3]);
                uint32_t a2 = pkbf2(sfr[2 * ks + 1][0], sfr[2 * ks + 1][1]);
                uint32_t a3 = pkbf2(sfr[2 * ks + 1][2], sfr[2 * ks + 1][3]);
                int w0 = ks * 8 + tig;
#pragma unroll
                for (int nt = 0; nt < 8; nt++) {
                    int d = nt * 8 + g;
                    uint32_t b0 = vt[d * VW + h * 32 + w0];
                    uint32_t b1 = vt[d * VW + h * 32 + w0 + 4];
                    MMA_BF16(o[nt][0], o[nt][1], o[nt][2], o[nt][3],
                             a0, a1, a2, a3, b0, b1);
                }
            }
        }
        __syncthreads();
    }

    {
        float inv0 = 1.f / l0, inv1 = 1.f / l1;
        float* outp = g_attn + ((size_t)b * 512 + n * 64) * 1024 + s0;
        int sA = q0w + g, sB = q0w + g + 8;
#pragma unroll
        for (int nt = 0; nt < 8; nt++) {
            int d = nt * 8 + tig * 2;
            outp[(size_t)d * 1024 + sA] = o[nt][0] * inv0;
            outp[(size_t)(d + 1) * 1024 + sA] = o[nt][1] * inv0;
            outp[(size_t)d * 1024 + sB] = o[nt][2] * inv1;
            outp[(size_t)(d + 1) * 1024 + sB] = o[nt][3] * inv1;
        }
    }
}

// ============================================================
extern "C" void kernel_launch(void* const* d_in, const int* in_sizes, int n_in,
                              void* d_out, int out_size) {
    const float* x       = (const float*)d_in[0];
    const float* context = (const float*)d_in[1];
    const float* gamma   = (const float*)d_in[2];
    const float* beta    = (const float*)d_in[3];
    const float* qkv_w   = (const float*)d_in[4];
    const float* qkv_b   = (const float*)d_in[5];
    const float* ckv_w   = (const float*)d_in[6];
    const float* ckv_b   = (const float*)d_in[7];
    const float* proj_w  = (const float*)d_in[8];
    const float* proj_b  = (const float*)d_in[9];
    float* out = (float*)d_out;

    float *xn_p, *qkv_p, *attn_p;
    cudaGetSymbolAddress((void**)&xn_p, g_xn);
    cudaGetSymbolAddress((void**)&qkv_p, g_qkv);
    cudaGetSymbolAddress((void**)&attn_p, g_attn);

    // 1. GroupNorm
    gn_kernel<<<BATCH * 32, 256>>>(x, gamma, beta, xn_p);

    // 2. QKV projection (bf16 tensor cores)
    gemm_bf16<<<dim3(8, 12, BATCH), 256>>>(qkv_w, qkv_b, xn_p, nullptr, qkv_p, 1536, 1024, 512);

    // 3. Context KV projection
    ckv_kernel<<<dim3(16, BATCH), 256>>>(context, ckv_w, ckv_b);

    // 4a. Pack K/V to bf16
    packk_kernel<<<dim3(NCHB * 2, HEADS, BATCH), 256>>>();
    packv_kernel<<<dim3(NCHB, HEADS, BATCH), 256>>>();

    // 4b. Flash attention v6
    cudaFuncSetAttribute(flash6_kernel, cudaFuncAttributeMaxDynamicSharedMemorySize, FL6_SMEM);
    flash6_kernel<<<dim3(8, HEADS, BATCH), 256, FL6_SMEM>>>();

    // 5. Output projection + bias + residual (tf32 tensor cores)
    gemm_tf32<<<dim3(8, 4, BATCH), 256>>>(proj_w, proj_b, attn_p, x, out, 512, 1024, 512);
}

// round 12
// speedup vs baseline: 3.8573x; 1.1227x over previous
#include <cuda_runtime.h>
#include <cuda_bf16.h>
#include <math.h>
#include <stdint.h>

#define BATCH 8
#define DIMC 512
#define HW 1024
#define HEADS 8
#define HD 64
#define LCTX 77
#define CTXD 768
#define TKV 1101
#define TPAD 1152     // padded KV length (9 chunks of 128)
#define NCHB 9

// ---- scratch (device globals) ----
__device__ float g_xn[BATCH * DIMC * HW];
__device__ float g_qkv[BATCH * 3 * DIMC * HW];
__device__ float g_ckv[BATCH * 2 * DIMC * LCTX];
__device__ float g_attn[BATCH * DIMC * HW];
__device__ uint32_t g_kb[BATCH * HEADS * TPAD * 32];
__device__ uint32_t g_vb[BATCH * HEADS * 64 * (TPAD / 2)];

__device__ __forceinline__ uint32_t pkbf2(float lo, float hi) {
    __nv_bfloat162 v = __floats2bfloat162_rn(lo, hi);
    return *reinterpret_cast<uint32_t*>(&v);
}
__device__ __forceinline__ void cpasync16(uint32_t s, const void* g) {
    asm volatile("cp.async.cg.shared.global [%0], [%1], 16;" :: "r"(s), "l"(g));
}
__device__ __forceinline__ uint32_t smaddr(const void* p) {
    return (uint32_t)__cvta_generic_to_shared(p);
}

#define MMA_BF16(c0,c1,c2,c3,a0,a1,a2,a3,b0,b1)                               \
    asm volatile(                                                              \
        "mma.sync.aligned.m16n8k16.row.col.f32.bf16.bf16.f32 "                 \
        "{%0,%1,%2,%3}, {%4,%5,%6,%7}, {%8,%9}, {%0,%1,%2,%3};"                \
        : "+f"(c0), "+f"(c1), "+f"(c2), "+f"(c3)                               \
        : "r"(a0), "r"(a1), "r"(a2), "r"(a3), "r"(b0), "r"(b1))

// ============================================================
// GroupNorm
// ============================================================
__global__ void gn_kernel(const float* __restrict__ x, const float* __restrict__ gamma,
                          const float* __restrict__ beta, float* __restrict__ xn) {
    __shared__ float ssum[256], ssq[256];
    int bg = blockIdx.x;
    int b = bg >> 5, g = bg & 31;
    const float* xp = x + ((size_t)b * DIMC + g * 16) * HW;
    float* xo = xn + ((size_t)b * DIMC + g * 16) * HW;
    int tid = threadIdx.x;

    float s = 0.f, sq = 0.f;
#pragma unroll
    for (int i = 0; i < 64; i++) {
        float v = xp[tid + i * 256];
        s += v; sq += v * v;
    }
    ssum[tid] = s; ssq[tid] = sq;
    __syncthreads();
    for (int off = 128; off > 0; off >>= 1) {
        if (tid < off) { ssum[tid] += ssum[tid + off]; ssq[tid] += ssq[tid + off]; }
        __syncthreads();
    }
    float mu = ssum[0] * (1.f / 16384.f);
    float var = ssq[0] * (1.f / 16384.f) - mu * mu;
    float inv = rsqrtf(var + 1e-5f);
#pragma unroll
    for (int i = 0; i < 64; i++) {
        int idx = tid + i * 256;
        int c = g * 16 + (idx >> 10);
        xo[idx] = (xp[idx] - mu) * inv * gamma[c] + beta[c];
    }
}

// ============================================================
// bf16 tensor-core GEMM (m16n8k16): C = W X + bias (+res)  [validated R11]
// ============================================================
__global__ void __launch_bounds__(256) gemm_bf16(
        const float* __restrict__ W, const float* __restrict__ bias,
        const float* __restrict__ X, const float* __restrict__ res,
        float* __restrict__ C, int M, int N, int K) {
    __shared__ uint32_t wsb[128 * 20];
    __shared__ __nv_bfloat16 xsb[32][136];

    int b = blockIdx.z;
    int m0 = blockIdx.y * 128, n0 = blockIdx.x * 128;
    const float* Xb = X + (size_t)b * K * N;
    int tid = threadIdx.x;
    int warp = tid >> 5, lane = tid & 31;
    int warpM = warp >> 2, warpN = warp & 3;
    int g = lane >> 2, tig = lane & 3;

    float c[4][4][4];
#pragma unroll
    for (int mt = 0; mt < 4; mt++)
#pragma unroll
        for (int nt = 0; nt < 4; nt++)
#pragma unroll
            for (int r = 0; r < 4; r++) c[mt][nt][r] = 0.f;

    int wrow = tid >> 1, wseg = tid & 1;
    int xk = tid >> 3, xn16 = (tid & 7) * 16;

    for (int k0 = 0; k0 < K; k0 += 32) {
        {
            const float* wp = W + (size_t)(m0 + wrow) * K + k0 + wseg * 16;
            float4 f0 = *(const float4*)(wp + 0);
            float4 f1 = *(const float4*)(wp + 4);
            float4 f2 = *(const float4*)(wp + 8);
            float4 f3 = *(const float4*)(wp + 12);
            uint32_t* wd = wsb + wrow * 20 + wseg * 8;
            wd[0] = pkbf2(f0.x, f0.y); wd[1] = pkbf2(f0.z, f0.w);
            wd[2] = pkbf2(f1.x, f1.y); wd[3] = pkbf2(f1.z, f1.w);
            wd[4] = pkbf2(f2.x, f2.y); wd[5] = pkbf2(f2.z, f2.w);
            wd[6] = pkbf2(f3.x, f3.y); wd[7] = pkbf2(f3.z, f3.w);
        }
        {
            const float* xp = Xb + (size_t)(k0 + xk) * N + n0 + xn16;
            float4 f0 = *(const float4*)(xp + 0);
            float4 f1 = *(const float4*)(xp + 4);
            float4 f2 = *(const float4*)(xp + 8);
            float4 f3 = *(const float4*)(xp + 12);
            uint32_t* xd = (uint32_t*)&xsb[xk][xn16];
            xd[0] = pkbf2(f0.x, f0.y); xd[1] = pkbf2(f0.z, f0.w);
            xd[2] = pkbf2(f1.x, f1.y); xd[3] = pkbf2(f1.z, f1.w);
            xd[4] = pkbf2(f2.x, f2.y); xd[5] = pkbf2(f2.z, f2.w);
            xd[6] = pkbf2(f3.x, f3.y); xd[7] = pkbf2(f3.z, f3.w);
        }
        __syncthreads();

#pragma unroll
        for (int ks = 0; ks < 2; ks++) {
            uint32_t bfr[4][2];
#pragma unroll
            for (int nt = 0; nt < 4; nt++) {
                int no = warpN * 32 + nt * 8;
                uint32_t addr = smaddr(&xsb[ks * 16 + (lane & 15)][no]);
                asm volatile(
                    "ldmatrix.sync.aligned.m8n8.x2.trans.shared.b16 {%0,%1}, [%2];"
                    : "=r"(bfr[nt][0]), "=r"(bfr[nt][1]) : "r"(addr));
            }
#pragma unroll
            for (int mt = 0; mt < 4; mt++) {
                int mo = warpM * 64 + mt * 16;
                uint32_t a0 = wsb[(mo + g) * 20 + ks * 8 + tig];
                uint32_t a1 = wsb[(mo + g + 8) * 20 + ks * 8 + tig];
                uint32_t a2 = wsb[(mo + g) * 20 + ks * 8 + tig + 4];
                uint32_t a3 = wsb[(mo + g + 8) * 20 + ks * 8 + tig + 4];
#pragma unroll
                for (int nt = 0; nt < 4; nt++)
                    MMA_BF16(c[mt][nt][0], c[mt][nt][1], c[mt][nt][2], c[mt][nt][3],
                             a0, a1, a2, a3, bfr[nt][0], bfr[nt][1]);
            }
        }
        __syncthreads();
    }

#pragma unroll
    for (int mt = 0; mt < 4; mt++) {
#pragma unroll
        for (int half = 0; half < 2; half++) {
            int m = m0 + warpM * 64 + mt * 16 + g + half * 8;
            float bv = bias[m];
            size_t rowoff = ((size_t)b * M + m) * N;
#pragma unroll
            for (int nt = 0; nt < 4; nt++) {
                int n = n0 + warpN * 32 + nt * 8 + tig * 2;
                float v0 = c[mt][nt][half * 2 + 0] + bv;
                float v1 = c[mt][nt][half * 2 + 1] + bv;
                if (res) {
                    v0 += res[rowoff + n];
                    v1 += res[rowoff + n + 1];
                }
                C[rowoff + n] = v0;
                C[rowoff + n + 1] = v1;
            }
        }
    }
}

// ============================================================
// ckv GEMM, bf16 mma: g_ckv[b][o][l] = sum_c W[o][c]*ctx[b][l][c] + b[o]
// m=o (128-tile), n=l (80 padded, 10 n8 tiles), k=c (768, BK=32).
// Both operands k-contiguous -> same pair-word staging as wsb.
// grid (8, BATCH), 256 thr, warp = 16 m rows x 80 n.
// ============================================================
__global__ void __launch_bounds__(256) ckv_bf16(
        const float* __restrict__ ctx, const float* __restrict__ W,
        const float* __restrict__ bias) {
    __shared__ uint32_t wsb[128 * 20];   // W pairs [m][20w]
    __shared__ uint32_t csb[80 * 20];    // ctx pairs [l][20w]

    int m0 = blockIdx.x * 128, b = blockIdx.y;
    int tid = threadIdx.x;
    int warp = tid >> 5, lane = tid & 31;
    int g = lane >> 2, tig = lane & 3;
    int mo = warp * 16;

    float c[10][4];
#pragma unroll
    for (int nt = 0; nt < 10; nt++)
#pragma unroll
        for (int r = 0; r < 4; r++) c[nt][r] = 0.f;

    int wrow = tid >> 1, wseg = tid & 1;

    for (int k0 = 0; k0 < CTXD; k0 += 32) {
        // W[m0+wrow][k0+wseg*16 ..16)
        {
            const float* wp = W + (size_t)(m0 + wrow) * CTXD + k0 + wseg * 16;
            float4 f0 = *(const float4*)(wp + 0);
            float4 f1 = *(const float4*)(wp + 4);
            float4 f2 = *(const float4*)(wp + 8);
            float4 f3 = *(const float4*)(wp + 12);
            uint32_t* wd = wsb + wrow * 20 + wseg * 8;
            wd[0] = pkbf2(f0.x, f0.y); wd[1] = pkbf2(f0.z, f0.w);
            wd[2] = pkbf2(f1.x, f1.y); wd[3] = pkbf2(f1.z, f1.w);
            wd[4] = pkbf2(f2.x, f2.y); wd[5] = pkbf2(f2.z, f2.w);
            wd[6] = pkbf2(f3.x, f3.y); wd[7] = pkbf2(f3.z, f3.w);
        }
        // ctx[b][l][k0+cseg*16 ..16), l < 77 (pad zeros)
        if (tid < 160) {
            int l = tid >> 1, cseg = tid & 1;
            uint32_t* cd = csb + l * 20 + cseg * 8;
            if (l < LCTX) {
                const float* cp = ctx + ((size_t)b * LCTX + l) * CTXD + k0 + cseg * 16;
                float4 f0 = *(const float4*)(cp + 0);
                float4 f1 = *(const float4*)(cp + 4);
                float4 f2 = *(const float4*)(cp + 8);
                float4 f3 = *(const float4*)(cp + 12);
                cd[0] = pkbf2(f0.x, f0.y); cd[1] = pkbf2(f0.z, f0.w);
                cd[2] = pkbf2(f1.x, f1.y); cd[3] = pkbf2(f1.z, f1.w);
                cd[4] = pkbf2(f2.x, f2.y); cd[5] = pkbf2(f2.z, f2.w);
                cd[6] = pkbf2(f3.x, f3.y); cd[7] = pkbf2(f3.z, f3.w);
            } else {
#pragma unroll
                for (int j = 0; j < 8; j++) cd[j] = 0;
            }
        }
        __syncthreads();

#pragma unroll
        for (int ks = 0; ks < 2; ks++) {
            int w0 = ks * 8 + tig;
            uint32_t a0 = wsb[(mo + g) * 20 + w0];
            uint32_t a1 = wsb[(mo + g + 8) * 20 + w0];
            uint32_t a2 = wsb[(mo + g) * 20 + w0 + 4];
            uint32_t a3 = wsb[(mo + g + 8) * 20 + w0 + 4];
#pragma unroll
            for (int nt = 0; nt < 10; nt++) {
                uint32_t b0 = csb[(nt * 8 + g) * 20 + w0];
                uint32_t b1 = csb[(nt * 8 + g) * 20 + w0 + 4];
                MMA_BF16(c[nt][0], c[nt][1], c[nt][2], c[nt][3],
                         a0, a1, a2, a3, b0, b1);
            }
        }
        __syncthreads();
    }

    // store: C[b][o][l], o = m0+mo+g(+8), l = nt*8+tig*2(+1), l<77
#pragma unroll
    for (int half = 0; half < 2; half++) {
        int o = m0 + mo + g + half * 8;
        float bv = bias[o];
        float* outp = g_ckv + ((size_t)b * 1024 + o) * LCTX;
#pragma unroll
        for (int nt = 0; nt < 10; nt++) {
            int l = nt * 8 + tig * 2;
            if (l < LCTX)     outp[l]     = c[nt][half * 2 + 0] + bv;
            if (l + 1 < LCTX) outp[l + 1] = c[nt][half * 2 + 1] + bv;
        }
    }
}

// ============================================================
// packk: g_kb[bn][t][32w] bf16, swizzled, 0.125 logit scale folded.
// ============================================================
__global__ void packk_kernel() {
    __shared__ unsigned short ks[64][66];
    int tt = blockIdx.x, n = blockIdx.y, b = blockIdx.z;
    int tid = threadIdx.x;
    const float* kck = g_ckv + ((size_t)b * 1024 + n * 64) * LCTX;
    const float* kim = g_qkv + ((size_t)b * 1536 + 512 + n * 64) * 1024;
    int tl = tid & 63, dh = tid >> 6;
    int t0 = tt * 64;
#pragma unroll
    for (int p = 0; p < 16; p++) {
        int d = p * 4 + dh;
        int gt = t0 + tl;
        float kv = 0.f;
        if (gt < LCTX) kv = kck[d * LCTX + gt];
        else if (gt < TKV) kv = kim[(size_t)d * 1024 + (gt - LCTX)];
        __nv_bfloat16 h = __float2bfloat16_rn(kv * 0.125f);
        ks[d][tl] = *reinterpret_cast<unsigned short*>(&h);
    }
    __syncthreads();

    int row = tid >> 2, q = tid & 3;
    int t = t0 + row;
    int s = (t >> 3) & 3;
    uint32_t* outw = g_kb + ((size_t)(b * HEADS + n) * TPAD + t) * 32;
#pragma unroll
    for (int half = 0; half < 2; half++) {
        int w0 = q * 4 + half * 16;
        uint32_t wv[4];
#pragma unroll
        for (int j = 0; j < 4; j++) {
            int p = (w0 + j) ^ s;
            wv[j] = (uint32_t)ks[2 * p][row] | ((uint32_t)ks[2 * p + 1][row] << 16);
        }
        uint4 v = {wv[0], wv[1], wv[2], wv[3]};
        *(uint4*)(outw + w0) = v;
    }
}

// ============================================================
// packv: g_vb[bn][d][576w] bf16 ([d][t] pairs). grid (9, HEADS, BATCH).
// ============================================================
__global__ void packv_kernel() {
    int ck = blockIdx.x, n = blockIdx.y, b = blockIdx.z;
    int tid = threadIdx.x;
    const float* vck = g_ckv + ((size_t)b * 1024 + 512 + n * 64) * LCTX;
    const float* vim = g_qkv + ((size_t)b * 1536 + 1024 + n * 64) * 1024;
    uint32_t* outw = g_vb + (size_t)(b * HEADS + n) * 64 * (TPAD / 2);
    int d = tid >> 2, wq = (tid & 3) * 16;
#pragma unroll
    for (int j = 0; j < 16; j++) {
        int tp = ck * 64 + wq + j;
        int t = tp * 2;
        float v0 = 0.f, v1 = 0.f;
        if (t < LCTX) v0 = vck[d * LCTX + t];
        else if (t < TKV) v0 = vim[(size_t)d * 1024 + (t - LCTX)];
        if (t + 1 < LCTX) v1 = vck[d * LCTX + t + 1];
        else if (t + 1 < TKV) v1 = vim[(size_t)d * 1024 + (t + 1 - LCTX)];
        outw[(size_t)d * (TPAD / 2) + tp] = pkbf2(v0, v1);
    }
}

// ============================================================
// Flash attention v6 (validated R10)
// ============================================================
#define QW 36
#define KW 36
#define VW 68
#define FL6_WORDS (128*QW + 2*(128*KW + 64*VW))
#define FL6_SMEM (FL6_WORDS * 4)   // 90112 B

__global__ void __launch_bounds__(256, 2) flash6_kernel() {
    extern __shared__ uint32_t sm6[];
    uint32_t* qs = sm6;
    uint32_t* ktb[2] = { qs + 128 * QW, qs + 128 * QW + 128 * KW };
    uint32_t* vtb[2] = { ktb[1] + 128 * KW, ktb[1] + 128 * KW + 64 * VW };
    __nv_bfloat16* qsb = (__nv_bfloat16*)qs;

    int s0 = blockIdx.x * 128;
    int n = blockIdx.y, b = blockIdx.z;
    int bn = b * HEADS + n;
    int tid = threadIdx.x;
    int warp = tid >> 5, lane = tid & 31;
    int g = lane >> 2, tig = lane & 3;
    int q0w = warp * 16;

    uint32_t kts[2], vts[2];
    kts[0] = smaddr(ktb[0]);
    kts[1] = smaddr(ktb[1]);
    vts[0] = smaddr(vtb[0]);
    vts[1] = smaddr(vtb[1]);

    const uint32_t* gk = g_kb + (size_t)bn * TPAD * 32;
    const uint32_t* gv = g_vb + (size_t)bn * 64 * (TPAD / 2);

    int ktrow = tid >> 1, ktq = tid & 1;
    int vdrow = tid >> 2, vwq = tid & 3;

    const float* qbase = g_qkv + ((size_t)b * 1536 + n * 64) * 1024 + s0;
    {
        int s = tid & 127, hi = tid >> 7;
#pragma unroll
        for (int p = 0; p < 32; p++) {
            int d = p * 2 + hi;
            qsb[s * (QW * 2) + d] = __float2bfloat16_rn(qbase[(size_t)d * 1024 + s]);
        }
    }

#define ISSUE_CHUNK(c)                                                         \
    do {                                                                       \
        int _bb = (c) & 1;                                                     \
        const uint32_t* _gkc = gk + ((size_t)(c) * 128 + ktrow) * 32 + ktq * 16; \
        uint32_t _kd = kts[_bb] + (ktrow * KW + ktq * 16) * 4;                 \
        cpasync16(_kd + 0,  _gkc + 0);                                         \
        cpasync16(_kd + 16, _gkc + 4);                                         \
        cpasync16(_kd + 32, _gkc + 8);                                         \
        cpasync16(_kd + 48, _gkc + 12);                                        \
        const uint32_t* _gvc = gv + (size_t)vdrow * (TPAD / 2) + (c) * 64 + vwq * 16; \
        uint32_t _vd = vts[_bb] + (vdrow * VW + vwq * 16) * 4;                 \
        cpasync16(_vd + 0,  _gvc + 0);                                         \
        cpasync16(_vd + 16, _gvc + 4);                                         \
        cpasync16(_vd + 32, _gvc + 8);                                         \
        cpasync16(_vd + 48, _gvc + 12);                                        \
        asm volatile("cp.async.commit_group;");                                \
    } while (0)

    ISSUE_CHUNK(0);

    float m0r = -1e30f, m1r = -1e30f, l0 = 0.f, l1 = 0.f;
    float o[8][4];
#pragma unroll
    for (int nt = 0; nt < 8; nt++)
#pragma unroll
        for (int r = 0; r < 4; r++) o[nt][r] = 0.f;

    for (int c = 0; c < NCHB; c++) {
        if (c + 1 < NCHB) {
            ISSUE_CHUNK(c + 1);
            asm volatile("cp.async.wait_group 1;");
        } else {
            asm volatile("cp.async.wait_group 0;");
        }
        __syncthreads();

        uint32_t* kt = ktb[c & 1];
        uint32_t* vt = vtb[c & 1];
        int t0 = c * 128;

#pragma unroll
        for (int h = 0; h < 2; h++) {
            float sfr[8][4];
#pragma unroll
            for (int nt = 0; nt < 8; nt++)
#pragma unroll
                for (int r = 0; r < 4; r++) sfr[nt][r] = 0.f;

#pragma unroll
            for (int ks = 0; ks < 4; ks++) {
                int w0 = ks * 8 + tig;
                uint32_t a0 = qs[(q0w + g) * QW + w0];
                uint32_t a1 = qs[(q0w + g + 8) * QW + w0];
                uint32_t a2 = qs[(q0w + g) * QW + w0 + 4];
                uint32_t a3 = qs[(q0w + g + 8) * QW + w0 + 4];
#pragma unroll
                for (int nt = 0; nt < 8; nt++) {
                    int t = h * 64 + nt * 8 + g;
                    int bw = w0 ^ (nt & 3);
                    uint32_t b0 = kt[t * KW + bw];
                    uint32_t b1 = kt[t * KW + bw + 4];
                    MMA_BF16(sfr[nt][0], sfr[nt][1], sfr[nt][2], sfr[nt][3],
                             a0, a1, a2, a3, b0, b1);
                }
            }

            if (t0 + h * 64 + 64 > TKV) {
#pragma unroll
                for (int nt = 0; nt < 8; nt++) {
                    int t = t0 + h * 64 + nt * 8 + tig * 2;
                    if (t >= TKV) { sfr[nt][0] = -1e30f; sfr[nt][2] = -1e30f; }
                    if (t + 1 >= TKV) { sfr[nt][1] = -1e30f; sfr[nt][3] = -1e30f; }
                }
            }

            float mx0 = -1e30f, mx1 = -1e30f;
#pragma unroll
            for (int nt = 0; nt < 8; nt++) {
                mx0 = fmaxf(mx0, fmaxf(sfr[nt][0], sfr[nt][1]));
                mx1 = fmaxf(mx1, fmaxf(sfr[nt][2], sfr[nt][3]));
            }
            mx0 = fmaxf(mx0, __shfl_xor_sync(0xffffffffu, mx0, 1));
            mx0 = fmaxf(mx0, __shfl_xor_sync(0xffffffffu, mx0, 2));
            mx1 = fmaxf(mx1, __shfl_xor_sync(0xffffffffu, mx1, 1));
            mx1 = fmaxf(mx1, __shfl_xor_sync(0xffffffffu, mx1, 2));

            float mn0 = fmaxf(m0r, mx0), mn1 = fmaxf(m1r, mx1);
            float sc0 = __expf(m0r - mn0), sc1 = __expf(m1r - mn1);
            m0r = mn0; m1r = mn1;

            float sum0 = 0.f, sum1 = 0.f;
#pragma unroll
            for (int nt = 0; nt < 8; nt++) {
                sfr[nt][0] = __expf(sfr[nt][0] - mn0);
                sfr[nt][1] = __expf(sfr[nt][1] - mn0);
                sfr[nt][2] = __expf(sfr[nt][2] - mn1);
                sfr[nt][3] = __expf(sfr[nt][3] - mn1);
                sum0 += sfr[nt][0] + sfr[nt][1];
                sum1 += sfr[nt][2] + sfr[nt][3];
            }
            sum0 += __shfl_xor_sync(0xffffffffu, sum0, 1);
            sum0 += __shfl_xor_sync(0xffffffffu, sum0, 2);
            sum1 += __shfl_xor_sync(0xffffffffu, sum1, 1);
            sum1 += __shfl_xor_sync(0xffffffffu, sum1, 2);
            l0 = l0 * sc0 + sum0;
            l1 = l1 * sc1 + sum1;

#pragma unroll
            for (int nt = 0; nt < 8; nt++) {
                o[nt][0] *= sc0; o[nt][1] *= sc0;
                o[nt][2] *= sc1; o[nt][3] *= sc1;
            }

#pragma unroll
            for (int ks = 0; ks < 4; ks++) {
                uint32_t a0 = pkbf2(sfr[2 * ks][0], sfr[2 * ks][1]);
                uint32_t a1 = pkbf2(sfr[2 * ks][2], sfr[2 * ks][3]);
                uint32_t a2 = pkbf2(sfr[2 * ks + 1][0], sfr[2 * ks + 1][1]);
                uint32_t a3 = pkbf2(sfr[2 * ks + 1][2], sfr[2 * ks + 1][3]);
                int w0 = ks * 8 + tig;
#pragma unroll
                for (int nt = 0; nt < 8; nt++) {
                    int d = nt * 8 + g;
                    uint32_t b0 = vt[d * VW + h * 32 + w0];
                    uint32_t b1 = vt[d * VW + h * 32 + w0 + 4];
                    MMA_BF16(o[nt][0], o[nt][1], o[nt][2], o[nt][3],
                             a0, a1, a2, a3, b0, b1);
                }
            }
        }
        __syncthreads();
    }

    {
        float inv0 = 1.f / l0, inv1 = 1.f / l1;
        float* outp = g_attn + ((size_t)b * 512 + n * 64) * 1024 + s0;
        int sA = q0w + g, sB = q0w + g + 8;
#pragma unroll
        for (int nt = 0; nt < 8; nt++) {
            int d = nt * 8 + tig * 2;
            outp[(size_t)d * 1024 + sA] = o[nt][0] * inv0;
            outp[(size_t)(d + 1) * 1024 + sA] = o[nt][1] * inv0;
            outp[(size_t)d * 1024 + sB] = o[nt][2] * inv1;
            outp[(size_t)(d + 1) * 1024 + sB] = o[nt][3] * inv1;
        }
    }
}

// ============================================================
extern "C" void kernel_launch(void* const* d_in, const int* in_sizes, int n_in,
                              void* d_out, int out_size) {
    const float* x       = (const float*)d_in[0];
    const float* context = (const float*)d_in[1];
    const float* gamma   = (const float*)d_in[2];
    const float* beta    = (const float*)d_in[3];
    const float* qkv_w   = (const float*)d_in[4];
    const float* qkv_b   = (const float*)d_in[5];
    const float* ckv_w   = (const float*)d_in[6];
    const float* ckv_b   = (const float*)d_in[7];
    const float* proj_w  = (const float*)d_in[8];
    const float* proj_b  = (const float*)d_in[9];
    float* out = (float*)d_out;

    float *xn_p, *qkv_p, *attn_p;
    cudaGetSymbolAddress((void**)&xn_p, g_xn);
    cudaGetSymbolAddress((void**)&qkv_p, g_qkv);
    cudaGetSymbolAddress((void**)&attn_p, g_attn);

    // 1. GroupNorm
    gn_kernel<<<BATCH * 32, 256>>>(x, gamma, beta, xn_p);

    // 2. QKV projection (bf16 tensor cores)
    gemm_bf16<<<dim3(8, 12, BATCH), 256>>>(qkv_w, qkv_b, xn_p, nullptr, qkv_p, 1536, 1024, 512);

    // 3. Context KV projection (bf16 tensor cores)
    ckv_bf16<<<dim3(8, BATCH), 256>>>(context, ckv_w, ckv_b);

    // 4a. Pack K/V to bf16
    packk_kernel<<<dim3(NCHB * 2, HEADS, BATCH), 256>>>();
    packv_kernel<<<dim3(NCHB, HEADS, BATCH), 256>>>();

    // 4b. Flash attention v6
    cudaFuncSetAttribute(flash6_kernel, cudaFuncAttributeMaxDynamicSharedMemorySize, FL6_SMEM);
    flash6_kernel<<<dim3(8, HEADS, BATCH), 256, FL6_SMEM>>>();

    // 5. Output projection + bias + residual (bf16 tensor cores)
    gemm_bf16<<<dim3(8, 4, BATCH), 256>>>(proj_w, proj_b, attn_p, x, out, 512, 1024, 512);
}

// round 13
// speedup vs baseline: 3.9569x; 1.0258x over previous
#include <cuda_runtime.h>
#include <cuda_bf16.h>
#include <math.h>
#include <stdint.h>

#define BATCH 8
#define DIMC 512
#define HW 1024
#define HEADS 8
#define HD 64
#define LCTX 77
#define CTXD 768
#define TKV 1101
#define TPAD 1152     // padded KV length (9 chunks of 128)
#define NCHB 9

// ---- scratch (device globals) ----
__device__ float g_xn[BATCH * DIMC * HW];
__device__ float g_qkv[BATCH * 3 * DIMC * HW];
__device__ float g_ckv[BATCH * 2 * DIMC * LCTX];
__device__ float g_attn[BATCH * DIMC * HW];
__device__ uint32_t g_kb[BATCH * HEADS * TPAD * 32];
__device__ uint32_t g_vb[BATCH * HEADS * 64 * (TPAD / 2)];

__device__ __forceinline__ uint32_t pkbf2(float lo, float hi) {
    __nv_bfloat162 v = __floats2bfloat162_rn(lo, hi);
    return *reinterpret_cast<uint32_t*>(&v);
}
__device__ __forceinline__ void cpasync16(uint32_t s, const void* g) {
    asm volatile("cp.async.cg.shared.global [%0], [%1], 16;" :: "r"(s), "l"(g));
}
__device__ __forceinline__ uint32_t smaddr(const void* p) {
    return (uint32_t)__cvta_generic_to_shared(p);
}

#define MMA_BF16(c0,c1,c2,c3,a0,a1,a2,a3,b0,b1)                               \
    asm volatile(                                                              \
        "mma.sync.aligned.m16n8k16.row.col.f32.bf16.bf16.f32 "                 \
        "{%0,%1,%2,%3}, {%4,%5,%6,%7}, {%8,%9}, {%0,%1,%2,%3};"                \
        : "+f"(c0), "+f"(c1), "+f"(c2), "+f"(c3)                               \
        : "r"(a0), "r"(a1), "r"(a2), "r"(a3), "r"(b0), "r"(b1))

// ============================================================
// GroupNorm
// ============================================================
__global__ void gn_kernel(const float* __restrict__ x, const float* __restrict__ gamma,
                          const float* __restrict__ beta, float* __restrict__ xn) {
    __shared__ float ssum[256], ssq[256];
    int bg = blockIdx.x;
    int b = bg >> 5, g = bg & 31;
    const float* xp = x + ((size_t)b * DIMC + g * 16) * HW;
    float* xo = xn + ((size_t)b * DIMC + g * 16) * HW;
    int tid = threadIdx.x;

    float s = 0.f, sq = 0.f;
#pragma unroll
    for (int i = 0; i < 64; i++) {
        float v = xp[tid + i * 256];
        s += v; sq += v * v;
    }
    ssum[tid] = s; ssq[tid] = sq;
    __syncthreads();
    for (int off = 128; off > 0; off >>= 1) {
        if (tid < off) { ssum[tid] += ssum[tid + off]; ssq[tid] += ssq[tid + off]; }
        __syncthreads();
    }
    float mu = ssum[0] * (1.f / 16384.f);
    float var = ssq[0] * (1.f / 16384.f) - mu * mu;
    float inv = rsqrtf(var + 1e-5f);
#pragma unroll
    for (int i = 0; i < 64; i++) {
        int idx = tid + i * 256;
        int c = g * 16 + (idx >> 10);
        xo[idx] = (xp[idx] - mu) * inv * gamma[c] + beta[c];
    }
}

// ============================================================
// bf16 tensor-core GEMM (m16n8k16): C = W X + bias (+res)  [validated R11]
// ============================================================
__global__ void __launch_bounds__(256) gemm_bf16(
        const float* __restrict__ W, const float* __restrict__ bias,
        const float* __restrict__ X, const float* __restrict__ res,
        float* __restrict__ C, int M, int N, int K) {
    __shared__ uint32_t wsb[128 * 20];
    __shared__ __nv_bfloat16 xsb[32][136];

    int b = blockIdx.z;
    int m0 = blockIdx.y * 128, n0 = blockIdx.x * 128;
    const float* Xb = X + (size_t)b * K * N;
    int tid = threadIdx.x;
    int warp = tid >> 5, lane = tid & 31;
    int warpM = warp >> 2, warpN = warp & 3;
    int g = lane >> 2, tig = lane & 3;

    float c[4][4][4];
#pragma unroll
    for (int mt = 0; mt < 4; mt++)
#pragma unroll
        for (int nt = 0; nt < 4; nt++)
#pragma unroll
            for (int r = 0; r < 4; r++) c[mt][nt][r] = 0.f;

    int wrow = tid >> 1, wseg = tid & 1;
    int xk = tid >> 3, xn16 = (tid & 7) * 16;

    for (int k0 = 0; k0 < K; k0 += 32) {
        {
            const float* wp = W + (size_t)(m0 + wrow) * K + k0 + wseg * 16;
            float4 f0 = *(const float4*)(wp + 0);
            float4 f1 = *(const float4*)(wp + 4);
            float4 f2 = *(const float4*)(wp + 8);
            float4 f3 = *(const float4*)(wp + 12);
            uint32_t* wd = wsb + wrow * 20 + wseg * 8;
            wd[0] = pkbf2(f0.x, f0.y); wd[1] = pkbf2(f0.z, f0.w);
            wd[2] = pkbf2(f1.x, f1.y); wd[3] = pkbf2(f1.z, f1.w);
            wd[4] = pkbf2(f2.x, f2.y); wd[5] = pkbf2(f2.z, f2.w);
            wd[6] = pkbf2(f3.x, f3.y); wd[7] = pkbf2(f3.z, f3.w);
        }
        {
            const float* xp = Xb + (size_t)(k0 + xk) * N + n0 + xn16;
            float4 f0 = *(const float4*)(xp + 0);
            float4 f1 = *(const float4*)(xp + 4);
            float4 f2 = *(const float4*)(xp + 8);
            float4 f3 = *(const float4*)(xp + 12);
            uint32_t* xd = (uint32_t*)&xsb[xk][xn16];
            xd[0] = pkbf2(f0.x, f0.y); xd[1] = pkbf2(f0.z, f0.w);
            xd[2] = pkbf2(f1.x, f1.y); xd[3] = pkbf2(f1.z, f1.w);
            xd[4] = pkbf2(f2.x, f2.y); xd[5] = pkbf2(f2.z, f2.w);
            xd[6] = pkbf2(f3.x, f3.y); xd[7] = pkbf2(f3.z, f3.w);
        }
        __syncthreads();

#pragma unroll
        for (int ks = 0; ks < 2; ks++) {
            uint32_t bfr[4][2];
#pragma unroll
            for (int nt = 0; nt < 4; nt++) {
                int no = warpN * 32 + nt * 8;
                uint32_t addr = smaddr(&xsb[ks * 16 + (lane & 15)][no]);
                asm volatile(
                    "ldmatrix.sync.aligned.m8n8.x2.trans.shared.b16 {%0,%1}, [%2];"
                    : "=r"(bfr[nt][0]), "=r"(bfr[nt][1]) : "r"(addr));
            }
#pragma unroll
            for (int mt = 0; mt < 4; mt++) {
                int mo = warpM * 64 + mt * 16;
                uint32_t a0 = wsb[(mo + g) * 20 + ks * 8 + tig];
                uint32_t a1 = wsb[(mo + g + 8) * 20 + ks * 8 + tig];
                uint32_t a2 = wsb[(mo + g) * 20 + ks * 8 + tig + 4];
                uint32_t a3 = wsb[(mo + g + 8) * 20 + ks * 8 + tig + 4];
#pragma unroll
                for (int nt = 0; nt < 4; nt++)
                    MMA_BF16(c[mt][nt][0], c[mt][nt][1], c[mt][nt][2], c[mt][nt][3],
                             a0, a1, a2, a3, bfr[nt][0], bfr[nt][1]);
            }
        }
        __syncthreads();
    }

#pragma unroll
    for (int mt = 0; mt < 4; mt++) {
#pragma unroll
        for (int half = 0; half < 2; half++) {
            int m = m0 + warpM * 64 + mt * 16 + g + half * 8;
            float bv = bias[m];
            size_t rowoff = ((size_t)b * M + m) * N;
#pragma unroll
            for (int nt = 0; nt < 4; nt++) {
                int n = n0 + warpN * 32 + nt * 8 + tig * 2;
                float v0 = c[mt][nt][half * 2 + 0] + bv;
                float v1 = c[mt][nt][half * 2 + 1] + bv;
                if (res) {
                    v0 += res[rowoff + n];
                    v1 += res[rowoff + n + 1];
                }
                C[rowoff + n] = v0;
                C[rowoff + n + 1] = v1;
            }
        }
    }
}

// ============================================================
// ckv GEMM, bf16 mma  [validated R12]
// ============================================================
__global__ void __launch_bounds__(256) ckv_bf16(
        const float* __restrict__ ctx, const float* __restrict__ W,
        const float* __restrict__ bias) {
    __shared__ uint32_t wsb[128 * 20];
    __shared__ uint32_t csb[80 * 20];

    int m0 = blockIdx.x * 128, b = blockIdx.y;
    int tid = threadIdx.x;
    int warp = tid >> 5, lane = tid & 31;
    int g = lane >> 2, tig = lane & 3;
    int mo = warp * 16;

    float c[10][4];
#pragma unroll
    for (int nt = 0; nt < 10; nt++)
#pragma unroll
        for (int r = 0; r < 4; r++) c[nt][r] = 0.f;

    int wrow = tid >> 1, wseg = tid & 1;

    for (int k0 = 0; k0 < CTXD; k0 += 32) {
        {
            const float* wp = W + (size_t)(m0 + wrow) * CTXD + k0 + wseg * 16;
            float4 f0 = *(const float4*)(wp + 0);
            float4 f1 = *(const float4*)(wp + 4);
            float4 f2 = *(const float4*)(wp + 8);
            float4 f3 = *(const float4*)(wp + 12);
            uint32_t* wd = wsb + wrow * 20 + wseg * 8;
            wd[0] = pkbf2(f0.x, f0.y); wd[1] = pkbf2(f0.z, f0.w);
            wd[2] = pkbf2(f1.x, f1.y); wd[3] = pkbf2(f1.z, f1.w);
            wd[4] = pkbf2(f2.x, f2.y); wd[5] = pkbf2(f2.z, f2.w);
            wd[6] = pkbf2(f3.x, f3.y); wd[7] = pkbf2(f3.z, f3.w);
        }
        if (tid < 160) {
            int l = tid >> 1, cseg = tid & 1;
            uint32_t* cd = csb + l * 20 + cseg * 8;
            if (l < LCTX) {
                const float* cp = ctx + ((size_t)b * LCTX + l) * CTXD + k0 + cseg * 16;
                float4 f0 = *(const float4*)(cp + 0);
                float4 f1 = *(const float4*)(cp + 4);
                float4 f2 = *(const float4*)(cp + 8);
                float4 f3 = *(const float4*)(cp + 12);
                cd[0] = pkbf2(f0.x, f0.y); cd[1] = pkbf2(f0.z, f0.w);
                cd[2] = pkbf2(f1.x, f1.y); cd[3] = pkbf2(f1.z, f1.w);
                cd[4] = pkbf2(f2.x, f2.y); cd[5] = pkbf2(f2.z, f2.w);
                cd[6] = pkbf2(f3.x, f3.y); cd[7] = pkbf2(f3.z, f3.w);
            } else {
#pragma unroll
                for (int j = 0; j < 8; j++) cd[j] = 0;
            }
        }
        __syncthreads();

#pragma unroll
        for (int ks = 0; ks < 2; ks++) {
            int w0 = ks * 8 + tig;
            uint32_t a0 = wsb[(mo + g) * 20 + w0];
            uint32_t a1 = wsb[(mo + g + 8) * 20 + w0];
            uint32_t a2 = wsb[(mo + g) * 20 + w0 + 4];
            uint32_t a3 = wsb[(mo + g + 8) * 20 + w0 + 4];
#pragma unroll
            for (int nt = 0; nt < 10; nt++) {
                uint32_t b0 = csb[(nt * 8 + g) * 20 + w0];
                uint32_t b1 = csb[(nt * 8 + g) * 20 + w0 + 4];
                MMA_BF16(c[nt][0], c[nt][1], c[nt][2], c[nt][3],
                         a0, a1, a2, a3, b0, b1);
            }
        }
        __syncthreads();
    }

#pragma unroll
    for (int half = 0; half < 2; half++) {
        int o = m0 + mo + g + half * 8;
        float bv = bias[o];
        float* outp = g_ckv + ((size_t)b * 1024 + o) * LCTX;
#pragma unroll
        for (int nt = 0; nt < 10; nt++) {
            int l = nt * 8 + tig * 2;
            if (l < LCTX)     outp[l]     = c[nt][half * 2 + 0] + bv;
            if (l + 1 < LCTX) outp[l + 1] = c[nt][half * 2 + 1] + bv;
        }
    }
}

// ============================================================
// packk: g_kb[bn][t][32w] bf16, swizzled, 0.125 logit scale folded.
// ============================================================
__global__ void packk_kernel() {
    __shared__ unsigned short ks[64][66];
    int tt = blockIdx.x, n = blockIdx.y, b = blockIdx.z;
    int tid = threadIdx.x;
    const float* kck = g_ckv + ((size_t)b * 1024 + n * 64) * LCTX;
    const float* kim = g_qkv + ((size_t)b * 1536 + 512 + n * 64) * 1024;
    int tl = tid & 63, dh = tid >> 6;
    int t0 = tt * 64;
#pragma unroll
    for (int p = 0; p < 16; p++) {
        int d = p * 4 + dh;
        int gt = t0 + tl;
        float kv = 0.f;
        if (gt < LCTX) kv = kck[d * LCTX + gt];
        else if (gt < TKV) kv = kim[(size_t)d * 1024 + (gt - LCTX)];
        __nv_bfloat16 h = __float2bfloat16_rn(kv * 0.125f);
        ks[d][tl] = *reinterpret_cast<unsigned short*>(&h);
    }
    __syncthreads();

    int row = tid >> 2, q = tid & 3;
    int t = t0 + row;
    int s = (t >> 3) & 3;
    uint32_t* outw = g_kb + ((size_t)(b * HEADS + n) * TPAD + t) * 32;
#pragma unroll
    for (int half = 0; half < 2; half++) {
        int w0 = q * 4 + half * 16;
        uint32_t wv[4];
#pragma unroll
        for (int j = 0; j < 4; j++) {
            int p = (w0 + j) ^ s;
            wv[j] = (uint32_t)ks[2 * p][row] | ((uint32_t)ks[2 * p + 1][row] << 16);
        }
        uint4 v = {wv[0], wv[1], wv[2], wv[3]};
        *(uint4*)(outw + w0) = v;
    }
}

// ============================================================
// packv: g_vb[bn][d][576w] bf16 ([d][t] pairs). grid (9, HEADS, BATCH).
// ============================================================
__global__ void packv_kernel() {
    int ck = blockIdx.x, n = blockIdx.y, b = blockIdx.z;
    int tid = threadIdx.x;
    const float* vck = g_ckv + ((size_t)b * 1024 + 512 + n * 64) * LCTX;
    const float* vim = g_qkv + ((size_t)b * 1536 + 1024 + n * 64) * 1024;
    uint32_t* outw = g_vb + (size_t)(b * HEADS + n) * 64 * (TPAD / 2);
    int d = tid >> 2, wq = (tid & 3) * 16;
#pragma unroll
    for (int j = 0; j < 16; j++) {
        int tp = ck * 64 + wq + j;
        int t = tp * 2;
        float v0 = 0.f, v1 = 0.f;
        if (t < LCTX) v0 = vck[d * LCTX + t];
        else if (t < TKV) v0 = vim[(size_t)d * 1024 + (t - LCTX)];
        if (t + 1 < LCTX) v1 = vck[d * LCTX + t + 1];
        else if (t + 1 < TKV) v1 = vim[(size_t)d * 1024 + (t + 1 - LCTX)];
        outw[(size_t)d * (TPAD / 2) + tp] = pkbf2(v0, v1);
    }
}

// ============================================================
// Flash attention v7: no-max softmax (logits provably bounded),
// zero shuffles in hot loop; l reduced once at kernel end.
// Otherwise identical to validated v6.
// ============================================================
#define QW 36
#define KW 36
#define VW 68
#define FL7_WORDS (128*QW + 2*(128*KW + 64*VW))
#define FL7_SMEM (FL7_WORDS * 4)   // 90112 B

__global__ void __launch_bounds__(256, 2) flash7_kernel() {
    extern __shared__ uint32_t sm7[];
    uint32_t* qs = sm7;
    uint32_t* ktb[2] = { qs + 128 * QW, qs + 128 * QW + 128 * KW };
    uint32_t* vtb[2] = { ktb[1] + 128 * KW, ktb[1] + 128 * KW + 64 * VW };
    __nv_bfloat16* qsb = (__nv_bfloat16*)qs;

    int s0 = blockIdx.x * 128;
    int n = blockIdx.y, b = blockIdx.z;
    int bn = b * HEADS + n;
    int tid = threadIdx.x;
    int warp = tid >> 5, lane = tid & 31;
    int g = lane >> 2, tig = lane & 3;
    int q0w = warp * 16;

    uint32_t kts[2], vts[2];
    kts[0] = smaddr(ktb[0]);
    kts[1] = smaddr(ktb[1]);
    vts[0] = smaddr(vtb[0]);
    vts[1] = smaddr(vtb[1]);

    const uint32_t* gk = g_kb + (size_t)bn * TPAD * 32;
    const uint32_t* gv = g_vb + (size_t)bn * 64 * (TPAD / 2);

    int ktrow = tid >> 1, ktq = tid & 1;
    int vdrow = tid >> 2, vwq = tid & 3;

    const float* qbase = g_qkv + ((size_t)b * 1536 + n * 64) * 1024 + s0;
    {
        int s = tid & 127, hi = tid >> 7;
#pragma unroll
        for (int p = 0; p < 32; p++) {
            int d = p * 2 + hi;
            qsb[s * (QW * 2) + d] = __float2bfloat16_rn(qbase[(size_t)d * 1024 + s]);
        }
    }

#define ISSUE_CHUNK(c)                                                         \
    do {                                                                       \
        int _bb = (c) & 1;                                                     \
        const uint32_t* _gkc = gk + ((size_t)(c) * 128 + ktrow) * 32 + ktq * 16; \
        uint32_t _kd = kts[_bb] + (ktrow * KW + ktq * 16) * 4;                 \
        cpasync16(_kd + 0,  _gkc + 0);                                         \
        cpasync16(_kd + 16, _gkc + 4);                                         \
        cpasync16(_kd + 32, _gkc + 8);                                         \
        cpasync16(_kd + 48, _gkc + 12);                                        \
        const uint32_t* _gvc = gv + (size_t)vdrow * (TPAD / 2) + (c) * 64 + vwq * 16; \
        uint32_t _vd = vts[_bb] + (vdrow * VW + vwq * 16) * 4;                 \
        cpasync16(_vd + 0,  _gvc + 0);                                         \
        cpasync16(_vd + 16, _gvc + 4);                                         \
        cpasync16(_vd + 32, _gvc + 8);                                         \
        cpasync16(_vd + 48, _gvc + 12);                                        \
        asm volatile("cp.async.commit_group;");                                \
    } while (0)

    ISSUE_CHUNK(0);

    float l0 = 0.f, l1 = 0.f;
    float o[8][4];
#pragma unroll
    for (int nt = 0; nt < 8; nt++)
#pragma unroll
        for (int r = 0; r < 4; r++) o[nt][r] = 0.f;

    for (int c = 0; c < NCHB; c++) {
        if (c + 1 < NCHB) {
            ISSUE_CHUNK(c + 1);
            asm volatile("cp.async.wait_group 1;");
        } else {
            asm volatile("cp.async.wait_group 0;");
        }
        __syncthreads();

        uint32_t* kt = ktb[c & 1];
        uint32_t* vt = vtb[c & 1];
        int t0 = c * 128;

#pragma unroll
        for (int h = 0; h < 2; h++) {
            // ---- S = Q K^T (scale pre-folded into K) ----
            float sfr[8][4];
#pragma unroll
            for (int nt = 0; nt < 8; nt++)
#pragma unroll
                for (int r = 0; r < 4; r++) sfr[nt][r] = 0.f;

#pragma unroll
            for (int ks = 0; ks < 4; ks++) {
                int w0 = ks * 8 + tig;
                uint32_t a0 = qs[(q0w + g) * QW + w0];
                uint32_t a1 = qs[(q0w + g + 8) * QW + w0];
                uint32_t a2 = qs[(q0w + g) * QW + w0 + 4];
                uint32_t a3 = qs[(q0w + g + 8) * QW + w0 + 4];
#pragma unroll
                for (int nt = 0; nt < 8; nt++) {
                    int t = h * 64 + nt * 8 + g;
                    int bw = w0 ^ (nt & 3);
                    uint32_t b0 = kt[t * KW + bw];
                    uint32_t b1 = kt[t * KW + bw + 4];
                    MMA_BF16(sfr[nt][0], sfr[nt][1], sfr[nt][2], sfr[nt][3],
                             a0, a1, a2, a3, b0, b1);
                }
            }

            // mask (last chunk only): exp(-1e30) -> 0
            if (t0 + h * 64 + 64 > TKV) {
#pragma unroll
                for (int nt = 0; nt < 8; nt++) {
                    int t = t0 + h * 64 + nt * 8 + tig * 2;
                    if (t >= TKV) { sfr[nt][0] = -1e30f; sfr[nt][2] = -1e30f; }
                    if (t + 1 >= TKV) { sfr[nt][1] = -1e30f; sfr[nt][3] = -1e30f; }
                }
            }

            // ---- no-max softmax: P = exp(S); l accumulates locally ----
#pragma unroll
            for (int nt = 0; nt < 8; nt++) {
                sfr[nt][0] = __expf(sfr[nt][0]);
                sfr[nt][1] = __expf(sfr[nt][1]);
                sfr[nt][2] = __expf(sfr[nt][2]);
                sfr[nt][3] = __expf(sfr[nt][3]);
                l0 += sfr[nt][0] + sfr[nt][1];
                l1 += sfr[nt][2] + sfr[nt][3];
            }

            // ---- O += P V : P fragments via C->A identity ----
#pragma unroll
            for (int ks = 0; ks < 4; ks++) {
                uint32_t a0 = pkbf2(sfr[2 * ks][0], sfr[2 * ks][1]);
                uint32_t a1 = pkbf2(sfr[2 * ks][2], sfr[2 * ks][3]);
                uint32_t a2 = pkbf2(sfr[2 * ks + 1][0], sfr[2 * ks + 1][1]);
                uint32_t a3 = pkbf2(sfr[2 * ks + 1][2], sfr[2 * ks + 1][3]);
                int w0 = ks * 8 + tig;
#pragma unroll
                for (int nt = 0; nt < 8; nt++) {
                    int d = nt * 8 + g;
                    uint32_t b0 = vt[d * VW + h * 32 + w0];
                    uint32_t b1 = vt[d * VW + h * 32 + w0 + 4];
                    MMA_BF16(o[nt][0], o[nt][1], o[nt][2], o[nt][3],
                             a0, a1, a2, a3, b0, b1);
                }
            }
        }
        __syncthreads();
    }

    // ---- single l reduction across the 4 tig lanes, normalize, store ----
    {
        l0 += __shfl_xor_sync(0xffffffffu, l0, 1);
        l0 += __shfl_xor_sync(0xffffffffu, l0, 2);
        l1 += __shfl_xor_sync(0xffffffffu, l1, 1);
        l1 += __shfl_xor_sync(0xffffffffu, l1, 2);
        float inv0 = 1.f / l0, inv1 = 1.f / l1;
        float* outp = g_attn + ((size_t)b * 512 + n * 64) * 1024 + s0;
        int sA = q0w + g, sB = q0w + g + 8;
#pragma unroll
        for (int nt = 0; nt < 8; nt++) {
            int d = nt * 8 + tig * 2;
            outp[(size_t)d * 1024 + sA] = o[nt][0] * inv0;
            outp[(size_t)(d + 1) * 1024 + sA] = o[nt][1] * inv0;
            outp[(size_t)d * 1024 + sB] = o[nt][2] * inv1;
            outp[(size_t)(d + 1) * 1024 + sB] = o[nt][3] * inv1;
        }
    }
}

// ============================================================
extern "C" void kernel_launch(void* const* d_in, const int* in_sizes, int n_in,
                              void* d_out, int out_size) {
    const float* x       = (const float*)d_in[0];
    const float* context = (const float*)d_in[1];
    const float* gamma   = (const float*)d_in[2];
    const float* beta    = (const float*)d_in[3];
    const float* qkv_w   = (const float*)d_in[4];
    const float* qkv_b   = (const float*)d_in[5];
    const float* ckv_w   = (const float*)d_in[6];
    const float* ckv_b   = (const float*)d_in[7];
    const float* proj_w  = (const float*)d_in[8];
    const float* proj_b  = (const float*)d_in[9];
    float* out = (float*)d_out;

    float *xn_p, *qkv_p, *attn_p;
    cudaGetSymbolAddress((void**)&xn_p, g_xn);
    cudaGetSymbolAddress((void**)&qkv_p, g_qkv);
    cudaGetSymbolAddress((void**)&attn_p, g_attn);

    // 1. GroupNorm
    gn_kernel<<<BATCH * 32, 256>>>(x, gamma, beta, xn_p);

    // 2. QKV projection (bf16 tensor cores)
    gemm_bf16<<<dim3(8, 12, BATCH), 256>>>(qkv_w, qkv_b, xn_p, nullptr, qkv_p, 1536, 1024, 512);

    // 3. Context KV projection (bf16 tensor cores)
    ckv_bf16<<<dim3(8, BATCH), 256>>>(context, ckv_w, ckv_b);

    // 4a. Pack K/V to bf16
    packk_kernel<<<dim3(NCHB * 2, HEADS, BATCH), 256>>>();
    packv_kernel<<<dim3(NCHB, HEADS, BATCH), 256>>>();

    // 4b. Flash attention v7 (no-max softmax)
    cudaFuncSetAttribute(flash7_kernel, cudaFuncAttributeMaxDynamicSharedMemorySize, FL7_SMEM);
    flash7_kernel<<<dim3(8, HEADS, BATCH), 256, FL7_SMEM>>>();

    // 5. Output projection + bias + residual (bf16 tensor cores)
    gemm_bf16<<<dim3(8, 4, BATCH), 256>>>(proj_w, proj_b, attn_p, x, out, 512, 1024, 512);
}

// round 16
// speedup vs baseline: 4.2408x; 1.0717x over previous
#include <cuda_runtime.h>
#include <cuda_bf16.h>
#include <math.h>
#include <stdint.h>

#define BATCH 8
#define DIMC 512
#define HW 1024
#define HEADS 8
#define HD 64
#define LCTX 77
#define CTXD 768
#define TKV 1101
#define TPAD 1152     // padded KV length (9 chunks of 128)
#define NCHB 9

// ---- scratch (device globals) ----
__device__ float g_xn[BATCH * DIMC * HW];
__device__ float g_qkv[BATCH * 3 * DIMC * HW];
__device__ float g_ckv[BATCH * 2 * DIMC * LCTX];
__device__ float g_attn[BATCH * DIMC * HW];
__device__ uint32_t g_kb[BATCH * HEADS * TPAD * 32];
__device__ uint32_t g_vb[BATCH * HEADS * 64 * (TPAD / 2)];

__device__ __forceinline__ uint32_t pkbf2(float lo, float hi) {
    __nv_bfloat162 v = __floats2bfloat162_rn(lo, hi);
    return *reinterpret_cast<uint32_t*>(&v);
}
__device__ __forceinline__ void cpasync16(uint32_t s, const void* g) {
    asm volatile("cp.async.cg.shared.global [%0], [%1], 16;" :: "r"(s), "l"(g));
}
__device__ __forceinline__ uint32_t smaddr(const void* p) {
    return (uint32_t)__cvta_generic_to_shared(p);
}

#define MMA_BF16(c0,c1,c2,c3,a0,a1,a2,a3,b0,b1)                               \
    asm volatile(                                                              \
        "mma.sync.aligned.m16n8k16.row.col.f32.bf16.bf16.f32 "                 \
        "{%0,%1,%2,%3}, {%4,%5,%6,%7}, {%8,%9}, {%0,%1,%2,%3};"                \
        : "+f"(c0), "+f"(c1), "+f"(c2), "+f"(c3)                               \
        : "r"(a0), "r"(a1), "r"(a2), "r"(a3), "r"(b0), "r"(b1))

#define LDMX4(r0,r1,r2,r3,addr)                                               \
    asm volatile(                                                              \
        "ldmatrix.sync.aligned.m8n8.x4.shared.b16 {%0,%1,%2,%3}, [%4];"        \
        : "=r"(r0), "=r"(r1), "=r"(r2), "=r"(r3) : "r"(addr))

// ============================================================
// GroupNorm
// ============================================================
__global__ void gn_kernel(const float* __restrict__ x, const float* __restrict__ gamma,
                          const float* __restrict__ beta, float* __restrict__ xn) {
    __shared__ float ssum[256], ssq[256];
    int bg = blockIdx.x;
    int b = bg >> 5, g = bg & 31;
    const float* xp = x + ((size_t)b * DIMC + g * 16) * HW;
    float* xo = xn + ((size_t)b * DIMC + g * 16) * HW;
    int tid = threadIdx.x;

    float s = 0.f, sq = 0.f;
#pragma unroll
    for (int i = 0; i < 64; i++) {
        float v = xp[tid + i * 256];
        s += v; sq += v * v;
    }
    ssum[tid] = s; ssq[tid] = sq;
    __syncthreads();
    for (int off = 128; off > 0; off >>= 1) {
        if (tid < off) { ssum[tid] += ssum[tid + off]; ssq[tid] += ssq[tid + off]; }
        __syncthreads();
    }
    float mu = ssum[0] * (1.f / 16384.f);
    float var = ssq[0] * (1.f / 16384.f) - mu * mu;
    float inv = rsqrtf(var + 1e-5f);
#pragma unroll
    for (int i = 0; i < 64; i++) {
        int idx = tid + i * 256;
        int c = g * 16 + (idx >> 10);
        xo[idx] = (xp[idx] - mu) * inv * gamma[c] + beta[c];
    }
}

// ============================================================
// bf16 tensor-core GEMM (m16n8k16): C = W X + bias (+res)  [validated R11]
// ============================================================
__global__ void __launch_bounds__(256) gemm_bf16(
        const float* __restrict__ W, const float* __restrict__ bias,
        const float* __restrict__ X, const float* __restrict__ res,
        float* __restrict__ C, int M, int N, int K) {
    __shared__ uint32_t wsb[128 * 20];
    __shared__ __nv_bfloat16 xsb[32][136];

    int b = blockIdx.z;
    int m0 = blockIdx.y * 128, n0 = blockIdx.x * 128;
    const float* Xb = X + (size_t)b * K * N;
    int tid = threadIdx.x;
    int warp = tid >> 5, lane = tid & 31;
    int warpM = warp >> 2, warpN = warp & 3;
    int g = lane >> 2, tig = lane & 3;

    float c[4][4][4];
#pragma unroll
    for (int mt = 0; mt < 4; mt++)
#pragma unroll
        for (int nt = 0; nt < 4; nt++)
#pragma unroll
            for (int r = 0; r < 4; r++) c[mt][nt][r] = 0.f;

    int wrow = tid >> 1, wseg = tid & 1;
    int xk = tid >> 3, xn16 = (tid & 7) * 16;

    for (int k0 = 0; k0 < K; k0 += 32) {
        {
            const float* wp = W + (size_t)(m0 + wrow) * K + k0 + wseg * 16;
            float4 f0 = *(const float4*)(wp + 0);
            float4 f1 = *(const float4*)(wp + 4);
            float4 f2 = *(const float4*)(wp + 8);
            float4 f3 = *(const float4*)(wp + 12);
            uint32_t* wd = wsb + wrow * 20 + wseg * 8;
            wd[0] = pkbf2(f0.x, f0.y); wd[1] = pkbf2(f0.z, f0.w);
            wd[2] = pkbf2(f1.x, f1.y); wd[3] = pkbf2(f1.z, f1.w);
            wd[4] = pkbf2(f2.x, f2.y); wd[5] = pkbf2(f2.z, f2.w);
            wd[6] = pkbf2(f3.x, f3.y); wd[7] = pkbf2(f3.z, f3.w);
        }
        {
            const float* xp = Xb + (size_t)(k0 + xk) * N + n0 + xn16;
            float4 f0 = *(const float4*)(xp + 0);
            float4 f1 = *(const float4*)(xp + 4);
            float4 f2 = *(const float4*)(xp + 8);
            float4 f3 = *(const float4*)(xp + 12);
            uint32_t* xd = (uint32_t*)&xsb[xk][xn16];
            xd[0] = pkbf2(f0.x, f0.y); xd[1] = pkbf2(f0.z, f0.w);
            xd[2] = pkbf2(f1.x, f1.y); xd[3] = pkbf2(f1.z, f1.w);
            xd[4] = pkbf2(f2.x, f2.y); xd[5] = pkbf2(f2.z, f2.w);
            xd[6] = pkbf2(f3.x, f3.y); xd[7] = pkbf2(f3.z, f3.w);
        }
        __syncthreads();

#pragma unroll
        for (int ks = 0; ks < 2; ks++) {
            uint32_t bfr[4][2];
#pragma unroll
            for (int nt = 0; nt < 4; nt++) {
                int no = warpN * 32 + nt * 8;
                uint32_t addr = smaddr(&xsb[ks * 16 + (lane & 15)][no]);
                asm volatile(
                    "ldmatrix.sync.aligned.m8n8.x2.trans.shared.b16 {%0,%1}, [%2];"
                    : "=r"(bfr[nt][0]), "=r"(bfr[nt][1]) : "r"(addr));
            }
#pragma unroll
            for (int mt = 0; mt < 4; mt++) {
                int mo = warpM * 64 + mt * 16;
                uint32_t a0 = wsb[(mo + g) * 20 + ks * 8 + tig];
                uint32_t a1 = wsb[(mo + g + 8) * 20 + ks * 8 + tig];
                uint32_t a2 = wsb[(mo + g) * 20 + ks * 8 + tig + 4];
                uint32_t a3 = wsb[(mo + g + 8) * 20 + ks * 8 + tig + 4];
#pragma unroll
                for (int nt = 0; nt < 4; nt++)
                    MMA_BF16(c[mt][nt][0], c[mt][nt][1], c[mt][nt][2], c[mt][nt][3],
                             a0, a1, a2, a3, bfr[nt][0], bfr[nt][1]);
            }
        }
        __syncthreads();
    }

#pragma unroll
    for (int mt = 0; mt < 4; mt++) {
#pragma unroll
        for (int half = 0; half < 2; half++) {
            int m = m0 + warpM * 64 + mt * 16 + g + half * 8;
            float bv = bias[m];
            size_t rowoff = ((size_t)b * M + m) * N;
#pragma unroll
            for (int nt = 0; nt < 4; nt++) {
                int n = n0 + warpN * 32 + nt * 8 + tig * 2;
                float v0 = c[mt][nt][half * 2 + 0] + bv;
                float v1 = c[mt][nt][half * 2 + 1] + bv;
                if (res) {
                    v0 += res[rowoff + n];
                    v1 += res[rowoff + n + 1];
                }
                C[rowoff + n] = v0;
                C[rowoff + n + 1] = v1;
            }
        }
    }
}

// ============================================================
// ckv GEMM, bf16 mma  [validated R12]
// ============================================================
__global__ void __launch_bounds__(256) ckv_bf16(
        const float* __restrict__ ctx, const float* __restrict__ W,
        const float* __restrict__ bias) {
    __shared__ uint32_t wsb[128 * 20];
    __shared__ uint32_t csb[80 * 20];

    int m0 = blockIdx.x * 128, b = blockIdx.y;
    int tid = threadIdx.x;
    int warp = tid >> 5, lane = tid & 31;
    int g = lane >> 2, tig = lane & 3;
    int mo = warp * 16;

    float c[10][4];
#pragma unroll
    for (int nt = 0; nt < 10; nt++)
#pragma unroll
        for (int r = 0; r < 4; r++) c[nt][r] = 0.f;

    int wrow = tid >> 1, wseg = tid & 1;

    for (int k0 = 0; k0 < CTXD; k0 += 32) {
        {
            const float* wp = W + (size_t)(m0 + wrow) * CTXD + k0 + wseg * 16;
            float4 f0 = *(const float4*)(wp + 0);
            float4 f1 = *(const float4*)(wp + 4);
            float4 f2 = *(const float4*)(wp + 8);
            float4 f3 = *(const float4*)(wp + 12);
            uint32_t* wd = wsb + wrow * 20 + wseg * 8;
            wd[0] = pkbf2(f0.x, f0.y); wd[1] = pkbf2(f0.z, f0.w);
            wd[2] = pkbf2(f1.x, f1.y); wd[3] = pkbf2(f1.z, f1.w);
            wd[4] = pkbf2(f2.x, f2.y); wd[5] = pkbf2(f2.z, f2.w);
            wd[6] = pkbf2(f3.x, f3.y); wd[7] = pkbf2(f3.z, f3.w);
        }
        if (tid < 160) {
            int l = tid >> 1, cseg = tid & 1;
            uint32_t* cd = csb + l * 20 + cseg * 8;
            if (l < LCTX) {
                const float* cp = ctx + ((size_t)b * LCTX + l) * CTXD + k0 + cseg * 16;
                float4 f0 = *(const float4*)(cp + 0);
                float4 f1 = *(const float4*)(cp + 4);
                float4 f2 = *(const float4*)(cp + 8);
                float4 f3 = *(const float4*)(cp + 12);
                cd[0] = pkbf2(f0.x, f0.y); cd[1] = pkbf2(f0.z, f0.w);
                cd[2] = pkbf2(f1.x, f1.y); cd[3] = pkbf2(f1.z, f1.w);
                cd[4] = pkbf2(f2.x, f2.y); cd[5] = pkbf2(f2.z, f2.w);
                cd[6] = pkbf2(f3.x, f3.y); cd[7] = pkbf2(f3.z, f3.w);
            } else {
#pragma unroll
                for (int j = 0; j < 8; j++) cd[j] = 0;
            }
        }
        __syncthreads();

#pragma unroll
        for (int ks = 0; ks < 2; ks++) {
            int w0 = ks * 8 + tig;
            uint32_t a0 = wsb[(mo + g) * 20 + w0];
            uint32_t a1 = wsb[(mo + g + 8) * 20 + w0];
            uint32_t a2 = wsb[(mo + g) * 20 + w0 + 4];
            uint32_t a3 = wsb[(mo + g + 8) * 20 + w0 + 4];
#pragma unroll
            for (int nt = 0; nt < 10; nt++) {
                uint32_t b0 = csb[(nt * 8 + g) * 20 + w0];
                uint32_t b1 = csb[(nt * 8 + g) * 20 + w0 + 4];
                MMA_BF16(c[nt][0], c[nt][1], c[nt][2], c[nt][3],
                         a0, a1, a2, a3, b0, b1);
            }
        }
        __syncthreads();
    }

#pragma unroll
    for (int half = 0; half < 2; half++) {
        int o = m0 + mo + g + half * 8;
        float bv = bias[o];
        float* outp = g_ckv + ((size_t)b * 1024 + o) * LCTX;
#pragma unroll
        for (int nt = 0; nt < 10; nt++) {
            int l = nt * 8 + tig * 2;
            if (l < LCTX)     outp[l]     = c[nt][half * 2 + 0] + bv;
            if (l + 1 < LCTX) outp[l + 1] = c[nt][half * 2 + 1] + bv;
        }
    }
}

// ============================================================
// packk: g_kb[bn][t][32w] bf16, PLAIN word order (no XOR — the
// 36-word smem row stride makes ldmatrix conflict-free), 0.125 folded.
// ============================================================
__global__ void packk_kernel() {
    __shared__ unsigned short ks[64][66];
    int tt = blockIdx.x, n = blockIdx.y, b = blockIdx.z;
    int tid = threadIdx.x;
    const float* kck = g_ckv + ((size_t)b * 1024 + n * 64) * LCTX;
    const float* kim = g_qkv + ((size_t)b * 1536 + 512 + n * 64) * 1024;
    int tl = tid & 63, dh = tid >> 6;
    int t0 = tt * 64;
#pragma unroll
    for (int p = 0; p < 16; p++) {
        int d = p * 4 + dh;
        int gt = t0 + tl;
        float kv = 0.f;
        if (gt < LCTX) kv = kck[d * LCTX + gt];
        else if (gt < TKV) kv = kim[(size_t)d * 1024 + (gt - LCTX)];
        __nv_bfloat16 h = __float2bfloat16_rn(kv * 0.125f);
        ks[d][tl] = *reinterpret_cast<unsigned short*>(&h);
    }
    __syncthreads();

    int row = tid >> 2, q = tid & 3;
    int t = t0 + row;
    uint32_t* outw = g_kb + ((size_t)(b * HEADS + n) * TPAD + t) * 32;
#pragma unroll
    for (int half = 0; half < 2; half++) {
        int w0 = q * 4 + half * 16;
        uint32_t wv[4];
#pragma unroll
        for (int j = 0; j < 4; j++) {
            int p = w0 + j;
            wv[j] = (uint32_t)ks[2 * p][row] | ((uint32_t)ks[2 * p + 1][row] << 16);
        }
        uint4 v = {wv[0], wv[1], wv[2], wv[3]};
        *(uint4*)(outw + w0) = v;
    }
}

// ============================================================
// packv: g_vb[bn][d][576w] bf16 ([d][t] pairs). grid (9, HEADS, BATCH).
// ============================================================
__global__ void packv_kernel() {
    int ck = blockIdx.x, n = blockIdx.y, b = blockIdx.z;
    int tid = threadIdx.x;
    const float* vck = g_ckv + ((size_t)b * 1024 + 512 + n * 64) * LCTX;
    const float* vim = g_qkv + ((size_t)b * 1536 + 1024 + n * 64) * 1024;
    uint32_t* outw = g_vb + (size_t)(b * HEADS + n) * 64 * (TPAD / 2);
    int d = tid >> 2, wq = (tid & 3) * 16;
#pragma unroll
    for (int j = 0; j < 16; j++) {
        int tp = ck * 64 + wq + j;
        int t = tp * 2;
        float v0 = 0.f, v1 = 0.f;
        if (t < LCTX) v0 = vck[d * LCTX + t];
        else if (t < TKV) v0 = vim[(size_t)d * 1024 + (t - LCTX)];
        if (t + 1 < LCTX) v1 = vck[d * LCTX + t + 1];
        else if (t + 1 < TKV) v1 = vim[(size_t)d * 1024 + (t + 1 - LCTX)];
        outw[(size_t)d * (TPAD / 2) + tp] = pkbf2(v0, v1);
    }
}

// ============================================================
// Flash attention v8: v7 + all fragment loads via ldmatrix.x4.
// Row strides (36/36/68 words = 9/9/17 x16B) are conflict-free for
// naive ldmatrix. No-max softmax; C->A identity for P.
// ============================================================
#define QW 36
#define KW 36
#define VW 68
#define FL8_WORDS (128*QW + 2*(128*KW + 64*VW))
#define FL8_SMEM (FL8_WORDS * 4)   // 90112 B

__global__ void __launch_bounds__(256, 2) flash8_kernel() {
    extern __shared__ uint32_t sm8[];
    uint32_t* qs = sm8;
    uint32_t* ktb[2] = { qs + 128 * QW, qs + 128 * QW + 128 * KW };
    uint32_t* vtb[2] = { ktb[1] + 128 * KW, ktb[1] + 128 * KW + 64 * VW };
    __nv_bfloat16* qsb = (__nv_bfloat16*)qs;

    int s0 = blockIdx.x * 128;
    int n = blockIdx.y, b = blockIdx.z;
    int bn = b * HEADS + n;
    int tid = threadIdx.x;
    int warp = tid >> 5, lane = tid & 31;
    int g = lane >> 2, tig = lane & 3;
    int q0w = warp * 16;
    int lr8 = lane & 7, lsel4 = (lane >> 3) << 2;   // K/V ldmatrix lane roles

    uint32_t kts[2], vts[2];
    kts[0] = smaddr(ktb[0]);
    kts[1] = smaddr(ktb[1]);
    vts[0] = smaddr(vtb[0]);
    vts[1] = smaddr(vtb[1]);

    const uint32_t* gk = g_kb + (size_t)bn * TPAD * 32;
    const uint32_t* gv = g_vb + (size_t)bn * 64 * (TPAD / 2);

    int ktrow = tid >> 1, ktq = tid & 1;
    int vdrow = tid >> 2, vwq = tid & 3;

    const float* qbase = g_qkv + ((size_t)b * 1536 + n * 64) * 1024 + s0;
    {
        int s = tid & 127, hi = tid >> 7;
#pragma unroll
        for (int p = 0; p < 32; p++) {
            int d = p * 2 + hi;
            qsb[s * (QW * 2) + d] = __float2bfloat16_rn(qbase[(size_t)d * 1024 + s]);
        }
    }
    __syncthreads();

    // ---- hoist Q fragments (chunk-invariant): 4 ldmatrix.x4 ----
    uint32_t qa[4][4];
    {
        uint32_t qaddr = smaddr(qs + (q0w + (lane & 15)) * QW + ((lane >> 4) << 2));
#pragma unroll
        for (int ks = 0; ks < 4; ks++)
            LDMX4(qa[ks][0], qa[ks][1], qa[ks][2], qa[ks][3], qaddr + ks * 32);
    }

#define ISSUE_CHUNK(c)                                                         \
    do {                                                                       \
        int _bb = (c) & 1;                                                     \
        const uint32_t* _gkc = gk + ((size_t)(c) * 128 + ktrow) * 32 + ktq * 16; \
        uint32_t _kd = kts[_bb] + (ktrow * KW + ktq * 16) * 4;                 \
        cpasync16(_kd + 0,  _gkc + 0);                                         \
        cpasync16(_kd + 16, _gkc + 4);                                         \
        cpasync16(_kd + 32, _gkc + 8);                                         \
        cpasync16(_kd + 48, _gkc + 12);                                        \
        const uint32_t* _gvc = gv + (size_t)vdrow * (TPAD / 2) + (c) * 64 + vwq * 16; \
        uint32_t _vd = vts[_bb] + (vdrow * VW + vwq * 16) * 4;                 \
        cpasync16(_vd + 0,  _gvc + 0);                                         \
        cpasync16(_vd + 16, _gvc + 4);                                         \
        cpasync16(_vd + 32, _gvc + 8);                                         \
        cpasync16(_vd + 48, _gvc + 12);                                        \
        asm volatile("cp.async.commit_group;");                                \
    } while (0)

    ISSUE_CHUNK(0);

    float l0 = 0.f, l1 = 0.f;
    float o[8][4];
#pragma unroll
    for (int nt = 0; nt < 8; nt++)
#pragma unroll
        for (int r = 0; r < 4; r++) o[nt][r] = 0.f;

    for (int c = 0; c < NCHB; c++) {
        if (c + 1 < NCHB) {
            ISSUE_CHUNK(c + 1);
            asm volatile("cp.async.wait_group 1;");
        } else {
            asm volatile("cp.async.wait_group 0;");
        }
        __syncthreads();

        uint32_t ktbase = kts[c & 1];
        uint32_t vtbase = vts[c & 1];
        int t0 = c * 128;

#pragma unroll
        for (int h = 0; h < 2; h++) {
            // ---- S = Q K^T : K fragments via 2 ldmatrix.x4 per nt ----
            float sfr[8][4];
#pragma unroll
            for (int nt = 0; nt < 8; nt++)
#pragma unroll
                for (int r = 0; r < 4; r++) sfr[nt][r] = 0.f;

#pragma unroll
            for (int nt = 0; nt < 8; nt++) {
                uint32_t ka = ktbase + ((h * 64 + nt * 8 + lr8) * KW + lsel4) * 4;
                uint32_t k0, k1, k2, k3, k4, k5, k6, k7;
                LDMX4(k0, k1, k2, k3, ka);
                LDMX4(k4, k5, k6, k7, ka + 64);
                MMA_BF16(sfr[nt][0], sfr[nt][1], sfr[nt][2], sfr[nt][3],
                         qa[0][0], qa[0][1], qa[0][2], qa[0][3], k0, k1);
                MMA_BF16(sfr[nt][0], sfr[nt][1], sfr[nt][2], sfr[nt][3],
                         qa[1][0], qa[1][1], qa[1][2], qa[1][3], k2, k3);
                MMA_BF16(sfr[nt][0], sfr[nt][1], sfr[nt][2], sfr[nt][3],
                         qa[2][0], qa[2][1], qa[2][2], qa[2][3], k4, k5);
                MMA_BF16(sfr[nt][0], sfr[nt][1], sfr[nt][2], sfr[nt][3],
                         qa[3][0], qa[3][1], qa[3][2], qa[3][3], k6, k7);
            }

            // mask (last chunk only): exp(-1e30) -> 0
            if (t0 + h * 64 + 64 > TKV) {
#pragma unroll
                for (int nt = 0; nt < 8; nt++) {
                    int t = t0 + h * 64 + nt * 8 + tig * 2;
                    if (t >= TKV) { sfr[nt][0] = -1e30f; sfr[nt][2] = -1e30f; }
                    if (t + 1 >= TKV) { sfr[nt][1] = -1e30f; sfr[nt][3] = -1e30f; }
                }
            }

            // ---- no-max softmax ----
#pragma unroll
            for (int nt = 0; nt < 8; nt++) {
                sfr[nt][0] = __expf(sfr[nt][0]);
                sfr[nt][1] = __expf(sfr[nt][1]);
                sfr[nt][2] = __expf(sfr[nt][2]);
                sfr[nt][3] = __expf(sfr[nt][3]);
                l0 += sfr[nt][0] + sfr[nt][1];
                l1 += sfr[nt][2] + sfr[nt][3];
            }

            // ---- pack P fragments (C->A identity) ----
            uint32_t pA[4][4];
#pragma unroll
            for (int ks = 0; ks < 4; ks++) {
                pA[ks][0] = pkbf2(sfr[2 * ks][0], sfr[2 * ks][1]);
                pA[ks][1] = pkbf2(sfr[2 * ks][2], sfr[2 * ks][3]);
                pA[ks][2] = pkbf2(sfr[2 * ks + 1][0], sfr[2 * ks + 1][1]);
                pA[ks][3] = pkbf2(sfr[2 * ks + 1][2], sfr[2 * ks + 1][3]);
            }

            // ---- O += P V : V fragments via 2 ldmatrix.x4 per nt ----
#pragma unroll
            for (int nt = 0; nt < 8; nt++) {
                uint32_t va = vtbase + ((nt * 8 + lr8) * VW + h * 32 + lsel4) * 4;
                uint32_t v0, v1, v2, v3, v4, v5, v6, v7;
                LDMX4(v0, v1, v2, v3, va);
                LDMX4(v4, v5, v6, v7, va + 64);
                MMA_BF16(o[nt][0], o[nt][1], o[nt][2], o[nt][3],
                         pA[0][0], pA[0][1], pA[0][2], pA[0][3], v0, v1);
                MMA_BF16(o[nt][0], o[nt][1], o[nt][2], o[nt][3],
                         pA[1][0], pA[1][1], pA[1][2], pA[1][3], v2, v3);
                MMA_BF16(o[nt][0], o[nt][1], o[nt][2], o[nt][3],
                         pA[2][0], pA[2][1], pA[2][2], pA[2][3], v4, v5);
                MMA_BF16(o[nt][0], o[nt][1], o[nt][2], o[nt][3],
                         pA[3][0], pA[3][1], pA[3][2], pA[3][3], v6, v7);
            }
        }
        __syncthreads();
    }

    // ---- single l reduction, normalize, store ----
    {
        l0 += __shfl_xor_sync(0xffffffffu, l0, 1);
        l0 += __shfl_xor_sync(0xffffffffu, l0, 2);
        l1 += __shfl_xor_sync(0xffffffffu, l1, 1);
        l1 += __shfl_xor_sync(0xffffffffu, l1, 2);
        float inv0 = 1.f / l0, inv1 = 1.f / l1;
        float* outp = g_attn + ((size_t)b * 512 + n * 64) * 1024 + s0;
        int sA = q0w + g, sB = q0w + g + 8;
#pragma unroll
        for (int nt = 0; nt < 8; nt++) {
            int d = nt * 8 + tig * 2;
            outp[(size_t)d * 1024 + sA] = o[nt][0] * inv0;
            outp[(size_t)(d + 1) * 1024 + sA] = o[nt][1] * inv0;
            outp[(size_t)d * 1024 + sB] = o[nt][2] * inv1;
            outp[(size_t)(d + 1) * 1024 + sB] = o[nt][3] * inv1;
        }
    }
}

// ============================================================
extern "C" void kernel_launch(void* const* d_in, const int* in_sizes, int n_in,
                              void* d_out, int out_size) {
    const float* x       = (const float*)d_in[0];
    const float* context = (const float*)d_in[1];
    const float* gamma   = (const float*)d_in[2];
    const float* beta    = (const float*)d_in[3];
    const float* qkv_w   = (const float*)d_in[4];
    const float* qkv_b   = (const float*)d_in[5];
    const float* ckv_w   = (const float*)d_in[6];
    const float* ckv_b   = (const float*)d_in[7];
    const float* proj_w  = (const float*)d_in[8];
    const float* proj_b  = (const float*)d_in[9];
    float* out = (float*)d_out;

    float *xn_p, *qkv_p, *attn_p;
    cudaGetSymbolAddress((void**)&xn_p, g_xn);
    cudaGetSymbolAddress((void**)&qkv_p, g_qkv);
    cudaGetSymbolAddress((void**)&attn_p, g_attn);

    // 1. GroupNorm
    gn_kernel<<<BATCH * 32, 256>>>(x, gamma, beta, xn_p);

    // 2. QKV projection (bf16 tensor cores)
    gemm_bf16<<<dim3(8, 12, BATCH), 256>>>(qkv_w, qkv_b, xn_p, nullptr, qkv_p, 1536, 1024, 512);

    // 3. Context KV projection (bf16 tensor cores)
    ckv_bf16<<<dim3(8, BATCH), 256>>>(context, ckv_w, ckv_b);

    // 4a. Pack K/V to bf16
    packk_kernel<<<dim3(NCHB * 2, HEADS, BATCH), 256>>>();
    packv_kernel<<<dim3(NCHB, HEADS, BATCH), 256>>>();

    // 4b. Flash attention v8 (ldmatrix fragments)
    cudaFuncSetAttribute(flash8_kernel, cudaFuncAttributeMaxDynamicSharedMemorySize, FL8_SMEM);
    flash8_kernel<<<dim3(8, HEADS, BATCH), 256, FL8_SMEM>>>();

    // 5. Output projection + bias + residual (bf16 tensor cores)
    gemm_bf16<<<dim3(8, 4, BATCH), 256>>>(proj_w, proj_b, attn_p, x, out, 512, 1024, 512);
}

// round 17
// speedup vs baseline: 4.9669x; 1.1712x over previous
#include <cuda_runtime.h>
#include <cuda_bf16.h>
#include <math.h>
#include <stdint.h>

#define BATCH 8
#define DIMC 512
#define HW 1024
#define HEADS 8
#define HD 64
#define LCTX 77
#define CTXD 768
#define TKV 1101
#define TPAD 1152
#define NCHB 9

__device__ float g_qkv[BATCH * 3 * DIMC * HW];
__device__ float g_ckv[BATCH * 2 * DIMC * LCTX];
__device__ uint32_t g_kb[BATCH * HEADS * TPAD * 32];
__device__ uint32_t g_vb[BATCH * HEADS * 64 * (TPAD / 2)];
__device__ __nv_bfloat16 g_xnb[BATCH * DIMC * HW];
__device__ __nv_bfloat16 g_attnb[BATCH * DIMC * HW];
__device__ __nv_bfloat16 g_wqkvb[3 * DIMC * DIMC];
__device__ __nv_bfloat16 g_wprojb[DIMC * DIMC];

__device__ __forceinline__ uint32_t pkbf2(float lo, float hi) {
    __nv_bfloat162 v = __floats2bfloat162_rn(lo, hi);
    return *reinterpret_cast<uint32_t*>(&v);
}
__device__ __forceinline__ void cpasync16(uint32_t s, const void* g) {
    asm volatile("cp.async.cg.shared.global [%0], [%1], 16;" :: "r"(s), "l"(g));
}
__device__ __forceinline__ uint32_t smaddr(const void* p) {
    return (uint32_t)__cvta_generic_to_shared(p);
}

#define MMA_BF16(c0,c1,c2,c3,a0,a1,a2,a3,b0,b1)                               \
    asm volatile(                                                              \
        "mma.sync.aligned.m16n8k16.row.col.f32.bf16.bf16.f32 "                 \
        "{%0,%1,%2,%3}, {%4,%5,%6,%7}, {%8,%9}, {%0,%1,%2,%3};"                \
        : "+f"(c0), "+f"(c1), "+f"(c2), "+f"(c3)                               \
        : "r"(a0), "r"(a1), "r"(a2), "r"(a3), "r"(b0), "r"(b1))

#define LDMX4(r0,r1,r2,r3,addr)                                               \
    asm volatile(                                                              \
        "ldmatrix.sync.aligned.m8n8.x4.shared.b16 {%0,%1,%2,%3}, [%4];"        \
        : "=r"(r0), "=r"(r1), "=r"(r2), "=r"(r3) : "r"(addr))

__global__ void wconv_kernel(const float* __restrict__ src,
                             __nv_bfloat16* __restrict__ dst, int n4) {
    int i = blockIdx.x * 256 + threadIdx.x;
    int stride = gridDim.x * 256;
    for (; i < n4; i += stride) {
        float4 f = *(const float4*)(src + (size_t)i * 4);
        uint32_t* d = (uint32_t*)(dst + (size_t)i * 4);
        d[0] = pkbf2(f.x, f.y);
        d[1] = pkbf2(f.z, f.w);
    }
}

__global__ void gn_kernel(const float* __restrict__ x, const float* __restrict__ gamma,
                          const float* __restrict__ beta) {
    __shared__ float ssum[256], ssq[256];
    int bg = blockIdx.x;
    int b = bg >> 5, g = bg & 31;
    const float* xp = x + ((size_t)b * DIMC + g * 16) * HW;
    __nv_bfloat16* xo = g_xnb + ((size_t)b * DIMC + g * 16) * HW;
    int tid = threadIdx.x;

    float s = 0.f, sq = 0.f;
#pragma unroll
    for (int i = 0; i < 64; i++) {
        float v = xp[tid + i * 256];
        s += v; sq += v * v;
    }
    ssum[tid] = s; ssq[tid] = sq;
    __syncthreads();
    for (int off = 128; off > 0; off >>= 1) {
        if (tid < off) { ssum[tid] += ssum[tid + off]; ssq[tid] += ssq[tid + off]; }
        __syncthreads();
    }
    float mu = ssum[0] * (1.f / 16384.f);
    float var = ssq[0] * (1.f / 16384.f) - mu * mu;
    float inv = rsqrtf(var + 1e-5f);
#pragma unroll
    for (int i = 0; i < 64; i++) {
        int idx = tid + i * 256;
        int c = g * 16 + (idx >> 10);
        xo[idx] = __float2bfloat16_rn((xp[idx] - mu) * inv * gamma[c] + beta[c]);
    }
}

__global__ void __launch_bounds__(256) gemm_bf16g(
        const __nv_bfloat16* __restrict__ W, const float* __restrict__ bias,
        const __nv_bfloat16* __restrict__ X, const float* __restrict__ res,
        float* __restrict__ C, int M, int N, int K) {
    __shared__ uint32_t ws2[2][128 * 20];
    __shared__ uint32_t xs2[2][32 * 68];

    int b = blockIdx.z;
    int m0 = blockIdx.y * 128, n0 = blockIdx.x * 128;
    const __nv_bfloat16* Xb = X + (size_t)b * K * N;
    int tid = threadIdx.x;
    int warp = tid >> 5, lane = tid & 31;
    int warpM = warp >> 2, warpN = warp & 3;
    int g = lane >> 2, tig = lane & 3;

    float c[4][4][4];
#pragma unroll
    for (int mt = 0; mt < 4; mt++)
#pragma unroll
        for (int nt = 0; nt < 4; nt++)
#pragma unroll
            for (int r = 0; r < 4; r++) c[mt][nt][r] = 0.f;

    int wrow = tid >> 1, wseg = tid & 1;
    int xrow = tid >> 3, xseg = tid & 7;

    uint32_t wsa[2] = { smaddr(ws2[0]), smaddr(ws2[1]) };
    uint32_t xsa[2] = { smaddr(xs2[0]), smaddr(xs2[1]) };

#define G_ISSUE(k0v, s)                                                        \
    do {                                                                       \
        const __nv_bfloat16* wp = W + (size_t)(m0 + wrow) * K + (k0v) + wseg * 16; \
        uint32_t wd = wsa[s] + (wrow * 20 + wseg * 8) * 4;                     \
        cpasync16(wd, wp);                                                     \
        cpasync16(wd + 16, wp + 8);                                            \
        const __nv_bfloat16* xp = Xb + (size_t)((k0v) + xrow) * N + n0 + xseg * 16; \
        uint32_t xd = xsa[s] + (xrow * 68 + xseg * 8) * 4;                     \
        cpasync16(xd, xp);                                                     \
        cpasync16(xd + 16, xp + 8);                                            \
        asm volatile("cp.async.commit_group;");                                \
    } while (0)

    G_ISSUE(0, 0);
    int niter = K >> 5;
    for (int it = 0; it < niter; it++) {
        if (it + 1 < niter) {
            G_ISSUE((it + 1) << 5, (it + 1) & 1);
            asm volatile("cp.async.wait_group 1;");
        } else {
            asm volatile("cp.async.wait_group 0;");
        }
        __syncthreads();

        int s = it & 1;
        uint32_t* wsb = ws2[s];
#pragma unroll
        for (int ks = 0; ks < 2; ks++) {
            uint32_t bfr[4][2];
#pragma unroll
            for (int nt = 0; nt < 4; nt++) {
                uint32_t addr = xsa[s] +
                    ((ks * 16 + (lane & 15)) * 68 + warpN * 16 + nt * 4) * 4;
                asm volatile(
                    "ldmatrix.sync.aligned.m8n8.x2.trans.shared.b16 {%0,%1}, [%2];"
                    : "=r"(bfr[nt][0]), "=r"(bfr[nt][1]) : "r"(addr));
            }
#pragma unroll
            for (int mt = 0; mt < 4; mt++) {
                int mo = warpM * 64 + mt * 16;
                uint32_t a0 = wsb[(mo + g) * 20 + ks * 8 + tig];
                uint32_t a1 = wsb[(mo + g + 8) * 20 + ks * 8 + tig];
                uint32_t a2 = wsb[(mo + g) * 20 + ks * 8 + tig + 4];
                uint32_t a3 = wsb[(mo + g + 8) * 20 + ks * 8 + tig + 4];
#pragma unroll
                for (int nt = 0; nt < 4; nt++)
                    MMA_BF16(c[mt][nt][0], c[mt][nt][1], c[mt][nt][2], c[mt][nt][3],
                             a0, a1, a2, a3, bfr[nt][0], bfr[nt][1]);
            }
        }
        __syncthreads();
    }

#pragma unroll
    for (int mt = 0; mt < 4; mt++) {
#pragma unroll
        for (int half = 0; half < 2; half++) {
            int m = m0 + warpM * 64 + mt * 16 + g + half * 8;
            float bv = bias[m];
            size_t rowoff = ((size_t)b * M + m) * N;
#pragma unroll
            for (int nt = 0; nt < 4; nt++) {
                int n = n0 + warpN * 32 + nt * 8 + tig * 2;
                float v0 = c[mt][nt][half * 2 + 0] + bv;
                float v1 = c[mt][nt][half * 2 + 1] + bv;
                if (res) {
                    v0 += res[rowoff + n];
                    v1 += res[rowoff + n + 1];
                }
                C[rowoff + n] = v0;
                C[rowoff + n + 1] = v1;
            }
        }
    }
}

__global__ void __launch_bounds__(256) ckv_bf16(
        const float* __restrict__ ctx, const float* __restrict__ W,
        const float* __restrict__ bias) {
    __shared__ uint32_t wsb[128 * 20];
    __shared__ uint32_t csb[80 * 20];

    int m0 = blockIdx.x * 128, b = blockIdx.y;
    int tid = threadIdx.x;
    int warp = tid >> 5, lane = tid & 31;
    int g = lane >> 2, tig = lane & 3;
    int mo = warp * 16;

    float c[10][4];
#pragma unroll
    for (int nt = 0; nt < 10; nt++)
#pragma unroll
        for (int r = 0; r < 4; r++) c[nt][r] = 0.f;

    int wrow = tid >> 1, wseg = tid & 1;

    for (int k0 = 0; k0 < CTXD; k0 += 32) {
        {
            const float* wp = W + (size_t)(m0 + wrow) * CTXD + k0 + wseg * 16;
            float4 f0 = *(const float4*)(wp + 0);
            float4 f1 = *(const float4*)(wp + 4);
            float4 f2 = *(const float4*)(wp + 8);
            float4 f3 = *(const float4*)(wp + 12);
            uint32_t* wd = wsb + wrow * 20 + wseg * 8;
            wd[0] = pkbf2(f0.x, f0.y); wd[1] = pkbf2(f0.z, f0.w);
            wd[2] = pkbf2(f1.x, f1.y); wd[3] = pkbf2(f1.z, f1.w);
            wd[4] = pkbf2(f2.x, f2.y); wd[5] = pkbf2(f2.z, f2.w);
            wd[6] = pkbf2(f3.x, f3.y); wd[7] = pkbf2(f3.z, f3.w);
        }
        if (tid < 160) {
            int l = tid >> 1, cseg = tid & 1;
            uint32_t* cd = csb + l * 20 + cseg * 8;
            if (l < LCTX) {
                const float* cp = ctx + ((size_t)b * LCTX + l) * CTXD + k0 + cseg * 16;
                float4 f0 = *(const float4*)(cp + 0);
                float4 f1 = *(const float4*)(cp + 4);
                float4 f2 = *(const float4*)(cp + 8);
                float4 f3 = *(const float4*)(cp + 12);
                cd[0] = pkbf2(f0.x, f0.y); cd[1] = pkbf2(f0.z, f0.w);
                cd[2] = pkbf2(f1.x, f1.y); cd[3] = pkbf2(f1.z, f1.w);
                cd[4] = pkbf2(f2.x, f2.y); cd[5] = pkbf2(f2.z, f2.w);
                cd[6] = pkbf2(f3.x, f3.y); cd[7] = pkbf2(f3.z, f3.w);
            } else {
#pragma unroll
                for (int j = 0; j < 8; j++) cd[j] = 0;
            }
        }
        __syncthreads();

#pragma unroll
        for (int ks = 0; ks < 2; ks++) {
            int w0 = ks * 8 + tig;
            uint32_t a0 = wsb[(mo + g) * 20 + w0];
            uint32_t a1 = wsb[(mo + g + 8) * 20 + w0];
            uint32_t a2 = wsb[(mo + g) * 20 + w0 + 4];
            uint32_t a3 = wsb[(mo + g + 8) * 20 + w0 + 4];
#pragma unroll
            for (int nt = 0; nt < 10; nt++) {
                uint32_t b0 = csb[(nt * 8 + g) * 20 + w0];
                uint32_t b1 = csb[(nt * 8 + g) * 20 + w0 + 4];
                MMA_BF16(c[nt][0], c[nt][1], c[nt][2], c[nt][3],
                         a0, a1, a2, a3, b0, b1);
            }
        }
        __syncthreads();
    }

#pragma unroll
    for (int half = 0; half < 2; half++) {
        int o = m0 + mo + g + half * 8;
        float bv = bias[o];
        float* outp = g_ckv + ((size_t)b * 1024 + o) * LCTX;
#pragma unroll
        for (int nt = 0; nt < 10; nt++) {
            int l = nt * 8 + tig * 2;
            if (l < LCTX)     outp[l]     = c[nt][half * 2 + 0] + bv;
            if (l + 1 < LCTX) outp[l + 1] = c[nt][half * 2 + 1] + bv;
        }
    }
}

__global__ void packk_kernel() {
    __shared__ unsigned short ks[64][66];
    int tt = blockIdx.x, n = blockIdx.y, b = blockIdx.z;
    int tid = threadIdx.x;
    const float* kck = g_ckv + ((size_t)b * 1024 + n * 64) * LCTX;
    const float* kim = g_qkv + ((size_t)b * 1536 + 512 + n * 64) * 1024;
    int tl = tid & 63, dh = tid >> 6;
    int t0 = tt * 64;
#pragma unroll
    for (int p = 0; p < 16; p++) {
        int d = p * 4 + dh;
        int gt = t0 + tl;
        float kv = 0.f;
        if (gt < LCTX) kv = kck[d * LCTX + gt];
        else if (gt < TKV) kv = kim[(size_t)d * 1024 + (gt - LCTX)];
        __nv_bfloat16 h = __float2bfloat16_rn(kv * 0.125f);
        ks[d][tl] = *reinterpret_cast<unsigned short*>(&h);
    }
    __syncthreads();

    int row = tid >> 2, q = tid & 3;
    int t = t0 + row;
    uint32_t* outw = g_kb + ((size_t)(b * HEADS + n) * TPAD + t) * 32;
#pragma unroll
    for (int half = 0; half < 2; half++) {
        int w0 = q * 4 + half * 16;
        uint32_t wv[4];
#pragma unroll
        for (int j = 0; j < 4; j++) {
            int p = w0 + j;
            wv[j] = (uint32_t)ks[2 * p][row] | ((uint32_t)ks[2 * p + 1][row] << 16);
        }
        uint4 v = {wv[0], wv[1], wv[2], wv[3]};
        *(uint4*)(outw + w0) = v;
    }
}

__global__ void packv_kernel() {
    int ck = blockIdx.x, n = blockIdx.y, b = blockIdx.z;
    int tid = threadIdx.x;
    const float* vck = g_ckv + ((size_t)b * 1024 + 512 + n * 64) * LCTX;
    const float* vim = g_qkv + ((size_t)b * 1536 + 1024 + n * 64) * 1024;
    uint32_t* outw = g_vb + (size_t)(b * HEADS + n) * 64 * (TPAD / 2);
    int d = tid >> 2, wq = (tid & 3) * 16;
#pragma unroll
    for (int j = 0; j < 16; j++) {
        int tp = ck * 64 + wq + j;
        int t = tp * 2;
        float v0 = 0.f, v1 = 0.f;
        if (t < LCTX) v0 = vck[d * LCTX + t];
        else if (t < TKV) v0 = vim[(size_t)d * 1024 + (t - LCTX)];
        if (t + 1 < LCTX) v1 = vck[d * LCTX + t + 1];
        else if (t + 1 < TKV) v1 = vim[(size_t)d * 1024 + (t + 1 - LCTX)];
        outw[(size_t)d * (TPAD / 2) + tp] = pkbf2(v0, v1);
    }
}

#define QW 36
#define KW 36
#define VW 68
#define FL8_WORDS (128*QW + 2*(128*KW + 64*VW))
#define FL8_SMEM (FL8_WORDS * 4)

__global__ void __launch_bounds__(256, 2) flash8_kernel() {
    extern __shared__ uint32_t sm8[];
    uint32_t* qs = sm8;
    uint32_t* ktb[2] = { qs + 128 * QW, qs + 128 * QW + 128 * KW };
    uint32_t* vtb[2] = { ktb[1] + 128 * KW, ktb[1] + 128 * KW + 64 * VW };
    __nv_bfloat16* qsb = (__nv_bfloat16*)qs;

    int s0 = blockIdx.x * 128;
    int n = blockIdx.y, b = blockIdx.z;
    int bn = b * HEADS + n;
    int tid = threadIdx.x;
    int warp = tid >> 5, lane = tid & 31;
    int g = lane >> 2, tig = lane & 3;
    int q0w = warp * 16;
    int lr8 = lane & 7, lsel4 = (lane >> 3) << 2;

    uint32_t kts[2], vts[2];
    kts[0] = smaddr(ktb[0]);
    kts[1] = smaddr(ktb[1]);
    vts[0] = smaddr(vtb[0]);
    vts[1] = smaddr(vtb[1]);

    const uint32_t* gk = g_kb + (size_t)bn * TPAD * 32;
    const uint32_t* gv = g_vb + (size_t)bn * 64 * (TPAD / 2);

    int ktrow = tid >> 1, ktq = tid & 1;
    int vdrow = tid >> 2, vwq = tid & 3;

    const float* qbase = g_qkv + ((size_t)b * 1536 + n * 64) * 1024 + s0;
    {
        int s = tid & 127, hi = tid >> 7;
#pragma unroll
        for (int p = 0; p < 32; p++) {
            int d = p * 2 + hi;
            qsb[s * (QW * 2) + d] = __float2bfloat16_rn(qbase[(size_t)d * 1024 + s]);
        }
    }
    __syncthreads();

    uint32_t qa[4][4];
    {
        uint32_t qaddr = smaddr(qs + (q0w + (lane & 15)) * QW + ((lane >> 4) << 2));
#pragma unroll
        for (int ks = 0; ks < 4; ks++)
            LDMX4(qa[ks][0], qa[ks][1], qa[ks][2], qa[ks][3], qaddr + ks * 32);
    }

#define ISSUE_CHUNK(c)                                                         \
    do {                                                                       \
        int _bb = (c) & 1;                                                     \
        const uint32_t* _gkc = gk + ((size_t)(c) * 128 + ktrow) * 32 + ktq * 16; \
        uint32_t _kd = kts[_bb] + (ktrow * KW + ktq * 16) * 4;                 \
        cpasync16(_kd + 0,  _gkc + 0);                                         \
        cpasync16(_kd + 16, _gkc + 4);                                         \
        cpasync16(_kd + 32, _gkc + 8);                                         \
        cpasync16(_kd + 48, _gkc + 12);                                        \
        const uint32_t* _gvc = gv + (size_t)vdrow * (TPAD / 2) + (c) * 64 + vwq * 16; \
        uint32_t _vd = vts[_bb] + (vdrow * VW + vwq * 16) * 4;                 \
        cpasync16(_vd + 0,  _gvc + 0);                                         \
        cpasync16(_vd + 16, _gvc + 4);                                         \
        cpasync16(_vd + 32, _gvc + 8);                                         \
        cpasync16(_vd + 48, _gvc + 12);                                        \
        asm volatile("cp.async.commit_group;");                                \
    } while (0)

    ISSUE_CHUNK(0);

    float l0 = 0.f, l1 = 0.f;
    float o[8][4];
#pragma unroll
    for (int nt = 0; nt < 8; nt++)
#pragma unroll
        for (int r = 0; r < 4; r++) o[nt][r] = 0.f;

    for (int c = 0; c < NCHB; c++) {
        if (c + 1 < NCHB) {
            ISSUE_CHUNK(c + 1);
            asm volatile("cp.async.wait_group 1;");
        } else {
            asm volatile("cp.async.wait_group 0;");
        }
        __syncthreads();

        uint32_t ktbase = kts[c & 1];
        uint32_t vtbase = vts[c & 1];
        int t0 = c * 128;

#pragma unroll
        for (int h = 0; h < 2; h++) {
            float sfr[8][4];
#pragma unroll
            for (int nt = 0; nt < 8; nt++)
#pragma unroll
                for (int r = 0; r < 4; r++) sfr[nt][r] = 0.f;

#pragma unroll
            for (int nt = 0; nt < 8; nt++) {
                uint32_t ka = ktbase + ((h * 64 + nt * 8 + lr8) * KW + lsel4) * 4;
                uint32_t k0, k1, k2, k3, k4, k5, k6, k7;
                LDMX4(k0, k1, k2, k3, ka);
                LDMX4(k4, k5, k6, k7, ka + 64);
                MMA_BF16(sfr[nt][0], sfr[nt][1], sfr[nt][2], sfr[nt][3],
                         qa[0][0], qa[0][1], qa[0][2], qa[0][3], k0, k1);
                MMA_BF16(sfr[nt][0], sfr[nt][1], sfr[nt][2], sfr[nt][3],
                         qa[1][0], qa[1][1], qa[1][2], qa[1][3], k2, k3);
                MMA_BF16(sfr[nt][0], sfr[nt][1], sfr[nt][2], sfr[nt][3],
                         qa[2][0], qa[2][1], qa[2][2], qa[2][3], k4, k5);
                MMA_BF16(sfr[nt][0], sfr[nt][1], sfr[nt][2], sfr[nt][3],
                         qa[3][0], qa[3][1], qa[3][2], qa[3][3], k6, k7);
            }

            if (t0 + h * 64 + 64 > TKV) {
#pragma unroll
                for (int nt = 0; nt < 8; nt++) {
                    int t = t0 + h * 64 + nt * 8 + tig * 2;
                    if (t >= TKV) { sfr[nt][0] = -1e30f; sfr[nt][2] = -1e30f; }
                    if (t + 1 >= TKV) { sfr[nt][1] = -1e30f; sfr[nt][3] = -1e30f; }
                }
            }

#pragma unroll
            for (int nt = 0; nt < 8; nt++) {
                sfr[nt][0] = __expf(sfr[nt][0]);
                sfr[nt][1] = __expf(sfr[nt][1]);
                sfr[nt][2] = __expf(sfr[nt][2]);
                sfr[nt][3] = __expf(sfr[nt][3]);
                l0 += sfr[nt][0] + sfr[nt][1];
                l1 += sfr[nt][2] + sfr[nt][3];
            }

            uint32_t pA[4][4];
#pragma unroll
            for (int ks = 0; ks < 4; ks++) {
                pA[ks][0] = pkbf2(sfr[2 * ks][0], sfr[2 * ks][1]);
                pA[ks][1] = pkbf2(sfr[2 * ks][2], sfr[2 * ks][3]);
                pA[ks][2] = pkbf2(sfr[2 * ks + 1][0], sfr[2 * ks + 1][1]);
                pA[ks][3] = pkbf2(sfr[2 * ks + 1][2], sfr[2 * ks + 1][3]);
            }

#pragma unroll
            for (int nt = 0; nt < 8; nt++) {
                uint32_t va = vtbase + ((nt * 8 + lr8) * VW + h * 32 + lsel4) * 4;
                uint32_t v0, v1, v2, v3, v4, v5, v6, v7;
                LDMX4(v0, v1, v2, v3, va);
                LDMX4(v4, v5, v6, v7, va + 64);
                MMA_BF16(o[nt][0], o[nt][1], o[nt][2], o[nt][3],
                         pA[0][0], pA[0][1], pA[0][2], pA[0][3], v0, v1);
                MMA_BF16(o[nt][0], o[nt][1], o[nt][2], o[nt][3],
                         pA[1][0], pA[1][1], pA[1][2], pA[1][3], v2, v3);
                MMA_BF16(o[nt][0], o[nt][1], o[nt][2], o[nt][3],
                         pA[2][0], pA[2][1], pA[2][2], pA[2][3], v4, v5);
                MMA_BF16(o[nt][0], o[nt][1], o[nt][2], o[nt][3],
                         pA[3][0], pA[3][1], pA[3][2], pA[3][3], v6, v7);
            }
        }
        __syncthreads();
    }

    {
        l0 += __shfl_xor_sync(0xffffffffu, l0, 1);
        l0 += __shfl_xor_sync(0xffffffffu, l0, 2);
        l1 += __shfl_xor_sync(0xffffffffu, l1, 1);
        l1 += __shfl_xor_sync(0xffffffffu, l1, 2);
        float inv0 = 1.f / l0, inv1 = 1.f / l1;
        __nv_bfloat16* outp = g_attnb + ((size_t)b * 512 + n * 64) * 1024 + s0;
        int sA = q0w + g, sB = q0w + g + 8;
#pragma unroll
        for (int nt = 0; nt < 8; nt++) {
            int d = nt * 8 + tig * 2;
            outp[(size_t)d * 1024 + sA] = __float2bfloat16_rn(o[nt][0] * inv0);
            outp[(size_t)(d + 1) * 1024 + sA] = __float2bfloat16_rn(o[nt][1] * inv0);
            outp[(size_t)d * 1024 + sB] = __float2bfloat16_rn(o[nt][2] * inv1);
            outp[(size_t)(d + 1) * 1024 + sB] = __float2bfloat16_rn(o[nt][3] * inv1);
        }
    }
}

extern "C" void kernel_launch(void* const* d_in, const int* in_sizes, int n_in,
                              void* d_out, int out_size) {
    const float* x       = (const float*)d_in[0];
    const float* context = (const float*)d_in[1];
    const float* gamma   = (const float*)d_in[2];
    const float* beta    = (const float*)d_in[3];
    const float* qkv_w   = (const float*)d_in[4];
    const float* qkv_b   = (const float*)d_in[5];
    const float* ckv_w   = (const float*)d_in[6];
    const float* ckv_b   = (const float*)d_in[7];
    const float* proj_w  = (const float*)d_in[8];
    const float* proj_b  = (const float*)d_in[9];
    float* out = (float*)d_out;

    __nv_bfloat16 *wqkvb_p, *wprojb_p, *xnb_p, *attnb_p;
    float* qkv_p;
    cudaGetSymbolAddress((void**)&wqkvb_p, g_wqkvb);
    cudaGetSymbolAddress((void**)&wprojb_p, g_wprojb);
    cudaGetSymbolAddress((void**)&xnb_p, g_xnb);
    cudaGetSymbolAddress((void**)&attnb_p, g_attnb);
    cudaGetSymbolAddress((void**)&qkv_p, g_qkv);

    // 0. Weight conversion (fp32 -> bf16)
    wconv_kernel<<<296, 256>>>(qkv_w, wqkvb_p, (3 * DIMC * DIMC) / 4);
    wconv_kernel<<<148, 256>>>(proj_w, wprojb_p, (DIMC * DIMC) / 4);

    // 1. GroupNorm (writes bf16 g_xnb)
    gn_kernel<<<BATCH * 32, 256>>>(x, gamma, beta);

    // 2. QKV projection (bf16 operands, cp.async pipelined)
    gemm_bf16g<<<dim3(8, 12, BATCH), 256>>>(wqkvb_p, qkv_b, xnb_p, nullptr,
                                            qkv_p, 1536, 1024, 512);

    // 3. Context KV projection
    ckv_bf16<<<dim3(8, BATCH), 256>>>(context, ckv_w, ckv_b);

    // 4a. Pack K/V
    packk_kernel<<<dim3(NCHB * 2, HEADS, BATCH), 256>>>();
    packv_kernel<<<dim3(NCHB, HEADS, BATCH), 256>>>();

    // 4b. Flash attention v8 (bf16 epilogue)
    cudaFuncSetAttribute(flash8_kernel, cudaFuncAttributeMaxDynamicSharedMemorySize, FL8_SMEM);
    flash8_kernel<<<dim3(8, HEADS, BATCH), 256, FL8_SMEM>>>();

    // 5. Output projection + bias + residual
    gemm_bf16g<<<dim3(8, 4, BATCH), 256>>>(wprojb_p, proj_b, attnb_p, x,
                                           out, 512, 1024, 512);
}